// round 10
// baseline (speedup 1.0000x reference)
#include <cuda_runtime.h>
#include <cuda_fp16.h>
#include <math.h>
#include <stdint.h>

// Problem constants
#define B_SZ   2
#define T_SEQ  2048
#define C_DIM  1024
#define C3     3072
#define NH     16
#define DH     64
#define MEMLEN 1024
#define M_TOT  4096
#define KD     1024

// Scratch fp16 hi/lo planes (no cudaMalloc allowed)
__device__ __half g_xh[(size_t)M_TOT * KD];
__device__ __half g_xl[(size_t)M_TOT * KD];
__device__ __half g_wqh[(size_t)C3 * KD];
__device__ __half g_wql[(size_t)C3 * KD];
__device__ __half g_wph[(size_t)C_DIM * KD];
__device__ __half g_wpl[(size_t)C_DIM * KD];
__device__ __half g_qkvh[(size_t)M_TOT * C3];
__device__ __half g_qkvl[(size_t)M_TOT * C3];
__device__ __half g_yh[(size_t)M_TOT * KD];

// ---------------------------------------------------------------------------
// helpers
// ---------------------------------------------------------------------------
__device__ __forceinline__ uint32_t pk2(__half a, __half b) {
    __half2 t = __halves2half2(a, b);
    return *reinterpret_cast<uint32_t*>(&t);
}

__device__ __forceinline__ uint32_t pkh(float a, float b) {
    __half2 t = __floats2half2_rn(a, b);
    return *reinterpret_cast<uint32_t*>(&t);
}

__device__ __forceinline__ uint32_t pkf(float a, float b, uint32_t* lo) {
    __half ha = __float2half_rn(a), hb = __float2half_rn(b);
    __half la = __float2half_rn(a - __half2float(ha));
    __half lb = __float2half_rn(b - __half2float(hb));
    *lo = pk2(la, lb);
    return pk2(ha, hb);
}

__device__ __forceinline__ void ldm4(uint32_t r[4], uint32_t a) {
    asm volatile("ldmatrix.sync.aligned.m8n8.x4.shared.b16 {%0,%1,%2,%3},[%4];\n"
                 : "=r"(r[0]), "=r"(r[1]), "=r"(r[2]), "=r"(r[3]) : "r"(a));
}
__device__ __forceinline__ void ldm4t(uint32_t r[4], uint32_t a) {
    asm volatile("ldmatrix.sync.aligned.m8n8.x4.trans.shared.b16 {%0,%1,%2,%3},[%4];\n"
                 : "=r"(r[0]), "=r"(r[1]), "=r"(r[2]), "=r"(r[3]) : "r"(a));
}

__device__ __forceinline__ void mma16(float d[4], const uint32_t a[4],
                                      uint32_t b0, uint32_t b1) {
    asm volatile(
        "mma.sync.aligned.m16n8k16.row.col.f32.f16.f16.f32 "
        "{%0,%1,%2,%3},{%4,%5,%6,%7},{%8,%9},{%0,%1,%2,%3};\n"
        : "+f"(d[0]), "+f"(d[1]), "+f"(d[2]), "+f"(d[3])
        : "r"(a[0]), "r"(a[1]), "r"(a[2]), "r"(a[3]), "r"(b0), "r"(b1));
}

__device__ __forceinline__ void cpa16(uint32_t d, const void* g) {
    asm volatile("cp.async.cg.shared.global [%0], [%1], 16;" :: "r"(d), "l"(g) : "memory");
}
__device__ __forceinline__ void cpa_commit() {
    asm volatile("cp.async.commit_group;" ::: "memory");
}
template <int N>
__device__ __forceinline__ void cpa_wait() {
    asm volatile("cp.async.wait_group %0;" :: "n"(N) : "memory");
}

// ---------------------------------------------------------------------------
// Split fp32 -> fp16 hi/lo planes
// ---------------------------------------------------------------------------
__global__ __launch_bounds__(256)
void split_kernel(const float* __restrict__ src,
                  __half* __restrict__ hi,
                  __half* __restrict__ lo, int n8)
{
    int i = blockIdx.x * 256 + threadIdx.x;
    if (i >= n8) return;
    float4 v0 = ((const float4*)src)[2 * i];
    float4 v1 = ((const float4*)src)[2 * i + 1];
    float v[8] = {v0.x, v0.y, v0.z, v0.w, v1.x, v1.y, v1.z, v1.w};
    uint32_t hp[4], lp[4];
#pragma unroll
    for (int j = 0; j < 4; j++)
        hp[j] = pkf(v[2 * j], v[2 * j + 1], &lp[j]);
    ((uint4*)hi)[i] = make_uint4(hp[0], hp[1], hp[2], hp[3]);
    ((uint4*)lo)[i] = make_uint4(lp[0], lp[1], lp[2], lp[3]);
}

// ---------------------------------------------------------------------------
// fp16 split NT GEMM, persistent grid-stride over tiles.
// 256 threads, 8 warps (4Mx2N of 32x64). Blocks with n0 < fullN: 3-mma;
// others: 2-mma.
// ---------------------------------------------------------------------------
#define PLANE        8192
#define STAGE_BYTES  32768
#define NSTAGE       3
#define GEMM_SMEM    (NSTAGE * STAGE_BYTES)
#define NCH          32

__global__ __launch_bounds__(256, 2)
void gemm_fp16_kernel(const __half* __restrict__ Ah,
                      const __half* __restrict__ Al,
                      const __half* __restrict__ Bh,
                      const __half* __restrict__ Bl,
                      float* __restrict__ C,
                      __half* __restrict__ Ch,
                      __half* __restrict__ Cl,
                      int N, int fullN, int nTiles, int tilesX)
{
    extern __shared__ char smem[];
    const uint32_t sbase = (uint32_t)__cvta_generic_to_shared(smem);
    const int tid = threadIdx.x, lane = tid & 31, warp = tid >> 5;
    const int mw = warp >> 1, nw = warp & 1;

    // loader thread shape (tile-independent parts)
    int l_p[8], l_r[8], l_kc[8];
    uint32_t sdst[8];
#pragma unroll
    for (int it = 0; it < 8; it++) {
        int c = tid + it * 256;
        l_p[it] = c >> 9;
        l_r[it] = (c >> 2) & 127;
        l_kc[it] = c & 3;
        sdst[it] = (uint32_t)(l_p[it] * PLANE + l_r[it] * 64 +
                              ((l_kc[it] ^ ((l_r[it] >> 1) & 3)) << 4));
    }

    // fragment address precompute (tile-independent)
    const int ra = lane & 15;
    const int ksel_a = lane >> 4;
    int rowA[2], swzA[2];
#pragma unroll
    for (int f = 0; f < 2; f++) {
        rowA[f] = mw * 32 + f * 16 + ra;
        swzA[f] = (rowA[f] >> 1) & 3;
    }
    const int rb = (lane & 7) + 8 * (lane >> 4);
    const int ksel_b = (lane >> 3) & 1;
    int rowB[4], swzB[4];
#pragma unroll
    for (int g = 0; g < 4; g++) {
        rowB[g] = nw * 64 + g * 16 + rb;
        swzB[g] = (rowB[g] >> 1) & 3;
    }

    for (int tile = blockIdx.x; tile < nTiles; tile += gridDim.x) {
        const int m0 = (tile / tilesX) * 128;
        const int n0 = (tile % tilesX) * 128;
        const bool full = (n0 < fullN);

        const __half* gsrc[8];
#pragma unroll
        for (int it = 0; it < 8; it++) {
            const __half* bp = (l_p[it] == 0) ? Ah : (l_p[it] == 1) ? Al
                             : (l_p[it] == 2) ? Bh : Bl;
            int row = ((l_p[it] < 2) ? m0 : n0) + l_r[it];
            gsrc[it] = bp + (size_t)row * KD + l_kc[it] * 8;
        }

        float acc[2][8][4] = {};

#pragma unroll
        for (int pt = 0; pt < 2; pt++) {
            uint32_t sb = sbase + pt * STAGE_BYTES;
#pragma unroll
            for (int it = 0; it < 8; it++) cpa16(sb + sdst[it], gsrc[it] + pt * 32);
            cpa_commit();
        }

        for (int t = 0; t < NCH; t++) {
            cpa_wait<1>();
            __syncthreads();

            if (t + 2 < NCH) {
                uint32_t sb = sbase + ((t + 2) % NSTAGE) * STAGE_BYTES;
#pragma unroll
                for (int it = 0; it < 8; it++)
                    cpa16(sb + sdst[it], gsrc[it] + (t + 2) * 32);
            }
            cpa_commit();

            const uint32_t sb = sbase + (t % NSTAGE) * STAGE_BYTES;
#pragma unroll
            for (int s16 = 0; s16 < 2; s16++) {
                uint32_t ah[2][4], al[2][4];
#pragma unroll
                for (int f = 0; f < 2; f++) {
                    uint32_t off = (uint32_t)(rowA[f] * 64 +
                                   (((2 * s16 + ksel_a) ^ swzA[f]) << 4));
                    ldm4(ah[f], sb + off);
                    if (full) ldm4(al[f], sb + PLANE + off);
                }
#pragma unroll
                for (int g = 0; g < 4; g++) {
                    uint32_t offb = (uint32_t)(rowB[g] * 64 +
                                    (((2 * s16 + ksel_b) ^ swzB[g]) << 4));
                    uint32_t bh[4], bl[4];
                    ldm4(bh, sb + 2 * PLANE + offb);
                    ldm4(bl, sb + 3 * PLANE + offb);
#pragma unroll
                    for (int f = 0; f < 2; f++) {
#pragma unroll
                        for (int j = 0; j < 2; j++) {
                            float* d = acc[f][g * 2 + j];
                            mma16(d, ah[f], bh[2 * j], bh[2 * j + 1]);
                            mma16(d, ah[f], bl[2 * j], bl[2 * j + 1]);
                            if (full) mma16(d, al[f], bh[2 * j], bh[2 * j + 1]);
                        }
                    }
                }
            }
        }

        const int er = lane >> 2, ec = (lane & 3) * 2;
#pragma unroll
        for (int f = 0; f < 2; f++) {
            int r = m0 + mw * 32 + f * 16 + er;
#pragma unroll
            for (int j8 = 0; j8 < 8; j8++) {
                int cc = n0 + nw * 64 + j8 * 8 + ec;
                if (Ch) {
                    uint32_t lo0, lo1;
                    uint32_t hi0 = pkf(acc[f][j8][0], acc[f][j8][1], &lo0);
                    uint32_t hi1 = pkf(acc[f][j8][2], acc[f][j8][3], &lo1);
                    *(uint32_t*)(Ch + (size_t)r * N + cc) = hi0;
                    *(uint32_t*)(Cl + (size_t)r * N + cc) = lo0;
                    *(uint32_t*)(Ch + (size_t)(r + 8) * N + cc) = hi1;
                    *(uint32_t*)(Cl + (size_t)(r + 8) * N + cc) = lo1;
                } else {
                    *(float2*)(C + (size_t)r * N + cc) =
                        make_float2(acc[f][j8][0], acc[f][j8][1]);
                    *(float2*)(C + (size_t)(r + 8) * N + cc) =
                        make_float2(acc[f][j8][2], acc[f][j8][3]);
                }
            }
        }
        // no barrier needed: next tile's cp.async writes smem, epilogue reads regs
    }
}

// ---------------------------------------------------------------------------
// fp16 mma flash attention: S 3-mma, PV 2-mma. LPT launch order (qt desc).
// ---------------------------------------------------------------------------
#define AQ 128
#define AKV 64
#define QH_OFF   0
#define QL_OFF   16384
#define ST_OFF   32768
#define AST      32768
#define QSC_OFF  (ST_OFF + 2 * AST)
#define ATTN2_SMEM (QSC_OFF + 256)

__global__ __launch_bounds__(256)
void attn_mma2(const float* __restrict__ qm,
               const __half* __restrict__ qkvh,
               const __half* __restrict__ qkvl,
               __half* __restrict__ yh)
{
    extern __shared__ char smem[];
    const uint32_t sb = (uint32_t)__cvta_generic_to_shared(smem);
    float* qsc = (float*)(smem + QSC_OFF);
    const int tid = threadIdx.x, lane = tid & 31, warp = tid >> 5;
    // LPT: largest-nT q-tiles launch first
    const int qt = (int)gridDim.x - 1 - (int)blockIdx.x;
    const int h = blockIdx.y, b = blockIdx.z;
    const int q0 = qt * AQ;

    if (tid < 64) qsc[tid] = logf(2048.0f) * qm[tid] * rsqrtf(64.0f);

    const __half* kvsrc[8];
    uint32_t kvdst[8];
#pragma unroll
    for (int it = 0; it < 8; it++) {
        int c = tid + it * 256;
        int p = c >> 9, r = (c >> 3) & 63, ch = c & 7;
        const __half* bp = (p & 1) ? qkvl : qkvh;
        int col = ((p >> 1) ? 2 * C_DIM : C_DIM) + h * DH + ch * 8;
        kvsrc[it] = bp + (size_t)(b * T_SEQ + r) * C3 + col;
        kvdst[it] = (uint32_t)(p * 8192 + r * 128 + ((ch ^ (r & 7)) << 4));
    }
#pragma unroll
    for (int it = 0; it < 8; it++) cpa16(sb + ST_OFF + kvdst[it], kvsrc[it]);
    cpa_commit();

    __syncthreads();

#pragma unroll
    for (int it = 0; it < 4; it++) {
        int u = tid + it * 256;
        int r = u >> 3, ch = u & 7;
        size_t src = (size_t)(b * T_SEQ + q0 + r) * C3 + h * DH + ch * 8;
        uint4 hv = *(const uint4*)(qkvh + src);
        uint4 lv = *(const uint4*)(qkvl + src);
        const __half2* hp = (const __half2*)&hv;
        const __half2* lp = (const __half2*)&lv;
        uint32_t oh[4], ol[4];
#pragma unroll
        for (int k = 0; k < 4; k++) {
            float2 hf = __half22float2(hp[k]);
            float2 lf = __half22float2(lp[k]);
            float v0 = (hf.x + lf.x) * qsc[ch * 8 + 2 * k];
            float v1 = (hf.y + lf.y) * qsc[ch * 8 + 2 * k + 1];
            oh[k] = pkf(v0, v1, &ol[k]);
        }
        uint32_t off = (uint32_t)(r * 128 + ((ch ^ (r & 7)) << 4));
        *(uint4*)(smem + QH_OFF + off) = make_uint4(oh[0], oh[1], oh[2], oh[3]);
        *(uint4*)(smem + QL_OFF + off) = make_uint4(ol[0], ol[1], ol[2], ol[3]);
    }

    float m0 = -1e30f, m1 = -1e30f, l0 = 0.0f, l1 = 0.0f;
    float acc[8][4] = {};

    const int maxc = (q0 + AQ > MEMLEN) ? (q0 + AQ) : MEMLEN;
    const int nT = maxc / AKV;

    for (int t = 0; t < nT; t++) {
        cpa_wait<0>();
        __syncthreads();
        if (t + 1 < nT) {
            uint32_t stb = sb + ST_OFF + ((t + 1) & 1) * AST;
            size_t delta = (size_t)(t + 1) * AKV * C3;
#pragma unroll
            for (int it = 0; it < 8; it++) cpa16(stb + kvdst[it], kvsrc[it] + delta);
            cpa_commit();
        }
        const uint32_t st = sb + ST_OFF + (t & 1) * AST;

        // ---- S = Q K^T (3-mma fp16) ----
        float s_[8][4] = {};
#pragma unroll
        for (int kk = 0; kk < 4; kk++) {
            uint32_t aH[4], aL[4];
            {
                int row = 16 * warp + (lane & 15);
                int ch = kk * 2 + (lane >> 4);
                uint32_t off = (uint32_t)(row * 128 + ((ch ^ (row & 7)) << 4));
                ldm4(aH, sb + QH_OFF + off);
                ldm4(aL, sb + QL_OFF + off);
            }
#pragma unroll
            for (int jj = 0; jj < 4; jj++) {
                int row = 16 * jj + 8 * (lane >> 4) + (lane & 7);
                int ch = kk * 2 + ((lane >> 3) & 1);
                uint32_t off = (uint32_t)(row * 128 + ((ch ^ (row & 7)) << 4));
                uint32_t bH[4], bL[4];
                ldm4(bH, st + off);
                ldm4(bL, st + 8192 + off);
#pragma unroll
                for (int u = 0; u < 2; u++) {
                    float* d = s_[2 * jj + u];
                    mma16(d, aH, bH[2 * u], bH[2 * u + 1]);
                    mma16(d, aH, bL[2 * u], bL[2 * u + 1]);
                    mma16(d, aL, bH[2 * u], bH[2 * u + 1]);
                }
            }
        }

        const int kj0 = t * AKV;
        if (kj0 >= MEMLEN) {
            int r0g = q0 + 16 * warp + (lane >> 2);
            int cb = kj0 + 2 * (lane & 3);
#pragma unroll
            for (int j = 0; j < 8; j++) {
                int cg = cb + 8 * j;
                if (cg > r0g)         s_[j][0] = -1e30f;
                if (cg + 1 > r0g)     s_[j][1] = -1e30f;
                if (cg > r0g + 8)     s_[j][2] = -1e30f;
                if (cg + 1 > r0g + 8) s_[j][3] = -1e30f;
            }
        }

        // ---- online softmax ----
        float mx0 = -1e30f, mx1 = -1e30f;
#pragma unroll
        for (int j = 0; j < 8; j++) {
            mx0 = fmaxf(mx0, fmaxf(s_[j][0], s_[j][1]));
            mx1 = fmaxf(mx1, fmaxf(s_[j][2], s_[j][3]));
        }
        mx0 = fmaxf(mx0, __shfl_xor_sync(0xffffffffu, mx0, 1));
        mx0 = fmaxf(mx0, __shfl_xor_sync(0xffffffffu, mx0, 2));
        mx1 = fmaxf(mx1, __shfl_xor_sync(0xffffffffu, mx1, 1));
        mx1 = fmaxf(mx1, __shfl_xor_sync(0xffffffffu, mx1, 2));
        float mn0 = fmaxf(m0, mx0), mn1 = fmaxf(m1, mx1);
        float f0 = __expf(m0 - mn0), f1 = __expf(m1 - mn1);
        float sum0 = 0.0f, sum1 = 0.0f;
        uint32_t phA[8], phB[8];
#pragma unroll
        for (int j = 0; j < 8; j++) {
            float p0 = __expf(s_[j][0] - mn0);
            float p1 = __expf(s_[j][1] - mn0);
            float p2 = __expf(s_[j][2] - mn1);
            float p3 = __expf(s_[j][3] - mn1);
            sum0 += p0 + p1; sum1 += p2 + p3;
            phA[j] = pkh(p0, p1);
            phB[j] = pkh(p2, p3);
        }
        sum0 += __shfl_xor_sync(0xffffffffu, sum0, 1);
        sum0 += __shfl_xor_sync(0xffffffffu, sum0, 2);
        sum1 += __shfl_xor_sync(0xffffffffu, sum1, 1);
        sum1 += __shfl_xor_sync(0xffffffffu, sum1, 2);
        l0 = l0 * f0 + sum0; l1 = l1 * f1 + sum1;
        m0 = mn0; m1 = mn1;
#pragma unroll
        for (int j = 0; j < 8; j++) {
            acc[j][0] *= f0; acc[j][1] *= f0;
            acc[j][2] *= f1; acc[j][3] *= f1;
        }

        // ---- P @ V (2-mma: P single fp16, V hi/lo) ----
#pragma unroll
        for (int jj = 0; jj < 4; jj++) {
            uint32_t pa[4] = {phA[2*jj], phB[2*jj], phA[2*jj+1], phB[2*jj+1]};
#pragma unroll
            for (int nn = 0; nn < 4; nn++) {
                int row = 16 * jj + 8 * ((lane >> 3) & 1) + (lane & 7);
                int ch = 2 * nn + (lane >> 4);
                uint32_t off = (uint32_t)(row * 128 + ((ch ^ (row & 7)) << 4));
                uint32_t vH[4], vL[4];
                ldm4t(vH, st + 16384 + off);
                ldm4t(vL, st + 24576 + off);
#pragma unroll
                for (int u = 0; u < 2; u++) {
                    float* d = acc[2 * nn + u];
                    mma16(d, pa, vH[2 * u], vH[2 * u + 1]);
                    mma16(d, pa, vL[2 * u], vL[2 * u + 1]);
                }
            }
        }
    }

    // ---- epilogue ----
    {
        float i0 = 1.0f / l0, i1 = 1.0f / l1;
        size_t r0 = (size_t)(b * T_SEQ + q0 + 16 * warp + (lane >> 2));
        int cb = h * DH + 2 * (lane & 3);
#pragma unroll
        for (int j = 0; j < 8; j++) {
            int cc = cb + 8 * j;
            *(uint32_t*)(yh + r0 * C_DIM + cc)       = pkh(acc[j][0] * i0, acc[j][1] * i0);
            *(uint32_t*)(yh + (r0 + 8) * C_DIM + cc) = pkh(acc[j][2] * i1, acc[j][3] * i1);
        }
    }
}

// ---------------------------------------------------------------------------
// Launch
// ---------------------------------------------------------------------------
#define PERSIST_CTAS 296   // 148 SMs x 2 resident CTAs

extern "C" void kernel_launch(void* const* d_in, const int* in_sizes, int n_in,
                              void* d_out, int out_size)
{
    const float* x      = (const float*)d_in[0];
    const float* w_qkv  = (const float*)d_in[1];
    const float* w_proj = (const float*)d_in[2];
    const float* qm     = (const float*)d_in[3];
    float* out = (float*)d_out;

    static __half *p_xh = nullptr, *p_xl, *p_wqh, *p_wql, *p_wph, *p_wpl;
    static __half *p_qkvh, *p_qkvl, *p_yh;
    if (!p_xh) {
        cudaGetSymbolAddress((void**)&p_xh, g_xh);
        cudaGetSymbolAddress((void**)&p_xl, g_xl);
        cudaGetSymbolAddress((void**)&p_wqh, g_wqh);
        cudaGetSymbolAddress((void**)&p_wql, g_wql);
        cudaGetSymbolAddress((void**)&p_wph, g_wph);
        cudaGetSymbolAddress((void**)&p_wpl, g_wpl);
        cudaGetSymbolAddress((void**)&p_qkvh, g_qkvh);
        cudaGetSymbolAddress((void**)&p_qkvl, g_qkvl);
        cudaGetSymbolAddress((void**)&p_yh, g_yh);
        cudaFuncSetAttribute(gemm_fp16_kernel,
                             cudaFuncAttributeMaxDynamicSharedMemorySize, GEMM_SMEM);
        cudaFuncSetAttribute(attn_mma2,
                             cudaFuncAttributeMaxDynamicSharedMemorySize, ATTN2_SMEM);
    }

    // Split fp32 inputs into fp16 hi/lo planes
    split_kernel<<<(M_TOT * KD / 8 + 255) / 256, 256>>>(x, p_xh, p_xl, M_TOT * KD / 8);
    split_kernel<<<(C3 * KD / 8 + 255) / 256, 256>>>(w_qkv, p_wqh, p_wql, C3 * KD / 8);
    split_kernel<<<(C_DIM * KD / 8 + 255) / 256, 256>>>(w_proj, p_wph, p_wpl, C_DIM * KD / 8);

    // GEMM1: qkv = x @ w_qkv^T -> fp16 hi/lo planes (Q,K 3-mma; V 2-mma)
    // persistent: 296 CTAs stride over 768 tiles (24 x 32)
    {
        int nTiles = (C3 / 128) * (M_TOT / 128);   // 768
        int grid = nTiles < PERSIST_CTAS ? nTiles : PERSIST_CTAS;
        gemm_fp16_kernel<<<grid, 256, GEMM_SMEM>>>(p_xh, p_xl, p_wqh, p_wql,
                                                   nullptr, p_qkvh, p_qkvl, C3,
                                                   2 * C_DIM, nTiles, C3 / 128);
    }

    // Fused attention -> y single fp16 plane (LPT: qt descending)
    {
        dim3 grid(T_SEQ / AQ, NH, B_SZ);
        attn_mma2<<<grid, 256, ATTN2_SMEM>>>(qm, p_qkvh, p_qkvl, p_yh);
    }

    // GEMM2: out = y @ w_proj^T -> fp32, 2-mma everywhere (256 tiles, 1 wave)
    {
        int nTiles = (C_DIM / 128) * (M_TOT / 128);  // 256
        int grid = nTiles < PERSIST_CTAS ? nTiles : PERSIST_CTAS;
        gemm_fp16_kernel<<<grid, 256, GEMM_SMEM>>>(p_yh, p_yh, p_wph, p_wpl,
                                                   out, nullptr, nullptr, C_DIM,
                                                   0, nTiles, C_DIM / 128);
    }
}

// round 11
// speedup vs baseline: 1.0760x; 1.0760x over previous
#include <cuda_runtime.h>
#include <cuda_fp16.h>
#include <math.h>
#include <stdint.h>

// Problem constants
#define B_SZ   2
#define T_SEQ  2048
#define C_DIM  1024
#define C3     3072
#define NH     16
#define DH     64
#define MEMLEN 1024
#define M_TOT  4096
#define KD     1024

// Scratch fp16 hi/lo planes (no cudaMalloc allowed)
__device__ __half g_xh[(size_t)M_TOT * KD];
__device__ __half g_xl[(size_t)M_TOT * KD];
__device__ __half g_wqh[(size_t)C3 * KD];
__device__ __half g_wql[(size_t)C3 * KD];
__device__ __half g_wph[(size_t)C_DIM * KD];
__device__ __half g_wpl[(size_t)C_DIM * KD];
__device__ __half g_qkvh[(size_t)M_TOT * C3];
__device__ __half g_qkvl[(size_t)M_TOT * C3];
__device__ __half g_yh[(size_t)M_TOT * KD];

// ---------------------------------------------------------------------------
// helpers
// ---------------------------------------------------------------------------
__device__ __forceinline__ uint32_t pk2(__half a, __half b) {
    __half2 t = __halves2half2(a, b);
    return *reinterpret_cast<uint32_t*>(&t);
}

__device__ __forceinline__ uint32_t pkh(float a, float b) {
    __half2 t = __floats2half2_rn(a, b);
    return *reinterpret_cast<uint32_t*>(&t);
}

__device__ __forceinline__ uint32_t pkf(float a, float b, uint32_t* lo) {
    __half ha = __float2half_rn(a), hb = __float2half_rn(b);
    __half la = __float2half_rn(a - __half2float(ha));
    __half lb = __float2half_rn(b - __half2float(hb));
    *lo = pk2(la, lb);
    return pk2(ha, hb);
}

__device__ __forceinline__ void ldm4(uint32_t r[4], uint32_t a) {
    asm volatile("ldmatrix.sync.aligned.m8n8.x4.shared.b16 {%0,%1,%2,%3},[%4];\n"
                 : "=r"(r[0]), "=r"(r[1]), "=r"(r[2]), "=r"(r[3]) : "r"(a));
}
__device__ __forceinline__ void ldm4t(uint32_t r[4], uint32_t a) {
    asm volatile("ldmatrix.sync.aligned.m8n8.x4.trans.shared.b16 {%0,%1,%2,%3},[%4];\n"
                 : "=r"(r[0]), "=r"(r[1]), "=r"(r[2]), "=r"(r[3]) : "r"(a));
}

__device__ __forceinline__ void mma16(float d[4], const uint32_t a[4],
                                      uint32_t b0, uint32_t b1) {
    asm volatile(
        "mma.sync.aligned.m16n8k16.row.col.f32.f16.f16.f32 "
        "{%0,%1,%2,%3},{%4,%5,%6,%7},{%8,%9},{%0,%1,%2,%3};\n"
        : "+f"(d[0]), "+f"(d[1]), "+f"(d[2]), "+f"(d[3])
        : "r"(a[0]), "r"(a[1]), "r"(a[2]), "r"(a[3]), "r"(b0), "r"(b1));
}

__device__ __forceinline__ void cpa16(uint32_t d, const void* g) {
    asm volatile("cp.async.cg.shared.global [%0], [%1], 16;" :: "r"(d), "l"(g) : "memory");
}
__device__ __forceinline__ void cpa_commit() {
    asm volatile("cp.async.commit_group;" ::: "memory");
}
template <int N>
__device__ __forceinline__ void cpa_wait() {
    asm volatile("cp.async.wait_group %0;" :: "n"(N) : "memory");
}

// ---------------------------------------------------------------------------
// Split fp32 -> fp16 hi/lo planes
// ---------------------------------------------------------------------------
__global__ __launch_bounds__(256)
void split_kernel(const float* __restrict__ src,
                  __half* __restrict__ hi,
                  __half* __restrict__ lo, int n8)
{
    int i = blockIdx.x * 256 + threadIdx.x;
    if (i >= n8) return;
    float4 v0 = ((const float4*)src)[2 * i];
    float4 v1 = ((const float4*)src)[2 * i + 1];
    float v[8] = {v0.x, v0.y, v0.z, v0.w, v1.x, v1.y, v1.z, v1.w};
    uint32_t hp[4], lp[4];
#pragma unroll
    for (int j = 0; j < 4; j++)
        hp[j] = pkf(v[2 * j], v[2 * j + 1], &lp[j]);
    ((uint4*)hi)[i] = make_uint4(hp[0], hp[1], hp[2], hp[3]);
    ((uint4*)lo)[i] = make_uint4(lp[0], lp[1], lp[2], lp[3]);
}

// ---------------------------------------------------------------------------
// fp16 split NT GEMM (R8 config: 256 thr, 8 warps of 32x64, 3-stage).
// Blocks with n0 < fullN use 3-mma; others 2-mma.
// ---------------------------------------------------------------------------
#define PLANE        8192
#define STAGE_BYTES  32768
#define NSTAGE       3
#define GEMM_SMEM    (NSTAGE * STAGE_BYTES)
#define NCH          32

__global__ __launch_bounds__(256, 2)
void gemm_fp16_kernel(const __half* __restrict__ Ah,
                      const __half* __restrict__ Al,
                      const __half* __restrict__ Bh,
                      const __half* __restrict__ Bl,
                      float* __restrict__ C,
                      __half* __restrict__ Ch,
                      __half* __restrict__ Cl, int N, int fullN)
{
    extern __shared__ char smem[];
    const uint32_t sbase = (uint32_t)__cvta_generic_to_shared(smem);
    const int tid = threadIdx.x, lane = tid & 31, warp = tid >> 5;
    const int m0 = blockIdx.y * 128, n0 = blockIdx.x * 128;
    const bool full = (n0 < fullN);
    const int mw = warp >> 1, nw = warp & 1;

    const __half* gsrc[8];
    uint32_t sdst[8];
#pragma unroll
    for (int it = 0; it < 8; it++) {
        int c = tid + it * 256;
        int p = c >> 9;
        int r = (c >> 2) & 127;
        int kc = c & 3;
        const __half* bp = (p == 0) ? Ah : (p == 1) ? Al : (p == 2) ? Bh : Bl;
        int row = ((p < 2) ? m0 : n0) + r;
        gsrc[it] = bp + (size_t)row * KD + kc * 8;
        sdst[it] = (uint32_t)(p * PLANE + r * 64 + ((kc ^ ((r >> 1) & 3)) << 4));
    }

    const int ra = lane & 15;
    const int ksel_a = lane >> 4;
    int rowA[2], swzA[2];
#pragma unroll
    for (int f = 0; f < 2; f++) {
        rowA[f] = mw * 32 + f * 16 + ra;
        swzA[f] = (rowA[f] >> 1) & 3;
    }
    const int rb = (lane & 7) + 8 * (lane >> 4);
    const int ksel_b = (lane >> 3) & 1;
    int rowB[4], swzB[4];
#pragma unroll
    for (int g = 0; g < 4; g++) {
        rowB[g] = nw * 64 + g * 16 + rb;
        swzB[g] = (rowB[g] >> 1) & 3;
    }

    float acc[2][8][4] = {};

#pragma unroll
    for (int pt = 0; pt < 2; pt++) {
        uint32_t sb = sbase + pt * STAGE_BYTES;
#pragma unroll
        for (int it = 0; it < 8; it++) cpa16(sb + sdst[it], gsrc[it] + pt * 32);
        cpa_commit();
    }

    for (int t = 0; t < NCH; t++) {
        cpa_wait<1>();
        __syncthreads();

        if (t + 2 < NCH) {
            uint32_t sb = sbase + ((t + 2) % NSTAGE) * STAGE_BYTES;
#pragma unroll
            for (int it = 0; it < 8; it++) cpa16(sb + sdst[it], gsrc[it] + (t + 2) * 32);
        }
        cpa_commit();

        const uint32_t sb = sbase + (t % NSTAGE) * STAGE_BYTES;
#pragma unroll
        for (int s16 = 0; s16 < 2; s16++) {
            uint32_t ah[2][4], al[2][4];
#pragma unroll
            for (int f = 0; f < 2; f++) {
                uint32_t off = (uint32_t)(rowA[f] * 64 +
                               (((2 * s16 + ksel_a) ^ swzA[f]) << 4));
                ldm4(ah[f], sb + off);
                if (full) ldm4(al[f], sb + PLANE + off);
            }
#pragma unroll
            for (int g = 0; g < 4; g++) {
                uint32_t offb = (uint32_t)(rowB[g] * 64 +
                                (((2 * s16 + ksel_b) ^ swzB[g]) << 4));
                uint32_t bh[4], bl[4];
                ldm4(bh, sb + 2 * PLANE + offb);
                ldm4(bl, sb + 3 * PLANE + offb);
#pragma unroll
                for (int f = 0; f < 2; f++) {
#pragma unroll
                    for (int j = 0; j < 2; j++) {
                        float* d = acc[f][g * 2 + j];
                        mma16(d, ah[f], bh[2 * j], bh[2 * j + 1]);
                        mma16(d, ah[f], bl[2 * j], bl[2 * j + 1]);
                        if (full) mma16(d, al[f], bh[2 * j], bh[2 * j + 1]);
                    }
                }
            }
        }
    }

    const int er = lane >> 2, ec = (lane & 3) * 2;
#pragma unroll
    for (int f = 0; f < 2; f++) {
        int r = m0 + mw * 32 + f * 16 + er;
#pragma unroll
        for (int j8 = 0; j8 < 8; j8++) {
            int cc = n0 + nw * 64 + j8 * 8 + ec;
            if (Ch) {
                uint32_t lo0, lo1;
                uint32_t hi0 = pkf(acc[f][j8][0], acc[f][j8][1], &lo0);
                uint32_t hi1 = pkf(acc[f][j8][2], acc[f][j8][3], &lo1);
                *(uint32_t*)(Ch + (size_t)r * N + cc) = hi0;
                *(uint32_t*)(Cl + (size_t)r * N + cc) = lo0;
                *(uint32_t*)(Ch + (size_t)(r + 8) * N + cc) = hi1;
                *(uint32_t*)(Cl + (size_t)(r + 8) * N + cc) = lo1;
            } else {
                *(float2*)(C + (size_t)r * N + cc) =
                    make_float2(acc[f][j8][0], acc[f][j8][1]);
                *(float2*)(C + (size_t)(r + 8) * N + cc) =
                    make_float2(acc[f][j8][2], acc[f][j8][3]);
            }
        }
    }
}

// ---------------------------------------------------------------------------
// fp16 mma flash attention: S 3-mma, PV 1-mma (V single fp16).
// KV stage = Kh,Kl,Vh (24KB); smem ~80KB -> 2 CTAs/SM.
// ---------------------------------------------------------------------------
#define AQ 128
#define AKV 64
#define QH_OFF   0
#define QL_OFF   16384
#define ST_OFF   32768
#define AST      24576     // per-stage: Kh@0, Kl@8192, Vh@16384
#define QSC_OFF  (ST_OFF + 2 * AST)
#define ATTN2_SMEM (QSC_OFF + 256)

__global__ __launch_bounds__(256, 2)
void attn_mma2(const float* __restrict__ qm,
               const __half* __restrict__ qkvh,
               const __half* __restrict__ qkvl,
               __half* __restrict__ yh)
{
    extern __shared__ char smem[];
    const uint32_t sb = (uint32_t)__cvta_generic_to_shared(smem);
    float* qsc = (float*)(smem + QSC_OFF);
    const int tid = threadIdx.x, lane = tid & 31, warp = tid >> 5;
    // LPT: largest-nT q-tiles launch first
    const int qt = (int)gridDim.x - 1 - (int)blockIdx.x;
    const int h = blockIdx.y, b = blockIdx.z;
    const int q0 = qt * AQ;

    if (tid < 64) qsc[tid] = logf(2048.0f) * qm[tid] * rsqrtf(64.0f);

    // KV loader: 6 x 16B per thread per stage (planes: Kh, Kl, Vh)
    const __half* kvsrc[6];
    uint32_t kvdst[6];
#pragma unroll
    for (int it = 0; it < 6; it++) {
        int c = tid + it * 256;
        int p = c >> 9, r = (c >> 3) & 63, ch = c & 7;
        const __half* bp = (p == 1) ? qkvl : qkvh;
        int col = ((p == 2) ? 2 * C_DIM : C_DIM) + h * DH + ch * 8;
        kvsrc[it] = bp + (size_t)(b * T_SEQ + r) * C3 + col;
        kvdst[it] = (uint32_t)(p * 8192 + r * 128 + ((ch ^ (r & 7)) << 4));
    }
#pragma unroll
    for (int it = 0; it < 6; it++) cpa16(sb + ST_OFF + kvdst[it], kvsrc[it]);
    cpa_commit();

    __syncthreads();

    // Q load: combine hi+lo, scale, re-split
#pragma unroll
    for (int it = 0; it < 4; it++) {
        int u = tid + it * 256;
        int r = u >> 3, ch = u & 7;
        size_t src = (size_t)(b * T_SEQ + q0 + r) * C3 + h * DH + ch * 8;
        uint4 hv = *(const uint4*)(qkvh + src);
        uint4 lv = *(const uint4*)(qkvl + src);
        const __half2* hp = (const __half2*)&hv;
        const __half2* lp = (const __half2*)&lv;
        uint32_t oh[4], ol[4];
#pragma unroll
        for (int k = 0; k < 4; k++) {
            float2 hf = __half22float2(hp[k]);
            float2 lf = __half22float2(lp[k]);
            float v0 = (hf.x + lf.x) * qsc[ch * 8 + 2 * k];
            float v1 = (hf.y + lf.y) * qsc[ch * 8 + 2 * k + 1];
            oh[k] = pkf(v0, v1, &ol[k]);
        }
        uint32_t off = (uint32_t)(r * 128 + ((ch ^ (r & 7)) << 4));
        *(uint4*)(smem + QH_OFF + off) = make_uint4(oh[0], oh[1], oh[2], oh[3]);
        *(uint4*)(smem + QL_OFF + off) = make_uint4(ol[0], ol[1], ol[2], ol[3]);
    }

    float m0 = -1e30f, m1 = -1e30f, l0 = 0.0f, l1 = 0.0f;
    float acc[8][4] = {};

    const int maxc = (q0 + AQ > MEMLEN) ? (q0 + AQ) : MEMLEN;
    const int nT = maxc / AKV;

    for (int t = 0; t < nT; t++) {
        cpa_wait<0>();
        __syncthreads();
        if (t + 1 < nT) {
            uint32_t stb = sb + ST_OFF + ((t + 1) & 1) * AST;
            size_t delta = (size_t)(t + 1) * AKV * C3;
#pragma unroll
            for (int it = 0; it < 6; it++) cpa16(stb + kvdst[it], kvsrc[it] + delta);
            cpa_commit();
        }
        const uint32_t st = sb + ST_OFF + (t & 1) * AST;

        // ---- S = Q K^T (3-mma fp16) ----
        float s_[8][4] = {};
#pragma unroll
        for (int kk = 0; kk < 4; kk++) {
            uint32_t aH[4], aL[4];
            {
                int row = 16 * warp + (lane & 15);
                int ch = kk * 2 + (lane >> 4);
                uint32_t off = (uint32_t)(row * 128 + ((ch ^ (row & 7)) << 4));
                ldm4(aH, sb + QH_OFF + off);
                ldm4(aL, sb + QL_OFF + off);
            }
#pragma unroll
            for (int jj = 0; jj < 4; jj++) {
                int row = 16 * jj + 8 * (lane >> 4) + (lane & 7);
                int ch = kk * 2 + ((lane >> 3) & 1);
                uint32_t off = (uint32_t)(row * 128 + ((ch ^ (row & 7)) << 4));
                uint32_t bH[4], bL[4];
                ldm4(bH, st + off);
                ldm4(bL, st + 8192 + off);
#pragma unroll
                for (int u = 0; u < 2; u++) {
                    float* d = s_[2 * jj + u];
                    mma16(d, aH, bH[2 * u], bH[2 * u + 1]);
                    mma16(d, aH, bL[2 * u], bL[2 * u + 1]);
                    mma16(d, aL, bH[2 * u], bH[2 * u + 1]);
                }
            }
        }

        const int kj0 = t * AKV;
        if (kj0 >= MEMLEN) {
            int r0g = q0 + 16 * warp + (lane >> 2);
            int cb = kj0 + 2 * (lane & 3);
#pragma unroll
            for (int j = 0; j < 8; j++) {
                int cg = cb + 8 * j;
                if (cg > r0g)         s_[j][0] = -1e30f;
                if (cg + 1 > r0g)     s_[j][1] = -1e30f;
                if (cg > r0g + 8)     s_[j][2] = -1e30f;
                if (cg + 1 > r0g + 8) s_[j][3] = -1e30f;
            }
        }

        // ---- online softmax ----
        float mx0 = -1e30f, mx1 = -1e30f;
#pragma unroll
        for (int j = 0; j < 8; j++) {
            mx0 = fmaxf(mx0, fmaxf(s_[j][0], s_[j][1]));
            mx1 = fmaxf(mx1, fmaxf(s_[j][2], s_[j][3]));
        }
        mx0 = fmaxf(mx0, __shfl_xor_sync(0xffffffffu, mx0, 1));
        mx0 = fmaxf(mx0, __shfl_xor_sync(0xffffffffu, mx0, 2));
        mx1 = fmaxf(mx1, __shfl_xor_sync(0xffffffffu, mx1, 1));
        mx1 = fmaxf(mx1, __shfl_xor_sync(0xffffffffu, mx1, 2));
        float mn0 = fmaxf(m0, mx0), mn1 = fmaxf(m1, mx1);
        float f0 = __expf(m0 - mn0), f1 = __expf(m1 - mn1);
        float sum0 = 0.0f, sum1 = 0.0f;
        uint32_t phA[8], phB[8];
#pragma unroll
        for (int j = 0; j < 8; j++) {
            float p0 = __expf(s_[j][0] - mn0);
            float p1 = __expf(s_[j][1] - mn0);
            float p2 = __expf(s_[j][2] - mn1);
            float p3 = __expf(s_[j][3] - mn1);
            sum0 += p0 + p1; sum1 += p2 + p3;
            phA[j] = pkh(p0, p1);
            phB[j] = pkh(p2, p3);
        }
        sum0 += __shfl_xor_sync(0xffffffffu, sum0, 1);
        sum0 += __shfl_xor_sync(0xffffffffu, sum0, 2);
        sum1 += __shfl_xor_sync(0xffffffffu, sum1, 1);
        sum1 += __shfl_xor_sync(0xffffffffu, sum1, 2);
        l0 = l0 * f0 + sum0; l1 = l1 * f1 + sum1;
        m0 = mn0; m1 = mn1;
#pragma unroll
        for (int j = 0; j < 8; j++) {
            acc[j][0] *= f0; acc[j][1] *= f0;
            acc[j][2] *= f1; acc[j][3] *= f1;
        }

        // ---- P @ V (1-mma: P fp16 x V single fp16) ----
#pragma unroll
        for (int jj = 0; jj < 4; jj++) {
            uint32_t pa[4] = {phA[2*jj], phB[2*jj], phA[2*jj+1], phB[2*jj+1]};
#pragma unroll
            for (int nn = 0; nn < 4; nn++) {
                int row = 16 * jj + 8 * ((lane >> 3) & 1) + (lane & 7);
                int ch = 2 * nn + (lane >> 4);
                uint32_t off = (uint32_t)(row * 128 + ((ch ^ (row & 7)) << 4));
                uint32_t vH[4];
                ldm4t(vH, st + 16384 + off);
#pragma unroll
                for (int u = 0; u < 2; u++)
                    mma16(acc[2 * nn + u], pa, vH[2 * u], vH[2 * u + 1]);
            }
        }
    }

    // ---- epilogue ----
    {
        float i0 = 1.0f / l0, i1 = 1.0f / l1;
        size_t r0 = (size_t)(b * T_SEQ + q0 + 16 * warp + (lane >> 2));
        int cb = h * DH + 2 * (lane & 3);
#pragma unroll
        for (int j = 0; j < 8; j++) {
            int cc = cb + 8 * j;
            *(uint32_t*)(yh + r0 * C_DIM + cc)       = pkh(acc[j][0] * i0, acc[j][1] * i0);
            *(uint32_t*)(yh + (r0 + 8) * C_DIM + cc) = pkh(acc[j][2] * i1, acc[j][3] * i1);
        }
    }
}

// ---------------------------------------------------------------------------
// Launch
// ---------------------------------------------------------------------------
extern "C" void kernel_launch(void* const* d_in, const int* in_sizes, int n_in,
                              void* d_out, int out_size)
{
    const float* x      = (const float*)d_in[0];
    const float* w_qkv  = (const float*)d_in[1];
    const float* w_proj = (const float*)d_in[2];
    const float* qm     = (const float*)d_in[3];
    float* out = (float*)d_out;

    static __half *p_xh = nullptr, *p_xl, *p_wqh, *p_wql, *p_wph, *p_wpl;
    static __half *p_qkvh, *p_qkvl, *p_yh;
    if (!p_xh) {
        cudaGetSymbolAddress((void**)&p_xh, g_xh);
        cudaGetSymbolAddress((void**)&p_xl, g_xl);
        cudaGetSymbolAddress((void**)&p_wqh, g_wqh);
        cudaGetSymbolAddress((void**)&p_wql, g_wql);
        cudaGetSymbolAddress((void**)&p_wph, g_wph);
        cudaGetSymbolAddress((void**)&p_wpl, g_wpl);
        cudaGetSymbolAddress((void**)&p_qkvh, g_qkvh);
        cudaGetSymbolAddress((void**)&p_qkvl, g_qkvl);
        cudaGetSymbolAddress((void**)&p_yh, g_yh);
        cudaFuncSetAttribute(gemm_fp16_kernel,
                             cudaFuncAttributeMaxDynamicSharedMemorySize, GEMM_SMEM);
        cudaFuncSetAttribute(attn_mma2,
                             cudaFuncAttributeMaxDynamicSharedMemorySize, ATTN2_SMEM);
    }

    // Split fp32 inputs into fp16 hi/lo planes
    split_kernel<<<(M_TOT * KD / 8 + 255) / 256, 256>>>(x, p_xh, p_xl, M_TOT * KD / 8);
    split_kernel<<<(C3 * KD / 8 + 255) / 256, 256>>>(w_qkv, p_wqh, p_wql, C3 * KD / 8);
    split_kernel<<<(C_DIM * KD / 8 + 255) / 256, 256>>>(w_proj, p_wph, p_wpl, C_DIM * KD / 8);

    // GEMM1: qkv = x @ w_qkv^T -> fp16 hi/lo planes (Q,K 3-mma; V 2-mma)
    {
        dim3 grid(C3 / 128, M_TOT / 128);
        gemm_fp16_kernel<<<grid, 256, GEMM_SMEM>>>(p_xh, p_xl, p_wqh, p_wql,
                                                   nullptr, p_qkvh, p_qkvl, C3,
                                                   2 * C_DIM);
    }

    // Fused attention -> y single fp16 plane
    {
        dim3 grid(T_SEQ / AQ, NH, B_SZ);
        attn_mma2<<<grid, 256, ATTN2_SMEM>>>(qm, p_qkvh, p_qkvl, p_yh);
    }

    // GEMM2: out = y @ w_proj^T -> fp32, 2-mma everywhere
    {
        dim3 grid(C_DIM / 128, M_TOT / 128);
        gemm_fp16_kernel<<<grid, 256, GEMM_SMEM>>>(p_yh, p_yh, p_wph, p_wpl,
                                                   out, nullptr, nullptr, C_DIM, 0);
    }
}

// round 12
// speedup vs baseline: 1.1301x; 1.0503x over previous
#include <cuda_runtime.h>
#include <cuda_fp16.h>
#include <math.h>
#include <stdint.h>

// Problem constants
#define B_SZ   2
#define T_SEQ  2048
#define C_DIM  1024
#define C3     3072
#define NH     16
#define DH     64
#define MEMLEN 1024
#define M_TOT  4096
#define KD     1024

// Scratch fp16 hi/lo planes (no cudaMalloc allowed)
__device__ __half g_xh[(size_t)M_TOT * KD];
__device__ __half g_xl[(size_t)M_TOT * KD];
__device__ __half g_wqh[(size_t)C3 * KD];
__device__ __half g_wql[(size_t)C3 * KD];
__device__ __half g_wph[(size_t)C_DIM * KD];
__device__ __half g_wpl[(size_t)C_DIM * KD];
__device__ __half g_qkvh[(size_t)M_TOT * C3];
__device__ __half g_qkvl[(size_t)M_TOT * C3];
__device__ __half g_yh[(size_t)M_TOT * KD];

// ---------------------------------------------------------------------------
// helpers
// ---------------------------------------------------------------------------
__device__ __forceinline__ uint32_t pk2(__half a, __half b) {
    __half2 t = __halves2half2(a, b);
    return *reinterpret_cast<uint32_t*>(&t);
}

__device__ __forceinline__ uint32_t pkh(float a, float b) {
    __half2 t = __floats2half2_rn(a, b);
    return *reinterpret_cast<uint32_t*>(&t);
}

__device__ __forceinline__ uint32_t pkf(float a, float b, uint32_t* lo) {
    __half ha = __float2half_rn(a), hb = __float2half_rn(b);
    __half la = __float2half_rn(a - __half2float(ha));
    __half lb = __float2half_rn(b - __half2float(hb));
    *lo = pk2(la, lb);
    return pk2(ha, hb);
}

__device__ __forceinline__ void ldm4(uint32_t r[4], uint32_t a) {
    asm volatile("ldmatrix.sync.aligned.m8n8.x4.shared.b16 {%0,%1,%2,%3},[%4];\n"
                 : "=r"(r[0]), "=r"(r[1]), "=r"(r[2]), "=r"(r[3]) : "r"(a));
}
__device__ __forceinline__ void ldm4t(uint32_t r[4], uint32_t a) {
    asm volatile("ldmatrix.sync.aligned.m8n8.x4.trans.shared.b16 {%0,%1,%2,%3},[%4];\n"
                 : "=r"(r[0]), "=r"(r[1]), "=r"(r[2]), "=r"(r[3]) : "r"(a));
}

__device__ __forceinline__ void mma16(float d[4], const uint32_t a[4],
                                      uint32_t b0, uint32_t b1) {
    asm volatile(
        "mma.sync.aligned.m16n8k16.row.col.f32.f16.f16.f32 "
        "{%0,%1,%2,%3},{%4,%5,%6,%7},{%8,%9},{%0,%1,%2,%3};\n"
        : "+f"(d[0]), "+f"(d[1]), "+f"(d[2]), "+f"(d[3])
        : "r"(a[0]), "r"(a[1]), "r"(a[2]), "r"(a[3]), "r"(b0), "r"(b1));
}

__device__ __forceinline__ void cpa16(uint32_t d, const void* g) {
    asm volatile("cp.async.cg.shared.global [%0], [%1], 16;" :: "r"(d), "l"(g) : "memory");
}
__device__ __forceinline__ void cpa_commit() {
    asm volatile("cp.async.commit_group;" ::: "memory");
}
template <int N>
__device__ __forceinline__ void cpa_wait() {
    asm volatile("cp.async.wait_group %0;" :: "n"(N) : "memory");
}

// ---------------------------------------------------------------------------
// Split fp32 -> fp16 hi/lo planes
// ---------------------------------------------------------------------------
__global__ __launch_bounds__(256)
void split_kernel(const float* __restrict__ src,
                  __half* __restrict__ hi,
                  __half* __restrict__ lo, int n8)
{
    int i = blockIdx.x * 256 + threadIdx.x;
    if (i >= n8) return;
    float4 v0 = ((const float4*)src)[2 * i];
    float4 v1 = ((const float4*)src)[2 * i + 1];
    float v[8] = {v0.x, v0.y, v0.z, v0.w, v1.x, v1.y, v1.z, v1.w};
    uint32_t hp[4], lp[4];
#pragma unroll
    for (int j = 0; j < 4; j++)
        hp[j] = pkf(v[2 * j], v[2 * j + 1], &lp[j]);
    ((uint4*)hi)[i] = make_uint4(hp[0], hp[1], hp[2], hp[3]);
    ((uint4*)lo)[i] = make_uint4(lp[0], lp[1], lp[2], lp[3]);
}

// ---------------------------------------------------------------------------
// fp16 split NT GEMM (256 thr, 8 warps of 32x64, 3-stage).
// Blocks with n0 < fullN: 3-mma, hi+lo output. Others: (1+useBl)-mma, hi-only
// output; Al plane never loaded; Bl plane loaded only when useBl.
// ---------------------------------------------------------------------------
#define PLANE        8192
#define STAGE_BYTES  32768
#define NSTAGE       3
#define GEMM_SMEM    (NSTAGE * STAGE_BYTES)
#define NCH          32

__global__ __launch_bounds__(256, 2)
void gemm_fp16_kernel(const __half* __restrict__ Ah,
                      const __half* __restrict__ Al,
                      const __half* __restrict__ Bh,
                      const __half* __restrict__ Bl,
                      float* __restrict__ C,
                      __half* __restrict__ Ch,
                      __half* __restrict__ Cl, int N, int fullN, int useBl)
{
    extern __shared__ char smem[];
    const uint32_t sbase = (uint32_t)__cvta_generic_to_shared(smem);
    const int tid = threadIdx.x, lane = tid & 31, warp = tid >> 5;
    const int m0 = blockIdx.y * 128, n0 = blockIdx.x * 128;
    const bool full = (n0 < fullN);
    const int mw = warp >> 1, nw = warp & 1;

    // it -> plane is uniform: it/2 == plane (0:Ah 1:Al 2:Bh 3:Bl)
    bool ld[8];
#pragma unroll
    for (int it = 0; it < 8; it++) {
        int p = it >> 1;
        ld[it] = (p == 0) || (p == 2) || (p == 1 && full) ||
                 (p == 3 && (full || useBl));
    }

    const __half* gsrc[8];
    uint32_t sdst[8];
#pragma unroll
    for (int it = 0; it < 8; it++) {
        int c = tid + it * 256;
        int p = c >> 9;
        int r = (c >> 2) & 127;
        int kc = c & 3;
        const __half* bp = (p == 0) ? Ah : (p == 1) ? Al : (p == 2) ? Bh : Bl;
        int row = ((p < 2) ? m0 : n0) + r;
        gsrc[it] = bp + (size_t)row * KD + kc * 8;
        sdst[it] = (uint32_t)(p * PLANE + r * 64 + ((kc ^ ((r >> 1) & 3)) << 4));
    }

    const int ra = lane & 15;
    const int ksel_a = lane >> 4;
    int rowA[2], swzA[2];
#pragma unroll
    for (int f = 0; f < 2; f++) {
        rowA[f] = mw * 32 + f * 16 + ra;
        swzA[f] = (rowA[f] >> 1) & 3;
    }
    const int rb = (lane & 7) + 8 * (lane >> 4);
    const int ksel_b = (lane >> 3) & 1;
    int rowB[4], swzB[4];
#pragma unroll
    for (int g = 0; g < 4; g++) {
        rowB[g] = nw * 64 + g * 16 + rb;
        swzB[g] = (rowB[g] >> 1) & 3;
    }

    float acc[2][8][4] = {};

#pragma unroll
    for (int pt = 0; pt < 2; pt++) {
        uint32_t sb = sbase + pt * STAGE_BYTES;
#pragma unroll
        for (int it = 0; it < 8; it++)
            if (ld[it]) cpa16(sb + sdst[it], gsrc[it] + pt * 32);
        cpa_commit();
    }

    for (int t = 0; t < NCH; t++) {
        cpa_wait<1>();
        __syncthreads();

        if (t + 2 < NCH) {
            uint32_t sb = sbase + ((t + 2) % NSTAGE) * STAGE_BYTES;
#pragma unroll
            for (int it = 0; it < 8; it++)
                if (ld[it]) cpa16(sb + sdst[it], gsrc[it] + (t + 2) * 32);
        }
        cpa_commit();

        const uint32_t sb = sbase + (t % NSTAGE) * STAGE_BYTES;
#pragma unroll
        for (int s16 = 0; s16 < 2; s16++) {
            uint32_t ah[2][4], al[2][4];
#pragma unroll
            for (int f = 0; f < 2; f++) {
                uint32_t off = (uint32_t)(rowA[f] * 64 +
                               (((2 * s16 + ksel_a) ^ swzA[f]) << 4));
                ldm4(ah[f], sb + off);
                if (full) ldm4(al[f], sb + PLANE + off);
            }
#pragma unroll
            for (int g = 0; g < 4; g++) {
                uint32_t offb = (uint32_t)(rowB[g] * 64 +
                                (((2 * s16 + ksel_b) ^ swzB[g]) << 4));
                uint32_t bh[4], bl[4];
                ldm4(bh, sb + 2 * PLANE + offb);
                if (full || useBl) ldm4(bl, sb + 3 * PLANE + offb);
#pragma unroll
                for (int f = 0; f < 2; f++) {
#pragma unroll
                    for (int j = 0; j < 2; j++) {
                        float* d = acc[f][g * 2 + j];
                        mma16(d, ah[f], bh[2 * j], bh[2 * j + 1]);
                        if (full || useBl) mma16(d, ah[f], bl[2 * j], bl[2 * j + 1]);
                        if (full) mma16(d, al[f], bh[2 * j], bh[2 * j + 1]);
                    }
                }
            }
        }
    }

    const int er = lane >> 2, ec = (lane & 3) * 2;
#pragma unroll
    for (int f = 0; f < 2; f++) {
        int r = m0 + mw * 32 + f * 16 + er;
#pragma unroll
        for (int j8 = 0; j8 < 8; j8++) {
            int cc = n0 + nw * 64 + j8 * 8 + ec;
            if (Ch) {
                if (full) {
                    uint32_t lo0, lo1;
                    uint32_t hi0 = pkf(acc[f][j8][0], acc[f][j8][1], &lo0);
                    uint32_t hi1 = pkf(acc[f][j8][2], acc[f][j8][3], &lo1);
                    *(uint32_t*)(Ch + (size_t)r * N + cc) = hi0;
                    *(uint32_t*)(Cl + (size_t)r * N + cc) = lo0;
                    *(uint32_t*)(Ch + (size_t)(r + 8) * N + cc) = hi1;
                    *(uint32_t*)(Cl + (size_t)(r + 8) * N + cc) = lo1;
                } else {
                    // V columns: attention reads only the hi plane
                    *(uint32_t*)(Ch + (size_t)r * N + cc) =
                        pkh(acc[f][j8][0], acc[f][j8][1]);
                    *(uint32_t*)(Ch + (size_t)(r + 8) * N + cc) =
                        pkh(acc[f][j8][2], acc[f][j8][3]);
                }
            } else {
                *(float2*)(C + (size_t)r * N + cc) =
                    make_float2(acc[f][j8][0], acc[f][j8][1]);
                *(float2*)(C + (size_t)(r + 8) * N + cc) =
                    make_float2(acc[f][j8][2], acc[f][j8][3]);
            }
        }
    }
}

// ---------------------------------------------------------------------------
// fp16 mma flash attention (unchanged from R11): S 3-mma, PV 1-mma.
// ---------------------------------------------------------------------------
#define AQ 128
#define AKV 64
#define QH_OFF   0
#define QL_OFF   16384
#define ST_OFF   32768
#define AST      24576     // per-stage: Kh@0, Kl@8192, Vh@16384
#define QSC_OFF  (ST_OFF + 2 * AST)
#define ATTN2_SMEM (QSC_OFF + 256)

__global__ __launch_bounds__(256, 2)
void attn_mma2(const float* __restrict__ qm,
               const __half* __restrict__ qkvh,
               const __half* __restrict__ qkvl,
               __half* __restrict__ yh)
{
    extern __shared__ char smem[];
    const uint32_t sb = (uint32_t)__cvta_generic_to_shared(smem);
    float* qsc = (float*)(smem + QSC_OFF);
    const int tid = threadIdx.x, lane = tid & 31, warp = tid >> 5;
    const int qt = (int)gridDim.x - 1 - (int)blockIdx.x;
    const int h = blockIdx.y, b = blockIdx.z;
    const int q0 = qt * AQ;

    if (tid < 64) qsc[tid] = logf(2048.0f) * qm[tid] * rsqrtf(64.0f);

    const __half* kvsrc[6];
    uint32_t kvdst[6];
#pragma unroll
    for (int it = 0; it < 6; it++) {
        int c = tid + it * 256;
        int p = c >> 9, r = (c >> 3) & 63, ch = c & 7;
        const __half* bp = (p == 1) ? qkvl : qkvh;
        int col = ((p == 2) ? 2 * C_DIM : C_DIM) + h * DH + ch * 8;
        kvsrc[it] = bp + (size_t)(b * T_SEQ + r) * C3 + col;
        kvdst[it] = (uint32_t)(p * 8192 + r * 128 + ((ch ^ (r & 7)) << 4));
    }
#pragma unroll
    for (int it = 0; it < 6; it++) cpa16(sb + ST_OFF + kvdst[it], kvsrc[it]);
    cpa_commit();

    __syncthreads();

#pragma unroll
    for (int it = 0; it < 4; it++) {
        int u = tid + it * 256;
        int r = u >> 3, ch = u & 7;
        size_t src = (size_t)(b * T_SEQ + q0 + r) * C3 + h * DH + ch * 8;
        uint4 hv = *(const uint4*)(qkvh + src);
        uint4 lv = *(const uint4*)(qkvl + src);
        const __half2* hp = (const __half2*)&hv;
        const __half2* lp = (const __half2*)&lv;
        uint32_t oh[4], ol[4];
#pragma unroll
        for (int k = 0; k < 4; k++) {
            float2 hf = __half22float2(hp[k]);
            float2 lf = __half22float2(lp[k]);
            float v0 = (hf.x + lf.x) * qsc[ch * 8 + 2 * k];
            float v1 = (hf.y + lf.y) * qsc[ch * 8 + 2 * k + 1];
            oh[k] = pkf(v0, v1, &ol[k]);
        }
        uint32_t off = (uint32_t)(r * 128 + ((ch ^ (r & 7)) << 4));
        *(uint4*)(smem + QH_OFF + off) = make_uint4(oh[0], oh[1], oh[2], oh[3]);
        *(uint4*)(smem + QL_OFF + off) = make_uint4(ol[0], ol[1], ol[2], ol[3]);
    }

    float m0 = -1e30f, m1 = -1e30f, l0 = 0.0f, l1 = 0.0f;
    float acc[8][4] = {};

    const int maxc = (q0 + AQ > MEMLEN) ? (q0 + AQ) : MEMLEN;
    const int nT = maxc / AKV;

    for (int t = 0; t < nT; t++) {
        cpa_wait<0>();
        __syncthreads();
        if (t + 1 < nT) {
            uint32_t stb = sb + ST_OFF + ((t + 1) & 1) * AST;
            size_t delta = (size_t)(t + 1) * AKV * C3;
#pragma unroll
            for (int it = 0; it < 6; it++) cpa16(stb + kvdst[it], kvsrc[it] + delta);
            cpa_commit();
        }
        const uint32_t st = sb + ST_OFF + (t & 1) * AST;

        float s_[8][4] = {};
#pragma unroll
        for (int kk = 0; kk < 4; kk++) {
            uint32_t aH[4], aL[4];
            {
                int row = 16 * warp + (lane & 15);
                int ch = kk * 2 + (lane >> 4);
                uint32_t off = (uint32_t)(row * 128 + ((ch ^ (row & 7)) << 4));
                ldm4(aH, sb + QH_OFF + off);
                ldm4(aL, sb + QL_OFF + off);
            }
#pragma unroll
            for (int jj = 0; jj < 4; jj++) {
                int row = 16 * jj + 8 * (lane >> 4) + (lane & 7);
                int ch = kk * 2 + ((lane >> 3) & 1);
                uint32_t off = (uint32_t)(row * 128 + ((ch ^ (row & 7)) << 4));
                uint32_t bH[4], bL[4];
                ldm4(bH, st + off);
                ldm4(bL, st + 8192 + off);
#pragma unroll
                for (int u = 0; u < 2; u++) {
                    float* d = s_[2 * jj + u];
                    mma16(d, aH, bH[2 * u], bH[2 * u + 1]);
                    mma16(d, aH, bL[2 * u], bL[2 * u + 1]);
                    mma16(d, aL, bH[2 * u], bH[2 * u + 1]);
                }
            }
        }

        const int kj0 = t * AKV;
        if (kj0 >= MEMLEN) {
            int r0g = q0 + 16 * warp + (lane >> 2);
            int cb = kj0 + 2 * (lane & 3);
#pragma unroll
            for (int j = 0; j < 8; j++) {
                int cg = cb + 8 * j;
                if (cg > r0g)         s_[j][0] = -1e30f;
                if (cg + 1 > r0g)     s_[j][1] = -1e30f;
                if (cg > r0g + 8)     s_[j][2] = -1e30f;
                if (cg + 1 > r0g + 8) s_[j][3] = -1e30f;
            }
        }

        float mx0 = -1e30f, mx1 = -1e30f;
#pragma unroll
        for (int j = 0; j < 8; j++) {
            mx0 = fmaxf(mx0, fmaxf(s_[j][0], s_[j][1]));
            mx1 = fmaxf(mx1, fmaxf(s_[j][2], s_[j][3]));
        }
        mx0 = fmaxf(mx0, __shfl_xor_sync(0xffffffffu, mx0, 1));
        mx0 = fmaxf(mx0, __shfl_xor_sync(0xffffffffu, mx0, 2));
        mx1 = fmaxf(mx1, __shfl_xor_sync(0xffffffffu, mx1, 1));
        mx1 = fmaxf(mx1, __shfl_xor_sync(0xffffffffu, mx1, 2));
        float mn0 = fmaxf(m0, mx0), mn1 = fmaxf(m1, mx1);
        float f0 = __expf(m0 - mn0), f1 = __expf(m1 - mn1);
        float sum0 = 0.0f, sum1 = 0.0f;
        uint32_t phA[8], phB[8];
#pragma unroll
        for (int j = 0; j < 8; j++) {
            float p0 = __expf(s_[j][0] - mn0);
            float p1 = __expf(s_[j][1] - mn0);
            float p2 = __expf(s_[j][2] - mn1);
            float p3 = __expf(s_[j][3] - mn1);
            sum0 += p0 + p1; sum1 += p2 + p3;
            phA[j] = pkh(p0, p1);
            phB[j] = pkh(p2, p3);
        }
        sum0 += __shfl_xor_sync(0xffffffffu, sum0, 1);
        sum0 += __shfl_xor_sync(0xffffffffu, sum0, 2);
        sum1 += __shfl_xor_sync(0xffffffffu, sum1, 1);
        sum1 += __shfl_xor_sync(0xffffffffu, sum1, 2);
        l0 = l0 * f0 + sum0; l1 = l1 * f1 + sum1;
        m0 = mn0; m1 = mn1;
#pragma unroll
        for (int j = 0; j < 8; j++) {
            acc[j][0] *= f0; acc[j][1] *= f0;
            acc[j][2] *= f1; acc[j][3] *= f1;
        }

#pragma unroll
        for (int jj = 0; jj < 4; jj++) {
            uint32_t pa[4] = {phA[2*jj], phB[2*jj], phA[2*jj+1], phB[2*jj+1]};
#pragma unroll
            for (int nn = 0; nn < 4; nn++) {
                int row = 16 * jj + 8 * ((lane >> 3) & 1) + (lane & 7);
                int ch = 2 * nn + (lane >> 4);
                uint32_t off = (uint32_t)(row * 128 + ((ch ^ (row & 7)) << 4));
                uint32_t vH[4];
                ldm4t(vH, st + 16384 + off);
#pragma unroll
                for (int u = 0; u < 2; u++)
                    mma16(acc[2 * nn + u], pa, vH[2 * u], vH[2 * u + 1]);
            }
        }
    }

    {
        float i0 = 1.0f / l0, i1 = 1.0f / l1;
        size_t r0 = (size_t)(b * T_SEQ + q0 + 16 * warp + (lane >> 2));
        int cb = h * DH + 2 * (lane & 3);
#pragma unroll
        for (int j = 0; j < 8; j++) {
            int cc = cb + 8 * j;
            *(uint32_t*)(yh + r0 * C_DIM + cc)       = pkh(acc[j][0] * i0, acc[j][1] * i0);
            *(uint32_t*)(yh + (r0 + 8) * C_DIM + cc) = pkh(acc[j][2] * i1, acc[j][3] * i1);
        }
    }
}

// ---------------------------------------------------------------------------
// Launch
// ---------------------------------------------------------------------------
extern "C" void kernel_launch(void* const* d_in, const int* in_sizes, int n_in,
                              void* d_out, int out_size)
{
    const float* x      = (const float*)d_in[0];
    const float* w_qkv  = (const float*)d_in[1];
    const float* w_proj = (const float*)d_in[2];
    const float* qm     = (const float*)d_in[3];
    float* out = (float*)d_out;

    static __half *p_xh = nullptr, *p_xl, *p_wqh, *p_wql, *p_wph, *p_wpl;
    static __half *p_qkvh, *p_qkvl, *p_yh;
    if (!p_xh) {
        cudaGetSymbolAddress((void**)&p_xh, g_xh);
        cudaGetSymbolAddress((void**)&p_xl, g_xl);
        cudaGetSymbolAddress((void**)&p_wqh, g_wqh);
        cudaGetSymbolAddress((void**)&p_wql, g_wql);
        cudaGetSymbolAddress((void**)&p_wph, g_wph);
        cudaGetSymbolAddress((void**)&p_wpl, g_wpl);
        cudaGetSymbolAddress((void**)&p_qkvh, g_qkvh);
        cudaGetSymbolAddress((void**)&p_qkvl, g_qkvl);
        cudaGetSymbolAddress((void**)&p_yh, g_yh);
        cudaFuncSetAttribute(gemm_fp16_kernel,
                             cudaFuncAttributeMaxDynamicSharedMemorySize, GEMM_SMEM);
        cudaFuncSetAttribute(attn_mma2,
                             cudaFuncAttributeMaxDynamicSharedMemorySize, ATTN2_SMEM);
    }

    // Split fp32 inputs into fp16 hi/lo planes
    split_kernel<<<(M_TOT * KD / 8 + 255) / 256, 256>>>(x, p_xh, p_xl, M_TOT * KD / 8);
    split_kernel<<<(C3 * KD / 8 + 255) / 256, 256>>>(w_qkv, p_wqh, p_wql, C3 * KD / 8);
    split_kernel<<<(C_DIM * KD / 8 + 255) / 256, 256>>>(w_proj, p_wph, p_wpl, C_DIM * KD / 8);

    // GEMM1: qkv = x @ w_qkv^T. Q,K cols: 3-mma hi/lo out. V cols: 2-mma
    // (useBl=1), hi-only out, Al plane not loaded.
    {
        dim3 grid(C3 / 128, M_TOT / 128);
        gemm_fp16_kernel<<<grid, 256, GEMM_SMEM>>>(p_xh, p_xl, p_wqh, p_wql,
                                                   nullptr, p_qkvh, p_qkvl, C3,
                                                   2 * C_DIM, 1);
    }

    // Fused attention -> y single fp16 plane
    {
        dim3 grid(T_SEQ / AQ, NH, B_SZ);
        attn_mma2<<<grid, 256, ATTN2_SMEM>>>(qm, p_qkvh, p_qkvl, p_yh);
    }

    // GEMM2: out = y @ w_proj^T -> fp32. 1-mma (useBl=0): only yh x wph,
    // Al/Bl planes not loaded.
    {
        dim3 grid(C_DIM / 128, M_TOT / 128);
        gemm_fp16_kernel<<<grid, 256, GEMM_SMEM>>>(p_yh, p_yh, p_wph, p_wpl,
                                                   out, nullptr, nullptr, C_DIM,
                                                   0, 0);
    }
}

// round 13
// speedup vs baseline: 1.2182x; 1.0780x over previous
#include <cuda_runtime.h>
#include <cuda_fp16.h>
#include <math.h>
#include <stdint.h>

// Problem constants
#define B_SZ   2
#define T_SEQ  2048
#define C_DIM  1024
#define C3     3072
#define NH     16
#define DH     64
#define MEMLEN 1024
#define M_TOT  4096
#define KD     1024

// Scratch fp16 hi/lo planes (no cudaMalloc allowed)
__device__ __half g_xh[(size_t)M_TOT * KD];
__device__ __half g_xl[(size_t)M_TOT * KD];
__device__ __half g_wqh[(size_t)C3 * KD];
__device__ __half g_wql[(size_t)C3 * KD];
__device__ __half g_wph[(size_t)C_DIM * KD];
__device__ __half g_wpl[(size_t)C_DIM * KD];
__device__ __half g_qkvh[(size_t)M_TOT * C3];
__device__ __half g_qkvl[(size_t)M_TOT * C3];
__device__ __half g_yh[(size_t)M_TOT * KD];

// ---------------------------------------------------------------------------
// helpers
// ---------------------------------------------------------------------------
__device__ __forceinline__ uint32_t pk2(__half a, __half b) {
    __half2 t = __halves2half2(a, b);
    return *reinterpret_cast<uint32_t*>(&t);
}

__device__ __forceinline__ uint32_t pkh(float a, float b) {
    __half2 t = __floats2half2_rn(a, b);
    return *reinterpret_cast<uint32_t*>(&t);
}

__device__ __forceinline__ uint32_t pkf(float a, float b, uint32_t* lo) {
    __half ha = __float2half_rn(a), hb = __float2half_rn(b);
    __half la = __float2half_rn(a - __half2float(ha));
    __half lb = __float2half_rn(b - __half2float(hb));
    *lo = pk2(la, lb);
    return pk2(ha, hb);
}

__device__ __forceinline__ void ldm4(uint32_t r[4], uint32_t a) {
    asm volatile("ldmatrix.sync.aligned.m8n8.x4.shared.b16 {%0,%1,%2,%3},[%4];\n"
                 : "=r"(r[0]), "=r"(r[1]), "=r"(r[2]), "=r"(r[3]) : "r"(a));
}
__device__ __forceinline__ void ldm4t(uint32_t r[4], uint32_t a) {
    asm volatile("ldmatrix.sync.aligned.m8n8.x4.trans.shared.b16 {%0,%1,%2,%3},[%4];\n"
                 : "=r"(r[0]), "=r"(r[1]), "=r"(r[2]), "=r"(r[3]) : "r"(a));
}

__device__ __forceinline__ void mma16(float d[4], const uint32_t a[4],
                                      uint32_t b0, uint32_t b1) {
    asm volatile(
        "mma.sync.aligned.m16n8k16.row.col.f32.f16.f16.f32 "
        "{%0,%1,%2,%3},{%4,%5,%6,%7},{%8,%9},{%0,%1,%2,%3};\n"
        : "+f"(d[0]), "+f"(d[1]), "+f"(d[2]), "+f"(d[3])
        : "r"(a[0]), "r"(a[1]), "r"(a[2]), "r"(a[3]), "r"(b0), "r"(b1));
}

__device__ __forceinline__ void cpa16(uint32_t d, const void* g) {
    asm volatile("cp.async.cg.shared.global [%0], [%1], 16;" :: "r"(d), "l"(g) : "memory");
}
__device__ __forceinline__ void cpa_commit() {
    asm volatile("cp.async.commit_group;" ::: "memory");
}
template <int N>
__device__ __forceinline__ void cpa_wait() {
    asm volatile("cp.async.wait_group %0;" :: "n"(N) : "memory");
}

// ---------------------------------------------------------------------------
// Split fp32 -> fp16 hi/lo planes
// ---------------------------------------------------------------------------
__global__ __launch_bounds__(256)
void split_kernel(const float* __restrict__ src,
                  __half* __restrict__ hi,
                  __half* __restrict__ lo, int n8)
{
    int i = blockIdx.x * 256 + threadIdx.x;
    if (i >= n8) return;
    float4 v0 = ((const float4*)src)[2 * i];
    float4 v1 = ((const float4*)src)[2 * i + 1];
    float v[8] = {v0.x, v0.y, v0.z, v0.w, v1.x, v1.y, v1.z, v1.w};
    uint32_t hp[4], lp[4];
#pragma unroll
    for (int j = 0; j < 4; j++)
        hp[j] = pkf(v[2 * j], v[2 * j + 1], &lp[j]);
    ((uint4*)hi)[i] = make_uint4(hp[0], hp[1], hp[2], hp[3]);
    ((uint4*)lo)[i] = make_uint4(lp[0], lp[1], lp[2], lp[3]);
}

// ---------------------------------------------------------------------------
// fp16 split NT GEMM (unchanged from R12).
// Blocks with n0 < fullN: 3-mma, hi+lo output. Others: (1+useBl)-mma, hi-only
// output; Al plane never loaded; Bl plane loaded only when useBl.
// ---------------------------------------------------------------------------
#define PLANE        8192
#define STAGE_BYTES  32768
#define NSTAGE       3
#define GEMM_SMEM    (NSTAGE * STAGE_BYTES)
#define NCH          32

__global__ __launch_bounds__(256, 2)
void gemm_fp16_kernel(const __half* __restrict__ Ah,
                      const __half* __restrict__ Al,
                      const __half* __restrict__ Bh,
                      const __half* __restrict__ Bl,
                      float* __restrict__ C,
                      __half* __restrict__ Ch,
                      __half* __restrict__ Cl, int N, int fullN, int useBl)
{
    extern __shared__ char smem[];
    const uint32_t sbase = (uint32_t)__cvta_generic_to_shared(smem);
    const int tid = threadIdx.x, lane = tid & 31, warp = tid >> 5;
    const int m0 = blockIdx.y * 128, n0 = blockIdx.x * 128;
    const bool full = (n0 < fullN);
    const int mw = warp >> 1, nw = warp & 1;

    bool ld[8];
#pragma unroll
    for (int it = 0; it < 8; it++) {
        int p = it >> 1;
        ld[it] = (p == 0) || (p == 2) || (p == 1 && full) ||
                 (p == 3 && (full || useBl));
    }

    const __half* gsrc[8];
    uint32_t sdst[8];
#pragma unroll
    for (int it = 0; it < 8; it++) {
        int c = tid + it * 256;
        int p = c >> 9;
        int r = (c >> 2) & 127;
        int kc = c & 3;
        const __half* bp = (p == 0) ? Ah : (p == 1) ? Al : (p == 2) ? Bh : Bl;
        int row = ((p < 2) ? m0 : n0) + r;
        gsrc[it] = bp + (size_t)row * KD + kc * 8;
        sdst[it] = (uint32_t)(p * PLANE + r * 64 + ((kc ^ ((r >> 1) & 3)) << 4));
    }

    const int ra = lane & 15;
    const int ksel_a = lane >> 4;
    int rowA[2], swzA[2];
#pragma unroll
    for (int f = 0; f < 2; f++) {
        rowA[f] = mw * 32 + f * 16 + ra;
        swzA[f] = (rowA[f] >> 1) & 3;
    }
    const int rb = (lane & 7) + 8 * (lane >> 4);
    const int ksel_b = (lane >> 3) & 1;
    int rowB[4], swzB[4];
#pragma unroll
    for (int g = 0; g < 4; g++) {
        rowB[g] = nw * 64 + g * 16 + rb;
        swzB[g] = (rowB[g] >> 1) & 3;
    }

    float acc[2][8][4] = {};

#pragma unroll
    for (int pt = 0; pt < 2; pt++) {
        uint32_t sb = sbase + pt * STAGE_BYTES;
#pragma unroll
        for (int it = 0; it < 8; it++)
            if (ld[it]) cpa16(sb + sdst[it], gsrc[it] + pt * 32);
        cpa_commit();
    }

    for (int t = 0; t < NCH; t++) {
        cpa_wait<1>();
        __syncthreads();

        if (t + 2 < NCH) {
            uint32_t sb = sbase + ((t + 2) % NSTAGE) * STAGE_BYTES;
#pragma unroll
            for (int it = 0; it < 8; it++)
                if (ld[it]) cpa16(sb + sdst[it], gsrc[it] + (t + 2) * 32);
        }
        cpa_commit();

        const uint32_t sb = sbase + (t % NSTAGE) * STAGE_BYTES;
#pragma unroll
        for (int s16 = 0; s16 < 2; s16++) {
            uint32_t ah[2][4], al[2][4];
#pragma unroll
            for (int f = 0; f < 2; f++) {
                uint32_t off = (uint32_t)(rowA[f] * 64 +
                               (((2 * s16 + ksel_a) ^ swzA[f]) << 4));
                ldm4(ah[f], sb + off);
                if (full) ldm4(al[f], sb + PLANE + off);
            }
#pragma unroll
            for (int g = 0; g < 4; g++) {
                uint32_t offb = (uint32_t)(rowB[g] * 64 +
                                (((2 * s16 + ksel_b) ^ swzB[g]) << 4));
                uint32_t bh[4], bl[4];
                ldm4(bh, sb + 2 * PLANE + offb);
                if (full || useBl) ldm4(bl, sb + 3 * PLANE + offb);
#pragma unroll
                for (int f = 0; f < 2; f++) {
#pragma unroll
                    for (int j = 0; j < 2; j++) {
                        float* d = acc[f][g * 2 + j];
                        mma16(d, ah[f], bh[2 * j], bh[2 * j + 1]);
                        if (full || useBl) mma16(d, ah[f], bl[2 * j], bl[2 * j + 1]);
                        if (full) mma16(d, al[f], bh[2 * j], bh[2 * j + 1]);
                    }
                }
            }
        }
    }

    const int er = lane >> 2, ec = (lane & 3) * 2;
#pragma unroll
    for (int f = 0; f < 2; f++) {
        int r = m0 + mw * 32 + f * 16 + er;
#pragma unroll
        for (int j8 = 0; j8 < 8; j8++) {
            int cc = n0 + nw * 64 + j8 * 8 + ec;
            if (Ch) {
                if (full) {
                    uint32_t lo0, lo1;
                    uint32_t hi0 = pkf(acc[f][j8][0], acc[f][j8][1], &lo0);
                    uint32_t hi1 = pkf(acc[f][j8][2], acc[f][j8][3], &lo1);
                    *(uint32_t*)(Ch + (size_t)r * N + cc) = hi0;
                    *(uint32_t*)(Cl + (size_t)r * N + cc) = lo0;
                    *(uint32_t*)(Ch + (size_t)(r + 8) * N + cc) = hi1;
                    *(uint32_t*)(Cl + (size_t)(r + 8) * N + cc) = lo1;
                } else {
                    *(uint32_t*)(Ch + (size_t)r * N + cc) =
                        pkh(acc[f][j8][0], acc[f][j8][1]);
                    *(uint32_t*)(Ch + (size_t)(r + 8) * N + cc) =
                        pkh(acc[f][j8][2], acc[f][j8][3]);
                }
            } else {
                *(float2*)(C + (size_t)r * N + cc) =
                    make_float2(acc[f][j8][0], acc[f][j8][1]);
                *(float2*)(C + (size_t)(r + 8) * N + cc) =
                    make_float2(acc[f][j8][2], acc[f][j8][3]);
            }
        }
    }
}

// ---------------------------------------------------------------------------
// fp16 mma flash attention: S 2-mma (Q single fp16, K hi/lo), PV 1-mma.
// Q plane 16KB single; KV stage = Kh,Kl,Vh (24KB) x2; smem ~66KB.
// ---------------------------------------------------------------------------
#define AQ 128
#define AKV 64
#define QS_OFF   0
#define ST_OFF   16384
#define AST      24576     // per-stage: Kh@0, Kl@8192, Vh@16384
#define QSC_OFF  (ST_OFF + 2 * AST)
#define ATTN2_SMEM (QSC_OFF + 256)

__global__ __launch_bounds__(256, 2)
void attn_mma2(const float* __restrict__ qm,
               const __half* __restrict__ qkvh,
               const __half* __restrict__ qkvl,
               __half* __restrict__ yh)
{
    extern __shared__ char smem[];
    const uint32_t sb = (uint32_t)__cvta_generic_to_shared(smem);
    float* qsc = (float*)(smem + QSC_OFF);
    const int tid = threadIdx.x, lane = tid & 31, warp = tid >> 5;
    const int qt = (int)gridDim.x - 1 - (int)blockIdx.x;
    const int h = blockIdx.y, b = blockIdx.z;
    const int q0 = qt * AQ;

    if (tid < 64) qsc[tid] = logf(2048.0f) * qm[tid] * rsqrtf(64.0f);

    const __half* kvsrc[6];
    uint32_t kvdst[6];
#pragma unroll
    for (int it = 0; it < 6; it++) {
        int c = tid + it * 256;
        int p = c >> 9, r = (c >> 3) & 63, ch = c & 7;
        const __half* bp = (p == 1) ? qkvl : qkvh;
        int col = ((p == 2) ? 2 * C_DIM : C_DIM) + h * DH + ch * 8;
        kvsrc[it] = bp + (size_t)(b * T_SEQ + r) * C3 + col;
        kvdst[it] = (uint32_t)(p * 8192 + r * 128 + ((ch ^ (r & 7)) << 4));
    }
#pragma unroll
    for (int it = 0; it < 6; it++) cpa16(sb + ST_OFF + kvdst[it], kvsrc[it]);
    cpa_commit();

    __syncthreads();

    // Q load: combine hi+lo, scale, round once to fp16
#pragma unroll
    for (int it = 0; it < 4; it++) {
        int u = tid + it * 256;
        int r = u >> 3, ch = u & 7;
        size_t src = (size_t)(b * T_SEQ + q0 + r) * C3 + h * DH + ch * 8;
        uint4 hv = *(const uint4*)(qkvh + src);
        uint4 lv = *(const uint4*)(qkvl + src);
        const __half2* hp = (const __half2*)&hv;
        const __half2* lp = (const __half2*)&lv;
        uint32_t oh[4];
#pragma unroll
        for (int k = 0; k < 4; k++) {
            float2 hf = __half22float2(hp[k]);
            float2 lf = __half22float2(lp[k]);
            oh[k] = pkh((hf.x + lf.x) * qsc[ch * 8 + 2 * k],
                        (hf.y + lf.y) * qsc[ch * 8 + 2 * k + 1]);
        }
        uint32_t off = (uint32_t)(r * 128 + ((ch ^ (r & 7)) << 4));
        *(uint4*)(smem + QS_OFF + off) = make_uint4(oh[0], oh[1], oh[2], oh[3]);
    }

    float m0 = -1e30f, m1 = -1e30f, l0 = 0.0f, l1 = 0.0f;
    float acc[8][4] = {};

    const int maxc = (q0 + AQ > MEMLEN) ? (q0 + AQ) : MEMLEN;
    const int nT = maxc / AKV;

    for (int t = 0; t < nT; t++) {
        cpa_wait<0>();
        __syncthreads();
        if (t + 1 < nT) {
            uint32_t stb = sb + ST_OFF + ((t + 1) & 1) * AST;
            size_t delta = (size_t)(t + 1) * AKV * C3;
#pragma unroll
            for (int it = 0; it < 6; it++) cpa16(stb + kvdst[it], kvsrc[it] + delta);
            cpa_commit();
        }
        const uint32_t st = sb + ST_OFF + (t & 1) * AST;

        // ---- S = Q K^T (2-mma: Q single, K hi/lo) ----
        float s_[8][4] = {};
#pragma unroll
        for (int kk = 0; kk < 4; kk++) {
            uint32_t aH[4];
            {
                int row = 16 * warp + (lane & 15);
                int ch = kk * 2 + (lane >> 4);
                uint32_t off = (uint32_t)(row * 128 + ((ch ^ (row & 7)) << 4));
                ldm4(aH, sb + QS_OFF + off);
            }
#pragma unroll
            for (int jj = 0; jj < 4; jj++) {
                int row = 16 * jj + 8 * (lane >> 4) + (lane & 7);
                int ch = kk * 2 + ((lane >> 3) & 1);
                uint32_t off = (uint32_t)(row * 128 + ((ch ^ (row & 7)) << 4));
                uint32_t bH[4], bL[4];
                ldm4(bH, st + off);
                ldm4(bL, st + 8192 + off);
#pragma unroll
                for (int u = 0; u < 2; u++) {
                    float* d = s_[2 * jj + u];
                    mma16(d, aH, bH[2 * u], bH[2 * u + 1]);
                    mma16(d, aH, bL[2 * u], bL[2 * u + 1]);
                }
            }
        }

        const int kj0 = t * AKV;
        if (kj0 >= MEMLEN) {
            int r0g = q0 + 16 * warp + (lane >> 2);
            int cb = kj0 + 2 * (lane & 3);
#pragma unroll
            for (int j = 0; j < 8; j++) {
                int cg = cb + 8 * j;
                if (cg > r0g)         s_[j][0] = -1e30f;
                if (cg + 1 > r0g)     s_[j][1] = -1e30f;
                if (cg > r0g + 8)     s_[j][2] = -1e30f;
                if (cg + 1 > r0g + 8) s_[j][3] = -1e30f;
            }
        }

        // ---- online softmax ----
        float mx0 = -1e30f, mx1 = -1e30f;
#pragma unroll
        for (int j = 0; j < 8; j++) {
            mx0 = fmaxf(mx0, fmaxf(s_[j][0], s_[j][1]));
            mx1 = fmaxf(mx1, fmaxf(s_[j][2], s_[j][3]));
        }
        mx0 = fmaxf(mx0, __shfl_xor_sync(0xffffffffu, mx0, 1));
        mx0 = fmaxf(mx0, __shfl_xor_sync(0xffffffffu, mx0, 2));
        mx1 = fmaxf(mx1, __shfl_xor_sync(0xffffffffu, mx1, 1));
        mx1 = fmaxf(mx1, __shfl_xor_sync(0xffffffffu, mx1, 2));
        float mn0 = fmaxf(m0, mx0), mn1 = fmaxf(m1, mx1);
        float f0 = __expf(m0 - mn0), f1 = __expf(m1 - mn1);
        float sum0 = 0.0f, sum1 = 0.0f;
        uint32_t phA[8], phB[8];
#pragma unroll
        for (int j = 0; j < 8; j++) {
            float p0 = __expf(s_[j][0] - mn0);
            float p1 = __expf(s_[j][1] - mn0);
            float p2 = __expf(s_[j][2] - mn1);
            float p3 = __expf(s_[j][3] - mn1);
            sum0 += p0 + p1; sum1 += p2 + p3;
            phA[j] = pkh(p0, p1);
            phB[j] = pkh(p2, p3);
        }
        sum0 += __shfl_xor_sync(0xffffffffu, sum0, 1);
        sum0 += __shfl_xor_sync(0xffffffffu, sum0, 2);
        sum1 += __shfl_xor_sync(0xffffffffu, sum1, 1);
        sum1 += __shfl_xor_sync(0xffffffffu, sum1, 2);
        l0 = l0 * f0 + sum0; l1 = l1 * f1 + sum1;
        m0 = mn0; m1 = mn1;
#pragma unroll
        for (int j = 0; j < 8; j++) {
            acc[j][0] *= f0; acc[j][1] *= f0;
            acc[j][2] *= f1; acc[j][3] *= f1;
        }

        // ---- P @ V (1-mma) ----
#pragma unroll
        for (int jj = 0; jj < 4; jj++) {
            uint32_t pa[4] = {phA[2*jj], phB[2*jj], phA[2*jj+1], phB[2*jj+1]};
#pragma unroll
            for (int nn = 0; nn < 4; nn++) {
                int row = 16 * jj + 8 * ((lane >> 3) & 1) + (lane & 7);
                int ch = 2 * nn + (lane >> 4);
                uint32_t off = (uint32_t)(row * 128 + ((ch ^ (row & 7)) << 4));
                uint32_t vH[4];
                ldm4t(vH, st + 16384 + off);
#pragma unroll
                for (int u = 0; u < 2; u++)
                    mma16(acc[2 * nn + u], pa, vH[2 * u], vH[2 * u + 1]);
            }
        }
    }

    // ---- epilogue ----
    {
        float i0 = 1.0f / l0, i1 = 1.0f / l1;
        size_t r0 = (size_t)(b * T_SEQ + q0 + 16 * warp + (lane >> 2));
        int cb = h * DH + 2 * (lane & 3);
#pragma unroll
        for (int j = 0; j < 8; j++) {
            int cc = cb + 8 * j;
            *(uint32_t*)(yh + r0 * C_DIM + cc)       = pkh(acc[j][0] * i0, acc[j][1] * i0);
            *(uint32_t*)(yh + (r0 + 8) * C_DIM + cc) = pkh(acc[j][2] * i1, acc[j][3] * i1);
        }
    }
}

// ---------------------------------------------------------------------------
// Launch
// ---------------------------------------------------------------------------
extern "C" void kernel_launch(void* const* d_in, const int* in_sizes, int n_in,
                              void* d_out, int out_size)
{
    const float* x      = (const float*)d_in[0];
    const float* w_qkv  = (const float*)d_in[1];
    const float* w_proj = (const float*)d_in[2];
    const float* qm     = (const float*)d_in[3];
    float* out = (float*)d_out;

    static __half *p_xh = nullptr, *p_xl, *p_wqh, *p_wql, *p_wph, *p_wpl;
    static __half *p_qkvh, *p_qkvl, *p_yh;
    if (!p_xh) {
        cudaGetSymbolAddress((void**)&p_xh, g_xh);
        cudaGetSymbolAddress((void**)&p_xl, g_xl);
        cudaGetSymbolAddress((void**)&p_wqh, g_wqh);
        cudaGetSymbolAddress((void**)&p_wql, g_wql);
        cudaGetSymbolAddress((void**)&p_wph, g_wph);
        cudaGetSymbolAddress((void**)&p_wpl, g_wpl);
        cudaGetSymbolAddress((void**)&p_qkvh, g_qkvh);
        cudaGetSymbolAddress((void**)&p_qkvl, g_qkvl);
        cudaGetSymbolAddress((void**)&p_yh, g_yh);
        cudaFuncSetAttribute(gemm_fp16_kernel,
                             cudaFuncAttributeMaxDynamicSharedMemorySize, GEMM_SMEM);
        cudaFuncSetAttribute(attn_mma2,
                             cudaFuncAttributeMaxDynamicSharedMemorySize, ATTN2_SMEM);
    }

    // Split fp32 inputs into fp16 hi/lo planes
    split_kernel<<<(M_TOT * KD / 8 + 255) / 256, 256>>>(x, p_xh, p_xl, M_TOT * KD / 8);
    split_kernel<<<(C3 * KD / 8 + 255) / 256, 256>>>(w_qkv, p_wqh, p_wql, C3 * KD / 8);
    split_kernel<<<(C_DIM * KD / 8 + 255) / 256, 256>>>(w_proj, p_wph, p_wpl, C_DIM * KD / 8);

    // GEMM1: qkv = x @ w_qkv^T. Q,K cols: 3-mma hi/lo out. V cols: 2-mma
    // (useBl=1), hi-only out.
    {
        dim3 grid(C3 / 128, M_TOT / 128);
        gemm_fp16_kernel<<<grid, 256, GEMM_SMEM>>>(p_xh, p_xl, p_wqh, p_wql,
                                                   nullptr, p_qkvh, p_qkvl, C3,
                                                   2 * C_DIM, 1);
    }

    // Fused attention -> y single fp16 plane
    {
        dim3 grid(T_SEQ / AQ, NH, B_SZ);
        attn_mma2<<<grid, 256, ATTN2_SMEM>>>(qm, p_qkvh, p_qkvl, p_yh);
    }

    // GEMM2: out = y @ w_proj^T -> fp32. 1-mma (useBl=0).
    {
        dim3 grid(C_DIM / 128, M_TOT / 128);
        gemm_fp16_kernel<<<grid, 256, GEMM_SMEM>>>(p_yh, p_yh, p_wph, p_wpl,
                                                   out, nullptr, nullptr, C_DIM,
                                                   0, 0);
    }
}

// round 14
// speedup vs baseline: 1.2416x; 1.0192x over previous
#include <cuda_runtime.h>
#include <cuda_fp16.h>
#include <math.h>
#include <stdint.h>

// Problem constants
#define B_SZ   2
#define T_SEQ  2048
#define C_DIM  1024
#define C3     3072
#define NH     16
#define DH     64
#define MEMLEN 1024
#define M_TOT  4096
#define KD     1024

// Scratch fp16 hi/lo planes (no cudaMalloc allowed)
__device__ __half g_xh[(size_t)M_TOT * KD];
__device__ __half g_xl[(size_t)M_TOT * KD];
__device__ __half g_wqh[(size_t)C3 * KD];
__device__ __half g_wql[(size_t)C3 * KD];
__device__ __half g_wph[(size_t)C_DIM * KD];
__device__ __half g_wpl[(size_t)C_DIM * KD];
__device__ __half g_qkvh[(size_t)M_TOT * C3];
__device__ __half g_qkvl[(size_t)M_TOT * C3];
__device__ __half g_yh[(size_t)M_TOT * KD];

// ---------------------------------------------------------------------------
// helpers
// ---------------------------------------------------------------------------
__device__ __forceinline__ uint32_t pk2(__half a, __half b) {
    __half2 t = __halves2half2(a, b);
    return *reinterpret_cast<uint32_t*>(&t);
}

__device__ __forceinline__ uint32_t pkh(float a, float b) {
    __half2 t = __floats2half2_rn(a, b);
    return *reinterpret_cast<uint32_t*>(&t);
}

__device__ __forceinline__ uint32_t pkf(float a, float b, uint32_t* lo) {
    __half ha = __float2half_rn(a), hb = __float2half_rn(b);
    __half la = __float2half_rn(a - __half2float(ha));
    __half lb = __float2half_rn(b - __half2float(hb));
    *lo = pk2(la, lb);
    return pk2(ha, hb);
}

// raw ex2.approx (logits kept in log2 domain; no FMUL by log2e needed)
__device__ __forceinline__ float ex2f(float x) {
    float r;
    asm("ex2.approx.f32 %0, %1;" : "=f"(r) : "f"(x));
    return r;
}

__device__ __forceinline__ void ldm4(uint32_t r[4], uint32_t a) {
    asm volatile("ldmatrix.sync.aligned.m8n8.x4.shared.b16 {%0,%1,%2,%3},[%4];\n"
                 : "=r"(r[0]), "=r"(r[1]), "=r"(r[2]), "=r"(r[3]) : "r"(a));
}
__device__ __forceinline__ void ldm4t(uint32_t r[4], uint32_t a) {
    asm volatile("ldmatrix.sync.aligned.m8n8.x4.trans.shared.b16 {%0,%1,%2,%3},[%4];\n"
                 : "=r"(r[0]), "=r"(r[1]), "=r"(r[2]), "=r"(r[3]) : "r"(a));
}

__device__ __forceinline__ void mma16(float d[4], const uint32_t a[4],
                                      uint32_t b0, uint32_t b1) {
    asm volatile(
        "mma.sync.aligned.m16n8k16.row.col.f32.f16.f16.f32 "
        "{%0,%1,%2,%3},{%4,%5,%6,%7},{%8,%9},{%0,%1,%2,%3};\n"
        : "+f"(d[0]), "+f"(d[1]), "+f"(d[2]), "+f"(d[3])
        : "r"(a[0]), "r"(a[1]), "r"(a[2]), "r"(a[3]), "r"(b0), "r"(b1));
}

__device__ __forceinline__ void cpa16(uint32_t d, const void* g) {
    asm volatile("cp.async.cg.shared.global [%0], [%1], 16;" :: "r"(d), "l"(g) : "memory");
}
__device__ __forceinline__ void cpa_commit() {
    asm volatile("cp.async.commit_group;" ::: "memory");
}
template <int N>
__device__ __forceinline__ void cpa_wait() {
    asm volatile("cp.async.wait_group %0;" :: "n"(N) : "memory");
}

// ---------------------------------------------------------------------------
// Merged split: fp32 -> fp16 hi/lo for x, w_qkv, w_proj in ONE launch.
// Region boundaries in 8-float chunks.
// ---------------------------------------------------------------------------
#define N8_X   (M_TOT * KD / 8)        // 524288
#define N8_WQ  (C3 * KD / 8)           // 393216
#define N8_WP  (C_DIM * KD / 8)        // 131072
#define N8_ALL (N8_X + N8_WQ + N8_WP)  // 1048576

__global__ __launch_bounds__(256)
void split_all_kernel(const float* __restrict__ x,
                      const float* __restrict__ wq,
                      const float* __restrict__ wp,
                      __half* __restrict__ xh, __half* __restrict__ xl,
                      __half* __restrict__ wqh, __half* __restrict__ wql,
                      __half* __restrict__ wph, __half* __restrict__ wpl)
{
    int i = blockIdx.x * 256 + threadIdx.x;
    if (i >= N8_ALL) return;
    const float* src;
    __half *hi, *lo;
    int j = i;
    if (j < N8_X) { src = x; hi = xh; lo = xl; }
    else if ((j -= N8_X) < N8_WQ) { src = wq; hi = wqh; lo = wql; }
    else { j -= N8_WQ; src = wp; hi = wph; lo = wpl; }

    float4 v0 = ((const float4*)src)[2 * j];
    float4 v1 = ((const float4*)src)[2 * j + 1];
    float v[8] = {v0.x, v0.y, v0.z, v0.w, v1.x, v1.y, v1.z, v1.w};
    uint32_t hp[4], lp[4];
#pragma unroll
    for (int k = 0; k < 4; k++)
        hp[k] = pkf(v[2 * k], v[2 * k + 1], &lp[k]);
    ((uint4*)hi)[j] = make_uint4(hp[0], hp[1], hp[2], hp[3]);
    ((uint4*)lo)[j] = make_uint4(lp[0], lp[1], lp[2], lp[3]);
}

// ---------------------------------------------------------------------------
// fp16 split NT GEMM (unchanged from R12/R13).
// ---------------------------------------------------------------------------
#define PLANE        8192
#define STAGE_BYTES  32768
#define NSTAGE       3
#define GEMM_SMEM    (NSTAGE * STAGE_BYTES)
#define NCH          32

__global__ __launch_bounds__(256, 2)
void gemm_fp16_kernel(const __half* __restrict__ Ah,
                      const __half* __restrict__ Al,
                      const __half* __restrict__ Bh,
                      const __half* __restrict__ Bl,
                      float* __restrict__ C,
                      __half* __restrict__ Ch,
                      __half* __restrict__ Cl, int N, int fullN, int useBl)
{
    extern __shared__ char smem[];
    const uint32_t sbase = (uint32_t)__cvta_generic_to_shared(smem);
    const int tid = threadIdx.x, lane = tid & 31, warp = tid >> 5;
    const int m0 = blockIdx.y * 128, n0 = blockIdx.x * 128;
    const bool full = (n0 < fullN);
    const int mw = warp >> 1, nw = warp & 1;

    bool ld[8];
#pragma unroll
    for (int it = 0; it < 8; it++) {
        int p = it >> 1;
        ld[it] = (p == 0) || (p == 2) || (p == 1 && full) ||
                 (p == 3 && (full || useBl));
    }

    const __half* gsrc[8];
    uint32_t sdst[8];
#pragma unroll
    for (int it = 0; it < 8; it++) {
        int c = tid + it * 256;
        int p = c >> 9;
        int r = (c >> 2) & 127;
        int kc = c & 3;
        const __half* bp = (p == 0) ? Ah : (p == 1) ? Al : (p == 2) ? Bh : Bl;
        int row = ((p < 2) ? m0 : n0) + r;
        gsrc[it] = bp + (size_t)row * KD + kc * 8;
        sdst[it] = (uint32_t)(p * PLANE + r * 64 + ((kc ^ ((r >> 1) & 3)) << 4));
    }

    const int ra = lane & 15;
    const int ksel_a = lane >> 4;
    int rowA[2], swzA[2];
#pragma unroll
    for (int f = 0; f < 2; f++) {
        rowA[f] = mw * 32 + f * 16 + ra;
        swzA[f] = (rowA[f] >> 1) & 3;
    }
    const int rb = (lane & 7) + 8 * (lane >> 4);
    const int ksel_b = (lane >> 3) & 1;
    int rowB[4], swzB[4];
#pragma unroll
    for (int g = 0; g < 4; g++) {
        rowB[g] = nw * 64 + g * 16 + rb;
        swzB[g] = (rowB[g] >> 1) & 3;
    }

    float acc[2][8][4] = {};

#pragma unroll
    for (int pt = 0; pt < 2; pt++) {
        uint32_t sb = sbase + pt * STAGE_BYTES;
#pragma unroll
        for (int it = 0; it < 8; it++)
            if (ld[it]) cpa16(sb + sdst[it], gsrc[it] + pt * 32);
        cpa_commit();
    }

    for (int t = 0; t < NCH; t++) {
        cpa_wait<1>();
        __syncthreads();

        if (t + 2 < NCH) {
            uint32_t sb = sbase + ((t + 2) % NSTAGE) * STAGE_BYTES;
#pragma unroll
            for (int it = 0; it < 8; it++)
                if (ld[it]) cpa16(sb + sdst[it], gsrc[it] + (t + 2) * 32);
        }
        cpa_commit();

        const uint32_t sb = sbase + (t % NSTAGE) * STAGE_BYTES;
#pragma unroll
        for (int s16 = 0; s16 < 2; s16++) {
            uint32_t ah[2][4], al[2][4];
#pragma unroll
            for (int f = 0; f < 2; f++) {
                uint32_t off = (uint32_t)(rowA[f] * 64 +
                               (((2 * s16 + ksel_a) ^ swzA[f]) << 4));
                ldm4(ah[f], sb + off);
                if (full) ldm4(al[f], sb + PLANE + off);
            }
#pragma unroll
            for (int g = 0; g < 4; g++) {
                uint32_t offb = (uint32_t)(rowB[g] * 64 +
                                (((2 * s16 + ksel_b) ^ swzB[g]) << 4));
                uint32_t bh[4], bl[4];
                ldm4(bh, sb + 2 * PLANE + offb);
                if (full || useBl) ldm4(bl, sb + 3 * PLANE + offb);
#pragma unroll
                for (int f = 0; f < 2; f++) {
#pragma unroll
                    for (int j = 0; j < 2; j++) {
                        float* d = acc[f][g * 2 + j];
                        mma16(d, ah[f], bh[2 * j], bh[2 * j + 1]);
                        if (full || useBl) mma16(d, ah[f], bl[2 * j], bl[2 * j + 1]);
                        if (full) mma16(d, al[f], bh[2 * j], bh[2 * j + 1]);
                    }
                }
            }
        }
    }

    const int er = lane >> 2, ec = (lane & 3) * 2;
#pragma unroll
    for (int f = 0; f < 2; f++) {
        int r = m0 + mw * 32 + f * 16 + er;
#pragma unroll
        for (int j8 = 0; j8 < 8; j8++) {
            int cc = n0 + nw * 64 + j8 * 8 + ec;
            if (Ch) {
                if (full) {
                    uint32_t lo0, lo1;
                    uint32_t hi0 = pkf(acc[f][j8][0], acc[f][j8][1], &lo0);
                    uint32_t hi1 = pkf(acc[f][j8][2], acc[f][j8][3], &lo1);
                    *(uint32_t*)(Ch + (size_t)r * N + cc) = hi0;
                    *(uint32_t*)(Cl + (size_t)r * N + cc) = lo0;
                    *(uint32_t*)(Ch + (size_t)(r + 8) * N + cc) = hi1;
                    *(uint32_t*)(Cl + (size_t)(r + 8) * N + cc) = lo1;
                } else {
                    *(uint32_t*)(Ch + (size_t)r * N + cc) =
                        pkh(acc[f][j8][0], acc[f][j8][1]);
                    *(uint32_t*)(Ch + (size_t)(r + 8) * N + cc) =
                        pkh(acc[f][j8][2], acc[f][j8][3]);
                }
            } else {
                *(float2*)(C + (size_t)r * N + cc) =
                    make_float2(acc[f][j8][0], acc[f][j8][1]);
                *(float2*)(C + (size_t)(r + 8) * N + cc) =
                    make_float2(acc[f][j8][2], acc[f][j8][3]);
            }
        }
    }
}

// ---------------------------------------------------------------------------
// fp16 mma flash attention: S 2-mma (Q single, K hi/lo), PV 1-mma.
// log2-domain softmax: qsc premultiplied by log2(e); exp via raw ex2.approx.
// ---------------------------------------------------------------------------
#define AQ 128
#define AKV 64
#define QS_OFF   0
#define ST_OFF   16384
#define AST      24576     // per-stage: Kh@0, Kl@8192, Vh@16384
#define QSC_OFF  (ST_OFF + 2 * AST)
#define ATTN2_SMEM (QSC_OFF + 256)

__global__ __launch_bounds__(256, 2)
void attn_mma2(const float* __restrict__ qm,
               const __half* __restrict__ qkvh,
               const __half* __restrict__ qkvl,
               __half* __restrict__ yh)
{
    extern __shared__ char smem[];
    const uint32_t sb = (uint32_t)__cvta_generic_to_shared(smem);
    float* qsc = (float*)(smem + QSC_OFF);
    const int tid = threadIdx.x, lane = tid & 31, warp = tid >> 5;
    const int qt = (int)gridDim.x - 1 - (int)blockIdx.x;
    const int h = blockIdx.y, b = blockIdx.z;
    const int q0 = qt * AQ;

    // log2(e) folded in: logits land directly in log2 domain
    if (tid < 64)
        qsc[tid] = 1.44269504f * logf(2048.0f) * qm[tid] * rsqrtf(64.0f);

    const __half* kvsrc[6];
    uint32_t kvdst[6];
#pragma unroll
    for (int it = 0; it < 6; it++) {
        int c = tid + it * 256;
        int p = c >> 9, r = (c >> 3) & 63, ch = c & 7;
        const __half* bp = (p == 1) ? qkvl : qkvh;
        int col = ((p == 2) ? 2 * C_DIM : C_DIM) + h * DH + ch * 8;
        kvsrc[it] = bp + (size_t)(b * T_SEQ + r) * C3 + col;
        kvdst[it] = (uint32_t)(p * 8192 + r * 128 + ((ch ^ (r & 7)) << 4));
    }
#pragma unroll
    for (int it = 0; it < 6; it++) cpa16(sb + ST_OFF + kvdst[it], kvsrc[it]);
    cpa_commit();

    __syncthreads();

    // Q load: combine hi+lo, scale (log2 domain), round once to fp16
#pragma unroll
    for (int it = 0; it < 4; it++) {
        int u = tid + it * 256;
        int r = u >> 3, ch = u & 7;
        size_t src = (size_t)(b * T_SEQ + q0 + r) * C3 + h * DH + ch * 8;
        uint4 hv = *(const uint4*)(qkvh + src);
        uint4 lv = *(const uint4*)(qkvl + src);
        const __half2* hp = (const __half2*)&hv;
        const __half2* lp = (const __half2*)&lv;
        uint32_t oh[4];
#pragma unroll
        for (int k = 0; k < 4; k++) {
            float2 hf = __half22float2(hp[k]);
            float2 lf = __half22float2(lp[k]);
            oh[k] = pkh((hf.x + lf.x) * qsc[ch * 8 + 2 * k],
                        (hf.y + lf.y) * qsc[ch * 8 + 2 * k + 1]);
        }
        uint32_t off = (uint32_t)(r * 128 + ((ch ^ (r & 7)) << 4));
        *(uint4*)(smem + QS_OFF + off) = make_uint4(oh[0], oh[1], oh[2], oh[3]);
    }

    float m0 = -1e30f, m1 = -1e30f, l0 = 0.0f, l1 = 0.0f;
    float acc[8][4] = {};

    const int maxc = (q0 + AQ > MEMLEN) ? (q0 + AQ) : MEMLEN;
    const int nT = maxc / AKV;

    for (int t = 0; t < nT; t++) {
        cpa_wait<0>();
        __syncthreads();
        if (t + 1 < nT) {
            uint32_t stb = sb + ST_OFF + ((t + 1) & 1) * AST;
            size_t delta = (size_t)(t + 1) * AKV * C3;
#pragma unroll
            for (int it = 0; it < 6; it++) cpa16(stb + kvdst[it], kvsrc[it] + delta);
            cpa_commit();
        }
        const uint32_t st = sb + ST_OFF + (t & 1) * AST;

        // ---- S = Q K^T (2-mma: Q single, K hi/lo) ----
        float s_[8][4] = {};
#pragma unroll
        for (int kk = 0; kk < 4; kk++) {
            uint32_t aH[4];
            {
                int row = 16 * warp + (lane & 15);
                int ch = kk * 2 + (lane >> 4);
                uint32_t off = (uint32_t)(row * 128 + ((ch ^ (row & 7)) << 4));
                ldm4(aH, sb + QS_OFF + off);
            }
#pragma unroll
            for (int jj = 0; jj < 4; jj++) {
                int row = 16 * jj + 8 * (lane >> 4) + (lane & 7);
                int ch = kk * 2 + ((lane >> 3) & 1);
                uint32_t off = (uint32_t)(row * 128 + ((ch ^ (row & 7)) << 4));
                uint32_t bH[4], bL[4];
                ldm4(bH, st + off);
                ldm4(bL, st + 8192 + off);
#pragma unroll
                for (int u = 0; u < 2; u++) {
                    float* d = s_[2 * jj + u];
                    mma16(d, aH, bH[2 * u], bH[2 * u + 1]);
                    mma16(d, aH, bL[2 * u], bL[2 * u + 1]);
                }
            }
        }

        const int kj0 = t * AKV;
        if (kj0 >= MEMLEN) {
            int r0g = q0 + 16 * warp + (lane >> 2);
            int cb = kj0 + 2 * (lane & 3);
#pragma unroll
            for (int j = 0; j < 8; j++) {
                int cg = cb + 8 * j;
                if (cg > r0g)         s_[j][0] = -1e30f;
                if (cg + 1 > r0g)     s_[j][1] = -1e30f;
                if (cg > r0g + 8)     s_[j][2] = -1e30f;
                if (cg + 1 > r0g + 8) s_[j][3] = -1e30f;
            }
        }

        // ---- online softmax (log2 domain) ----
        float mx0 = -1e30f, mx1 = -1e30f;
#pragma unroll
        for (int j = 0; j < 8; j++) {
            mx0 = fmaxf(mx0, fmaxf(s_[j][0], s_[j][1]));
            mx1 = fmaxf(mx1, fmaxf(s_[j][2], s_[j][3]));
        }
        mx0 = fmaxf(mx0, __shfl_xor_sync(0xffffffffu, mx0, 1));
        mx0 = fmaxf(mx0, __shfl_xor_sync(0xffffffffu, mx0, 2));
        mx1 = fmaxf(mx1, __shfl_xor_sync(0xffffffffu, mx1, 1));
        mx1 = fmaxf(mx1, __shfl_xor_sync(0xffffffffu, mx1, 2));
        float mn0 = fmaxf(m0, mx0), mn1 = fmaxf(m1, mx1);
        float f0 = ex2f(m0 - mn0), f1 = ex2f(m1 - mn1);
        float sum0 = 0.0f, sum1 = 0.0f;
        uint32_t phA[8], phB[8];
#pragma unroll
        for (int j = 0; j < 8; j++) {
            float p0 = ex2f(s_[j][0] - mn0);
            float p1 = ex2f(s_[j][1] - mn0);
            float p2 = ex2f(s_[j][2] - mn1);
            float p3 = ex2f(s_[j][3] - mn1);
            sum0 += p0 + p1; sum1 += p2 + p3;
            phA[j] = pkh(p0, p1);
            phB[j] = pkh(p2, p3);
        }
        sum0 += __shfl_xor_sync(0xffffffffu, sum0, 1);
        sum0 += __shfl_xor_sync(0xffffffffu, sum0, 2);
        sum1 += __shfl_xor_sync(0xffffffffu, sum1, 1);
        sum1 += __shfl_xor_sync(0xffffffffu, sum1, 2);
        l0 = l0 * f0 + sum0; l1 = l1 * f1 + sum1;
        m0 = mn0; m1 = mn1;
#pragma unroll
        for (int j = 0; j < 8; j++) {
            acc[j][0] *= f0; acc[j][1] *= f0;
            acc[j][2] *= f1; acc[j][3] *= f1;
        }

        // ---- P @ V (1-mma) ----
#pragma unroll
        for (int jj = 0; jj < 4; jj++) {
            uint32_t pa[4] = {phA[2*jj], phB[2*jj], phA[2*jj+1], phB[2*jj+1]};
#pragma unroll
            for (int nn = 0; nn < 4; nn++) {
                int row = 16 * jj + 8 * ((lane >> 3) & 1) + (lane & 7);
                int ch = 2 * nn + (lane >> 4);
                uint32_t off = (uint32_t)(row * 128 + ((ch ^ (row & 7)) << 4));
                uint32_t vH[4];
                ldm4t(vH, st + 16384 + off);
#pragma unroll
                for (int u = 0; u < 2; u++)
                    mma16(acc[2 * nn + u], pa, vH[2 * u], vH[2 * u + 1]);
            }
        }
    }

    // ---- epilogue ----
    {
        float i0 = 1.0f / l0, i1 = 1.0f / l1;
        size_t r0 = (size_t)(b * T_SEQ + q0 + 16 * warp + (lane >> 2));
        int cb = h * DH + 2 * (lane & 3);
#pragma unroll
        for (int j = 0; j < 8; j++) {
            int cc = cb + 8 * j;
            *(uint32_t*)(yh + r0 * C_DIM + cc)       = pkh(acc[j][0] * i0, acc[j][1] * i0);
            *(uint32_t*)(yh + (r0 + 8) * C_DIM + cc) = pkh(acc[j][2] * i1, acc[j][3] * i1);
        }
    }
}

// ---------------------------------------------------------------------------
// Launch
// ---------------------------------------------------------------------------
extern "C" void kernel_launch(void* const* d_in, const int* in_sizes, int n_in,
                              void* d_out, int out_size)
{
    const float* x      = (const float*)d_in[0];
    const float* w_qkv  = (const float*)d_in[1];
    const float* w_proj = (const float*)d_in[2];
    const float* qm     = (const float*)d_in[3];
    float* out = (float*)d_out;

    static __half *p_xh = nullptr, *p_xl, *p_wqh, *p_wql, *p_wph, *p_wpl;
    static __half *p_qkvh, *p_qkvl, *p_yh;
    if (!p_xh) {
        cudaGetSymbolAddress((void**)&p_xh, g_xh);
        cudaGetSymbolAddress((void**)&p_xl, g_xl);
        cudaGetSymbolAddress((void**)&p_wqh, g_wqh);
        cudaGetSymbolAddress((void**)&p_wql, g_wql);
        cudaGetSymbolAddress((void**)&p_wph, g_wph);
        cudaGetSymbolAddress((void**)&p_wpl, g_wpl);
        cudaGetSymbolAddress((void**)&p_qkvh, g_qkvh);
        cudaGetSymbolAddress((void**)&p_qkvl, g_qkvl);
        cudaGetSymbolAddress((void**)&p_yh, g_yh);
        cudaFuncSetAttribute(gemm_fp16_kernel,
                             cudaFuncAttributeMaxDynamicSharedMemorySize, GEMM_SMEM);
        cudaFuncSetAttribute(attn_mma2,
                             cudaFuncAttributeMaxDynamicSharedMemorySize, ATTN2_SMEM);
    }

    // Single merged split launch for x, w_qkv, w_proj
    split_all_kernel<<<(N8_ALL + 255) / 256, 256>>>(
        x, w_qkv, w_proj, p_xh, p_xl, p_wqh, p_wql, p_wph, p_wpl);

    // GEMM1: qkv = x @ w_qkv^T. Q,K cols: 3-mma hi/lo out. V cols: 2-mma.
    {
        dim3 grid(C3 / 128, M_TOT / 128);
        gemm_fp16_kernel<<<grid, 256, GEMM_SMEM>>>(p_xh, p_xl, p_wqh, p_wql,
                                                   nullptr, p_qkvh, p_qkvl, C3,
                                                   2 * C_DIM, 1);
    }

    // Fused attention -> y single fp16 plane
    {
        dim3 grid(T_SEQ / AQ, NH, B_SZ);
        attn_mma2<<<grid, 256, ATTN2_SMEM>>>(qm, p_qkvh, p_qkvl, p_yh);
    }

    // GEMM2: out = y @ w_proj^T -> fp32. 1-mma.
    {
        dim3 grid(C_DIM / 128, M_TOT / 128);
        gemm_fp16_kernel<<<grid, 256, GEMM_SMEM>>>(p_yh, p_yh, p_wph, p_wpl,
                                                   out, nullptr, nullptr, C_DIM,
                                                   0, 0);
    }
}

// round 15
// speedup vs baseline: 1.3650x; 1.0994x over previous
#include <cuda_runtime.h>
#include <cuda_fp16.h>
#include <math.h>
#include <stdint.h>

// Problem constants
#define B_SZ   2
#define T_SEQ  2048
#define C_DIM  1024
#define C3     3072
#define NH     16
#define DH     64
#define MEMLEN 1024
#define M_TOT  4096
#define KD     1024

// Scratch fp16 hi/lo planes (no cudaMalloc allowed)
__device__ __half g_xh[(size_t)M_TOT * KD];
__device__ __half g_xl[(size_t)M_TOT * KD];
__device__ __half g_wqh[(size_t)C3 * KD];
__device__ __half g_wql[(size_t)C3 * KD];
__device__ __half g_wph[(size_t)C_DIM * KD];
__device__ __half g_wpl[(size_t)C_DIM * KD];
__device__ __half g_qkvh[(size_t)M_TOT * C3];
__device__ __half g_qkvl[(size_t)M_TOT * C3];
__device__ __half g_yh[(size_t)M_TOT * KD];

// ---------------------------------------------------------------------------
// helpers
// ---------------------------------------------------------------------------
__device__ __forceinline__ uint32_t pk2(__half a, __half b) {
    __half2 t = __halves2half2(a, b);
    return *reinterpret_cast<uint32_t*>(&t);
}

__device__ __forceinline__ uint32_t pkh(float a, float b) {
    __half2 t = __floats2half2_rn(a, b);
    return *reinterpret_cast<uint32_t*>(&t);
}

__device__ __forceinline__ uint32_t pkf(float a, float b, uint32_t* lo) {
    __half ha = __float2half_rn(a), hb = __float2half_rn(b);
    __half la = __float2half_rn(a - __half2float(ha));
    __half lb = __float2half_rn(b - __half2float(hb));
    *lo = pk2(la, lb);
    return pk2(ha, hb);
}

// raw ex2.approx (logits kept in log2 domain)
__device__ __forceinline__ float ex2f(float x) {
    float r;
    asm("ex2.approx.f32 %0, %1;" : "=f"(r) : "f"(x));
    return r;
}

__device__ __forceinline__ void ldm4(uint32_t r[4], uint32_t a) {
    asm volatile("ldmatrix.sync.aligned.m8n8.x4.shared.b16 {%0,%1,%2,%3},[%4];\n"
                 : "=r"(r[0]), "=r"(r[1]), "=r"(r[2]), "=r"(r[3]) : "r"(a));
}
__device__ __forceinline__ void ldm4t(uint32_t r[4], uint32_t a) {
    asm volatile("ldmatrix.sync.aligned.m8n8.x4.trans.shared.b16 {%0,%1,%2,%3},[%4];\n"
                 : "=r"(r[0]), "=r"(r[1]), "=r"(r[2]), "=r"(r[3]) : "r"(a));
}

__device__ __forceinline__ void mma16(float d[4], const uint32_t a[4],
                                      uint32_t b0, uint32_t b1) {
    asm volatile(
        "mma.sync.aligned.m16n8k16.row.col.f32.f16.f16.f32 "
        "{%0,%1,%2,%3},{%4,%5,%6,%7},{%8,%9},{%0,%1,%2,%3};\n"
        : "+f"(d[0]), "+f"(d[1]), "+f"(d[2]), "+f"(d[3])
        : "r"(a[0]), "r"(a[1]), "r"(a[2]), "r"(a[3]), "r"(b0), "r"(b1));
}

__device__ __forceinline__ void cpa16(uint32_t d, const void* g) {
    asm volatile("cp.async.cg.shared.global [%0], [%1], 16;" :: "r"(d), "l"(g) : "memory");
}
__device__ __forceinline__ void cpa_commit() {
    asm volatile("cp.async.commit_group;" ::: "memory");
}
template <int N>
__device__ __forceinline__ void cpa_wait() {
    asm volatile("cp.async.wait_group %0;" :: "n"(N) : "memory");
}

// ---------------------------------------------------------------------------
// Merged split: fp32 -> fp16 hi/lo for x, w_qkv, w_proj in ONE launch.
// ---------------------------------------------------------------------------
#define N8_X   (M_TOT * KD / 8)
#define N8_WQ  (C3 * KD / 8)
#define N8_WP  (C_DIM * KD / 8)
#define N8_ALL (N8_X + N8_WQ + N8_WP)

__global__ __launch_bounds__(256)
void split_all_kernel(const float* __restrict__ x,
                      const float* __restrict__ wq,
                      const float* __restrict__ wp,
                      __half* __restrict__ xh, __half* __restrict__ xl,
                      __half* __restrict__ wqh, __half* __restrict__ wql,
                      __half* __restrict__ wph, __half* __restrict__ wpl)
{
    int i = blockIdx.x * 256 + threadIdx.x;
    if (i >= N8_ALL) return;
    const float* src;
    __half *hi, *lo;
    int j = i;
    if (j < N8_X) { src = x; hi = xh; lo = xl; }
    else if ((j -= N8_X) < N8_WQ) { src = wq; hi = wqh; lo = wql; }
    else { j -= N8_WQ; src = wp; hi = wph; lo = wpl; }

    float4 v0 = ((const float4*)src)[2 * j];
    float4 v1 = ((const float4*)src)[2 * j + 1];
    float v[8] = {v0.x, v0.y, v0.z, v0.w, v1.x, v1.y, v1.z, v1.w};
    uint32_t hp[4], lp[4];
#pragma unroll
    for (int k = 0; k < 4; k++)
        hp[k] = pkf(v[2 * k], v[2 * k + 1], &lp[k]);
    ((uint4*)hi)[j] = make_uint4(hp[0], hp[1], hp[2], hp[3]);
    ((uint4*)lo)[j] = make_uint4(lp[0], lp[1], lp[2], lp[3]);
}

// ---------------------------------------------------------------------------
// GEMM1: fp16 split NT GEMM (unchanged from R12-R14).
// ---------------------------------------------------------------------------
#define PLANE        8192
#define STAGE_BYTES  32768
#define NSTAGE       3
#define GEMM_SMEM    (NSTAGE * STAGE_BYTES)
#define NCH          32

__global__ __launch_bounds__(256, 2)
void gemm_fp16_kernel(const __half* __restrict__ Ah,
                      const __half* __restrict__ Al,
                      const __half* __restrict__ Bh,
                      const __half* __restrict__ Bl,
                      __half* __restrict__ Ch,
                      __half* __restrict__ Cl, int N, int fullN, int useBl)
{
    extern __shared__ char smem[];
    const uint32_t sbase = (uint32_t)__cvta_generic_to_shared(smem);
    const int tid = threadIdx.x, lane = tid & 31, warp = tid >> 5;
    const int m0 = blockIdx.y * 128, n0 = blockIdx.x * 128;
    const bool full = (n0 < fullN);
    const int mw = warp >> 1, nw = warp & 1;

    bool ld[8];
#pragma unroll
    for (int it = 0; it < 8; it++) {
        int p = it >> 1;
        ld[it] = (p == 0) || (p == 2) || (p == 1 && full) ||
                 (p == 3 && (full || useBl));
    }

    const __half* gsrc[8];
    uint32_t sdst[8];
#pragma unroll
    for (int it = 0; it < 8; it++) {
        int c = tid + it * 256;
        int p = c >> 9;
        int r = (c >> 2) & 127;
        int kc = c & 3;
        const __half* bp = (p == 0) ? Ah : (p == 1) ? Al : (p == 2) ? Bh : Bl;
        int row = ((p < 2) ? m0 : n0) + r;
        gsrc[it] = bp + (size_t)row * KD + kc * 8;
        sdst[it] = (uint32_t)(p * PLANE + r * 64 + ((kc ^ ((r >> 1) & 3)) << 4));
    }

    const int ra = lane & 15;
    const int ksel_a = lane >> 4;
    int rowA[2], swzA[2];
#pragma unroll
    for (int f = 0; f < 2; f++) {
        rowA[f] = mw * 32 + f * 16 + ra;
        swzA[f] = (rowA[f] >> 1) & 3;
    }
    const int rb = (lane & 7) + 8 * (lane >> 4);
    const int ksel_b = (lane >> 3) & 1;
    int rowB[4], swzB[4];
#pragma unroll
    for (int g = 0; g < 4; g++) {
        rowB[g] = nw * 64 + g * 16 + rb;
        swzB[g] = (rowB[g] >> 1) & 3;
    }

    float acc[2][8][4] = {};

#pragma unroll
    for (int pt = 0; pt < 2; pt++) {
        uint32_t sb = sbase + pt * STAGE_BYTES;
#pragma unroll
        for (int it = 0; it < 8; it++)
            if (ld[it]) cpa16(sb + sdst[it], gsrc[it] + pt * 32);
        cpa_commit();
    }

    for (int t = 0; t < NCH; t++) {
        cpa_wait<1>();
        __syncthreads();

        if (t + 2 < NCH) {
            uint32_t sb = sbase + ((t + 2) % NSTAGE) * STAGE_BYTES;
#pragma unroll
            for (int it = 0; it < 8; it++)
                if (ld[it]) cpa16(sb + sdst[it], gsrc[it] + (t + 2) * 32);
        }
        cpa_commit();

        const uint32_t sb = sbase + (t % NSTAGE) * STAGE_BYTES;
#pragma unroll
        for (int s16 = 0; s16 < 2; s16++) {
            uint32_t ah[2][4], al[2][4];
#pragma unroll
            for (int f = 0; f < 2; f++) {
                uint32_t off = (uint32_t)(rowA[f] * 64 +
                               (((2 * s16 + ksel_a) ^ swzA[f]) << 4));
                ldm4(ah[f], sb + off);
                if (full) ldm4(al[f], sb + PLANE + off);
            }
#pragma unroll
            for (int g = 0; g < 4; g++) {
                uint32_t offb = (uint32_t)(rowB[g] * 64 +
                                (((2 * s16 + ksel_b) ^ swzB[g]) << 4));
                uint32_t bh[4], bl[4];
                ldm4(bh, sb + 2 * PLANE + offb);
                if (full || useBl) ldm4(bl, sb + 3 * PLANE + offb);
#pragma unroll
                for (int f = 0; f < 2; f++) {
#pragma unroll
                    for (int j = 0; j < 2; j++) {
                        float* d = acc[f][g * 2 + j];
                        mma16(d, ah[f], bh[2 * j], bh[2 * j + 1]);
                        if (full || useBl) mma16(d, ah[f], bl[2 * j], bl[2 * j + 1]);
                        if (full) mma16(d, al[f], bh[2 * j], bh[2 * j + 1]);
                    }
                }
            }
        }
    }

    const int er = lane >> 2, ec = (lane & 3) * 2;
#pragma unroll
    for (int f = 0; f < 2; f++) {
        int r = m0 + mw * 32 + f * 16 + er;
#pragma unroll
        for (int j8 = 0; j8 < 8; j8++) {
            int cc = n0 + nw * 64 + j8 * 8 + ec;
            if (full) {
                uint32_t lo0, lo1;
                uint32_t hi0 = pkf(acc[f][j8][0], acc[f][j8][1], &lo0);
                uint32_t hi1 = pkf(acc[f][j8][2], acc[f][j8][3], &lo1);
                *(uint32_t*)(Ch + (size_t)r * N + cc) = hi0;
                *(uint32_t*)(Cl + (size_t)r * N + cc) = lo0;
                *(uint32_t*)(Ch + (size_t)(r + 8) * N + cc) = hi1;
                *(uint32_t*)(Cl + (size_t)(r + 8) * N + cc) = lo1;
            } else {
                *(uint32_t*)(Ch + (size_t)r * N + cc) =
                    pkh(acc[f][j8][0], acc[f][j8][1]);
                *(uint32_t*)(Ch + (size_t)(r + 8) * N + cc) =
                    pkh(acc[f][j8][2], acc[f][j8][3]);
            }
        }
    }
}

// ---------------------------------------------------------------------------
// GEMM2: dedicated lean 1-mma kernel. 2 planes (Ah@0, Bh@8K), 16KB stages,
// 5-stage cp.async ring (80KB smem, 2 CTAs/SM), fp32 output.
// ---------------------------------------------------------------------------
#define G2_STAGE  16384
#define G2_NSTAGE 5
#define G2_SMEM   (G2_NSTAGE * G2_STAGE)

__global__ __launch_bounds__(256, 2)
void gemm2_kernel(const __half* __restrict__ Ah,
                  const __half* __restrict__ Bh,
                  float* __restrict__ C, int N)
{
    extern __shared__ char smem[];
    const uint32_t sbase = (uint32_t)__cvta_generic_to_shared(smem);
    const int tid = threadIdx.x, lane = tid & 31, warp = tid >> 5;
    const int m0 = blockIdx.y * 128, n0 = blockIdx.x * 128;
    const int mw = warp >> 1, nw = warp & 1;

    // loader: 4 x 16B per thread per stage (2 planes x 512 chunks)
    const __half* gsrc[4];
    uint32_t sdst[4];
#pragma unroll
    for (int it = 0; it < 4; it++) {
        int c = tid + it * 256;          // 0..1023
        int p = c >> 9;                  // 0: A, 1: B
        int r = (c >> 2) & 127;
        int kc = c & 3;
        const __half* bp = p ? Bh : Ah;
        int row = (p ? n0 : m0) + r;
        gsrc[it] = bp + (size_t)row * KD + kc * 8;
        sdst[it] = (uint32_t)(p * PLANE + r * 64 + ((kc ^ ((r >> 1) & 3)) << 4));
    }

    const int ra = lane & 15;
    const int ksel_a = lane >> 4;
    int rowA[2], swzA[2];
#pragma unroll
    for (int f = 0; f < 2; f++) {
        rowA[f] = mw * 32 + f * 16 + ra;
        swzA[f] = (rowA[f] >> 1) & 3;
    }
    const int rb = (lane & 7) + 8 * (lane >> 4);
    const int ksel_b = (lane >> 3) & 1;
    int rowB[4], swzB[4];
#pragma unroll
    for (int g = 0; g < 4; g++) {
        rowB[g] = nw * 64 + g * 16 + rb;
        swzB[g] = (rowB[g] >> 1) & 3;
    }

    float acc[2][8][4] = {};

    // prologue: 4 stages in flight
#pragma unroll
    for (int pt = 0; pt < 4; pt++) {
        uint32_t sb = sbase + pt * G2_STAGE;
#pragma unroll
        for (int it = 0; it < 4; it++) cpa16(sb + sdst[it], gsrc[it] + pt * 32);
        cpa_commit();
    }

    for (int t = 0; t < NCH; t++) {
        cpa_wait<3>();
        __syncthreads();

        if (t + 4 < NCH) {
            uint32_t sb = sbase + ((t + 4) % G2_NSTAGE) * G2_STAGE;
#pragma unroll
            for (int it = 0; it < 4; it++)
                cpa16(sb + sdst[it], gsrc[it] + (t + 4) * 32);
        }
        cpa_commit();

        const uint32_t sb = sbase + (t % G2_NSTAGE) * G2_STAGE;
#pragma unroll
        for (int s16 = 0; s16 < 2; s16++) {
            uint32_t ah[2][4];
#pragma unroll
            for (int f = 0; f < 2; f++) {
                uint32_t off = (uint32_t)(rowA[f] * 64 +
                               (((2 * s16 + ksel_a) ^ swzA[f]) << 4));
                ldm4(ah[f], sb + off);
            }
#pragma unroll
            for (int g = 0; g < 4; g++) {
                uint32_t offb = (uint32_t)(rowB[g] * 64 +
                                (((2 * s16 + ksel_b) ^ swzB[g]) << 4));
                uint32_t bh[4];
                ldm4(bh, sb + PLANE + offb);
#pragma unroll
                for (int f = 0; f < 2; f++) {
#pragma unroll
                    for (int j = 0; j < 2; j++)
                        mma16(acc[f][g * 2 + j], ah[f], bh[2 * j], bh[2 * j + 1]);
                }
            }
        }
    }

    const int er = lane >> 2, ec = (lane & 3) * 2;
#pragma unroll
    for (int f = 0; f < 2; f++) {
        int r = m0 + mw * 32 + f * 16 + er;
#pragma unroll
        for (int j8 = 0; j8 < 8; j8++) {
            int cc = n0 + nw * 64 + j8 * 8 + ec;
            *(float2*)(C + (size_t)r * N + cc) =
                make_float2(acc[f][j8][0], acc[f][j8][1]);
            *(float2*)(C + (size_t)(r + 8) * N + cc) =
                make_float2(acc[f][j8][2], acc[f][j8][3]);
        }
    }
}

// ---------------------------------------------------------------------------
// fp16 mma flash attention: S 2-mma, PV 1-mma, log2-domain softmax.
// 3-stage KV ring (Kh,Kl,Vh 24KB/stage); smem ~90KB -> 2 CTAs/SM.
// ---------------------------------------------------------------------------
#define AQ 128
#define AKV 64
#define QS_OFF   0
#define ST_OFF   16384
#define AST      24576
#define ANST     3
#define QSC_OFF  (ST_OFF + ANST * AST)
#define ATTN2_SMEM (QSC_OFF + 256)

__global__ __launch_bounds__(256, 2)
void attn_mma2(const float* __restrict__ qm,
               const __half* __restrict__ qkvh,
               const __half* __restrict__ qkvl,
               __half* __restrict__ yh)
{
    extern __shared__ char smem[];
    const uint32_t sb = (uint32_t)__cvta_generic_to_shared(smem);
    float* qsc = (float*)(smem + QSC_OFF);
    const int tid = threadIdx.x, lane = tid & 31, warp = tid >> 5;
    const int qt = (int)gridDim.x - 1 - (int)blockIdx.x;
    const int h = blockIdx.y, b = blockIdx.z;
    const int q0 = qt * AQ;

    if (tid < 64)
        qsc[tid] = 1.44269504f * logf(2048.0f) * qm[tid] * rsqrtf(64.0f);

    const __half* kvsrc[6];
    uint32_t kvdst[6];
#pragma unroll
    for (int it = 0; it < 6; it++) {
        int c = tid + it * 256;
        int p = c >> 9, r = (c >> 3) & 63, ch = c & 7;
        const __half* bp = (p == 1) ? qkvl : qkvh;
        int col = ((p == 2) ? 2 * C_DIM : C_DIM) + h * DH + ch * 8;
        kvsrc[it] = bp + (size_t)(b * T_SEQ + r) * C3 + col;
        kvdst[it] = (uint32_t)(p * 8192 + r * 128 + ((ch ^ (r & 7)) << 4));
    }
    // prologue: stages 0 and 1 (nT >= 16 always)
#pragma unroll
    for (int pt = 0; pt < 2; pt++) {
        uint32_t stb = sb + ST_OFF + pt * AST;
        size_t delta = (size_t)pt * AKV * C3;
#pragma unroll
        for (int it = 0; it < 6; it++) cpa16(stb + kvdst[it], kvsrc[it] + delta);
        cpa_commit();
    }

    __syncthreads();  // qsc visible

    // Q load: combine hi+lo, scale (log2 domain), round once to fp16
#pragma unroll
    for (int it = 0; it < 4; it++) {
        int u = tid + it * 256;
        int r = u >> 3, ch = u & 7;
        size_t src = (size_t)(b * T_SEQ + q0 + r) * C3 + h * DH + ch * 8;
        uint4 hv = *(const uint4*)(qkvh + src);
        uint4 lv = *(const uint4*)(qkvl + src);
        const __half2* hp = (const __half2*)&hv;
        const __half2* lp = (const __half2*)&lv;
        uint32_t oh[4];
#pragma unroll
        for (int k = 0; k < 4; k++) {
            float2 hf = __half22float2(hp[k]);
            float2 lf = __half22float2(lp[k]);
            oh[k] = pkh((hf.x + lf.x) * qsc[ch * 8 + 2 * k],
                        (hf.y + lf.y) * qsc[ch * 8 + 2 * k + 1]);
        }
        uint32_t off = (uint32_t)(r * 128 + ((ch ^ (r & 7)) << 4));
        *(uint4*)(smem + QS_OFF + off) = make_uint4(oh[0], oh[1], oh[2], oh[3]);
    }

    float m0 = -1e30f, m1 = -1e30f, l0 = 0.0f, l1 = 0.0f;
    float acc[8][4] = {};

    const int maxc = (q0 + AQ > MEMLEN) ? (q0 + AQ) : MEMLEN;
    const int nT = maxc / AKV;

    for (int t = 0; t < nT; t++) {
        cpa_wait<1>();
        __syncthreads();
        if (t + 2 < nT) {
            uint32_t stb = sb + ST_OFF + ((t + 2) % ANST) * AST;
            size_t delta = (size_t)(t + 2) * AKV * C3;
#pragma unroll
            for (int it = 0; it < 6; it++) cpa16(stb + kvdst[it], kvsrc[it] + delta);
        }
        cpa_commit();
        const uint32_t st = sb + ST_OFF + (t % ANST) * AST;

        // ---- S = Q K^T (2-mma: Q single, K hi/lo) ----
        float s_[8][4] = {};
#pragma unroll
        for (int kk = 0; kk < 4; kk++) {
            uint32_t aH[4];
            {
                int row = 16 * warp + (lane & 15);
                int ch = kk * 2 + (lane >> 4);
                uint32_t off = (uint32_t)(row * 128 + ((ch ^ (row & 7)) << 4));
                ldm4(aH, sb + QS_OFF + off);
            }
#pragma unroll
            for (int jj = 0; jj < 4; jj++) {
                int row = 16 * jj + 8 * (lane >> 4) + (lane & 7);
                int ch = kk * 2 + ((lane >> 3) & 1);
                uint32_t off = (uint32_t)(row * 128 + ((ch ^ (row & 7)) << 4));
                uint32_t bH[4], bL[4];
                ldm4(bH, st + off);
                ldm4(bL, st + 8192 + off);
#pragma unroll
                for (int u = 0; u < 2; u++) {
                    float* d = s_[2 * jj + u];
                    mma16(d, aH, bH[2 * u], bH[2 * u + 1]);
                    mma16(d, aH, bL[2 * u], bL[2 * u + 1]);
                }
            }
        }

        const int kj0 = t * AKV;
        if (kj0 >= MEMLEN) {
            int r0g = q0 + 16 * warp + (lane >> 2);
            int cb = kj0 + 2 * (lane & 3);
#pragma unroll
            for (int j = 0; j < 8; j++) {
                int cg = cb + 8 * j;
                if (cg > r0g)         s_[j][0] = -1e30f;
                if (cg + 1 > r0g)     s_[j][1] = -1e30f;
                if (cg > r0g + 8)     s_[j][2] = -1e30f;
                if (cg + 1 > r0g + 8) s_[j][3] = -1e30f;
            }
        }

        // ---- online softmax (log2 domain) ----
        float mx0 = -1e30f, mx1 = -1e30f;
#pragma unroll
        for (int j = 0; j < 8; j++) {
            mx0 = fmaxf(mx0, fmaxf(s_[j][0], s_[j][1]));
            mx1 = fmaxf(mx1, fmaxf(s_[j][2], s_[j][3]));
        }
        mx0 = fmaxf(mx0, __shfl_xor_sync(0xffffffffu, mx0, 1));
        mx0 = fmaxf(mx0, __shfl_xor_sync(0xffffffffu, mx0, 2));
        mx1 = fmaxf(mx1, __shfl_xor_sync(0xffffffffu, mx1, 1));
        mx1 = fmaxf(mx1, __shfl_xor_sync(0xffffffffu, mx1, 2));
        float mn0 = fmaxf(m0, mx0), mn1 = fmaxf(m1, mx1);
        float f0 = ex2f(m0 - mn0), f1 = ex2f(m1 - mn1);
        float sum0 = 0.0f, sum1 = 0.0f;
        uint32_t phA[8], phB[8];
#pragma unroll
        for (int j = 0; j < 8; j++) {
            float p0 = ex2f(s_[j][0] - mn0);
            float p1 = ex2f(s_[j][1] - mn0);
            float p2 = ex2f(s_[j][2] - mn1);
            float p3 = ex2f(s_[j][3] - mn1);
            sum0 += p0 + p1; sum1 += p2 + p3;
            phA[j] = pkh(p0, p1);
            phB[j] = pkh(p2, p3);
        }
        sum0 += __shfl_xor_sync(0xffffffffu, sum0, 1);
        sum0 += __shfl_xor_sync(0xffffffffu, sum0, 2);
        sum1 += __shfl_xor_sync(0xffffffffu, sum1, 1);
        sum1 += __shfl_xor_sync(0xffffffffu, sum1, 2);
        l0 = l0 * f0 + sum0; l1 = l1 * f1 + sum1;
        m0 = mn0; m1 = mn1;
#pragma unroll
        for (int j = 0; j < 8; j++) {
            acc[j][0] *= f0; acc[j][1] *= f0;
            acc[j][2] *= f1; acc[j][3] *= f1;
        }

        // ---- P @ V (1-mma) ----
#pragma unroll
        for (int jj = 0; jj < 4; jj++) {
            uint32_t pa[4] = {phA[2*jj], phB[2*jj], phA[2*jj+1], phB[2*jj+1]};
#pragma unroll
            for (int nn = 0; nn < 4; nn++) {
                int row = 16 * jj + 8 * ((lane >> 3) & 1) + (lane & 7);
                int ch = 2 * nn + (lane >> 4);
                uint32_t off = (uint32_t)(row * 128 + ((ch ^ (row & 7)) << 4));
                uint32_t vH[4];
                ldm4t(vH, st + 16384 + off);
#pragma unroll
                for (int u = 0; u < 2; u++)
                    mma16(acc[2 * nn + u], pa, vH[2 * u], vH[2 * u + 1]);
            }
        }
    }

    // ---- epilogue ----
    {
        float i0 = 1.0f / l0, i1 = 1.0f / l1;
        size_t r0 = (size_t)(b * T_SEQ + q0 + 16 * warp + (lane >> 2));
        int cb = h * DH + 2 * (lane & 3);
#pragma unroll
        for (int j = 0; j < 8; j++) {
            int cc = cb + 8 * j;
            *(uint32_t*)(yh + r0 * C_DIM + cc)       = pkh(acc[j][0] * i0, acc[j][1] * i0);
            *(uint32_t*)(yh + (r0 + 8) * C_DIM + cc) = pkh(acc[j][2] * i1, acc[j][3] * i1);
        }
    }
}

// ---------------------------------------------------------------------------
// Launch
// ---------------------------------------------------------------------------
extern "C" void kernel_launch(void* const* d_in, const int* in_sizes, int n_in,
                              void* d_out, int out_size)
{
    const float* x      = (const float*)d_in[0];
    const float* w_qkv  = (const float*)d_in[1];
    const float* w_proj = (const float*)d_in[2];
    const float* qm     = (const float*)d_in[3];
    float* out = (float*)d_out;

    static __half *p_xh = nullptr, *p_xl, *p_wqh, *p_wql, *p_wph, *p_wpl;
    static __half *p_qkvh, *p_qkvl, *p_yh;
    if (!p_xh) {
        cudaGetSymbolAddress((void**)&p_xh, g_xh);
        cudaGetSymbolAddress((void**)&p_xl, g_xl);
        cudaGetSymbolAddress((void**)&p_wqh, g_wqh);
        cudaGetSymbolAddress((void**)&p_wql, g_wql);
        cudaGetSymbolAddress((void**)&p_wph, g_wph);
        cudaGetSymbolAddress((void**)&p_wpl, g_wpl);
        cudaGetSymbolAddress((void**)&p_qkvh, g_qkvh);
        cudaGetSymbolAddress((void**)&p_qkvl, g_qkvl);
        cudaGetSymbolAddress((void**)&p_yh, g_yh);
        cudaFuncSetAttribute(gemm_fp16_kernel,
                             cudaFuncAttributeMaxDynamicSharedMemorySize, GEMM_SMEM);
        cudaFuncSetAttribute(gemm2_kernel,
                             cudaFuncAttributeMaxDynamicSharedMemorySize, G2_SMEM);
        cudaFuncSetAttribute(attn_mma2,
                             cudaFuncAttributeMaxDynamicSharedMemorySize, ATTN2_SMEM);
    }

    // Single merged split launch for x, w_qkv, w_proj
    split_all_kernel<<<(N8_ALL + 255) / 256, 256>>>(
        x, w_qkv, w_proj, p_xh, p_xl, p_wqh, p_wql, p_wph, p_wpl);

    // GEMM1: qkv = x @ w_qkv^T. Q,K cols: 3-mma hi/lo out. V cols: 2-mma.
    {
        dim3 grid(C3 / 128, M_TOT / 128);
        gemm_fp16_kernel<<<grid, 256, GEMM_SMEM>>>(p_xh, p_xl, p_wqh, p_wql,
                                                   p_qkvh, p_qkvl, C3,
                                                   2 * C_DIM, 1);
    }

    // Fused attention -> y single fp16 plane
    {
        dim3 grid(T_SEQ / AQ, NH, B_SZ);
        attn_mma2<<<grid, 256, ATTN2_SMEM>>>(qm, p_qkvh, p_qkvl, p_yh);
    }

    // GEMM2: out = y @ w_proj^T -> fp32 (lean 1-mma, 5-stage pipeline)
    {
        dim3 grid(C_DIM / 128, M_TOT / 128);
        gemm2_kernel<<<grid, 256, G2_SMEM>>>(p_yh, p_wph, out, C_DIM);
    }
}

// round 16
// speedup vs baseline: 1.3802x; 1.0111x over previous
#include <cuda_runtime.h>
#include <cuda_fp16.h>
#include <math.h>
#include <stdint.h>

// Problem constants
#define B_SZ   2
#define T_SEQ  2048
#define C_DIM  1024
#define C3     3072
#define NH     16
#define DH     64
#define MEMLEN 1024
#define M_TOT  4096
#define KD     1024

// Scratch fp16 hi/lo planes (no cudaMalloc allowed)
__device__ __half g_xh[(size_t)M_TOT * KD];
__device__ __half g_xl[(size_t)M_TOT * KD];
__device__ __half g_wqh[(size_t)C3 * KD];
__device__ __half g_wql[(size_t)C3 * KD];
__device__ __half g_wph[(size_t)C_DIM * KD];
__device__ __half g_wpl[(size_t)C_DIM * KD];
__device__ __half g_qkvh[(size_t)M_TOT * C3];
__device__ __half g_qkvl[(size_t)M_TOT * C3];
__device__ __half g_yh[(size_t)M_TOT * KD];

// ---------------------------------------------------------------------------
// helpers
// ---------------------------------------------------------------------------
__device__ __forceinline__ uint32_t pk2(__half a, __half b) {
    __half2 t = __halves2half2(a, b);
    return *reinterpret_cast<uint32_t*>(&t);
}

__device__ __forceinline__ uint32_t pkh(float a, float b) {
    __half2 t = __floats2half2_rn(a, b);
    return *reinterpret_cast<uint32_t*>(&t);
}

__device__ __forceinline__ uint32_t pkf(float a, float b, uint32_t* lo) {
    __half ha = __float2half_rn(a), hb = __float2half_rn(b);
    __half la = __float2half_rn(a - __half2float(ha));
    __half lb = __float2half_rn(b - __half2float(hb));
    *lo = pk2(la, lb);
    return pk2(ha, hb);
}

// raw ex2.approx fp32 (for accumulator rescale factors)
__device__ __forceinline__ float ex2f(float x) {
    float r;
    asm("ex2.approx.f32 %0, %1;" : "=f"(r) : "f"(x));
    return r;
}
// packed fp16x2 ex2 (softmax probabilities)
__device__ __forceinline__ uint32_t ex2h2(uint32_t x) {
    uint32_t r;
    asm("ex2.approx.f16x2 %0, %1;" : "=r"(r) : "r"(x));
    return r;
}
__device__ __forceinline__ float2 h22f2(uint32_t x) {
    __half2 h = *reinterpret_cast<__half2*>(&x);
    return __half22float2(h);
}

__device__ __forceinline__ void ldm4(uint32_t r[4], uint32_t a) {
    asm volatile("ldmatrix.sync.aligned.m8n8.x4.shared.b16 {%0,%1,%2,%3},[%4];\n"
                 : "=r"(r[0]), "=r"(r[1]), "=r"(r[2]), "=r"(r[3]) : "r"(a));
}
__device__ __forceinline__ void ldm4t(uint32_t r[4], uint32_t a) {
    asm volatile("ldmatrix.sync.aligned.m8n8.x4.trans.shared.b16 {%0,%1,%2,%3},[%4];\n"
                 : "=r"(r[0]), "=r"(r[1]), "=r"(r[2]), "=r"(r[3]) : "r"(a));
}

__device__ __forceinline__ void mma16(float d[4], const uint32_t a[4],
                                      uint32_t b0, uint32_t b1) {
    asm volatile(
        "mma.sync.aligned.m16n8k16.row.col.f32.f16.f16.f32 "
        "{%0,%1,%2,%3},{%4,%5,%6,%7},{%8,%9},{%0,%1,%2,%3};\n"
        : "+f"(d[0]), "+f"(d[1]), "+f"(d[2]), "+f"(d[3])
        : "r"(a[0]), "r"(a[1]), "r"(a[2]), "r"(a[3]), "r"(b0), "r"(b1));
}

__device__ __forceinline__ void cpa16(uint32_t d, const void* g) {
    asm volatile("cp.async.cg.shared.global [%0], [%1], 16;" :: "r"(d), "l"(g) : "memory");
}
__device__ __forceinline__ void cpa_commit() {
    asm volatile("cp.async.commit_group;" ::: "memory");
}
template <int N>
__device__ __forceinline__ void cpa_wait() {
    asm volatile("cp.async.wait_group %0;" :: "n"(N) : "memory");
}

// ---------------------------------------------------------------------------
// Merged split: fp32 -> fp16 hi/lo for x, w_qkv, w_proj in ONE launch.
// ---------------------------------------------------------------------------
#define N8_X   (M_TOT * KD / 8)
#define N8_WQ  (C3 * KD / 8)
#define N8_WP  (C_DIM * KD / 8)
#define N8_ALL (N8_X + N8_WQ + N8_WP)

__global__ __launch_bounds__(256)
void split_all_kernel(const float* __restrict__ x,
                      const float* __restrict__ wq,
                      const float* __restrict__ wp,
                      __half* __restrict__ xh, __half* __restrict__ xl,
                      __half* __restrict__ wqh, __half* __restrict__ wql,
                      __half* __restrict__ wph, __half* __restrict__ wpl)
{
    int i = blockIdx.x * 256 + threadIdx.x;
    if (i >= N8_ALL) return;
    const float* src;
    __half *hi, *lo;
    int j = i;
    if (j < N8_X) { src = x; hi = xh; lo = xl; }
    else if ((j -= N8_X) < N8_WQ) { src = wq; hi = wqh; lo = wql; }
    else { j -= N8_WQ; src = wp; hi = wph; lo = wpl; }

    float4 v0 = ((const float4*)src)[2 * j];
    float4 v1 = ((const float4*)src)[2 * j + 1];
    float v[8] = {v0.x, v0.y, v0.z, v0.w, v1.x, v1.y, v1.z, v1.w};
    uint32_t hp[4], lp[4];
#pragma unroll
    for (int k = 0; k < 4; k++)
        hp[k] = pkf(v[2 * k], v[2 * k + 1], &lp[k]);
    ((uint4*)hi)[j] = make_uint4(hp[0], hp[1], hp[2], hp[3]);
    ((uint4*)lo)[j] = make_uint4(lp[0], lp[1], lp[2], lp[3]);
}

// ---------------------------------------------------------------------------
// GEMM1: fp16 split NT GEMM.
// Q,K blocks (n0 < fullN): 3-mma, hi+lo output, 4 planes.
// V blocks: 1-mma (Ah x Bh only), hi-only output, 2 planes loaded.
// ---------------------------------------------------------------------------
#define PLANE        8192
#define STAGE_BYTES  32768
#define NSTAGE       3
#define GEMM_SMEM    (NSTAGE * STAGE_BYTES)
#define NCH          32

__global__ __launch_bounds__(256, 2)
void gemm_fp16_kernel(const __half* __restrict__ Ah,
                      const __half* __restrict__ Al,
                      const __half* __restrict__ Bh,
                      const __half* __restrict__ Bl,
                      __half* __restrict__ Ch,
                      __half* __restrict__ Cl, int N, int fullN)
{
    extern __shared__ char smem[];
    const uint32_t sbase = (uint32_t)__cvta_generic_to_shared(smem);
    const int tid = threadIdx.x, lane = tid & 31, warp = tid >> 5;
    const int m0 = blockIdx.y * 128, n0 = blockIdx.x * 128;
    const bool full = (n0 < fullN);
    const int mw = warp >> 1, nw = warp & 1;

    // plane for chunk it is it>>1 (0:Ah 1:Al 2:Bh 3:Bl); lo planes only if full
    bool ld[8];
#pragma unroll
    for (int it = 0; it < 8; it++) {
        int p = it >> 1;
        ld[it] = (p == 0) || (p == 2) || full;
    }

    const __half* gsrc[8];
    uint32_t sdst[8];
#pragma unroll
    for (int it = 0; it < 8; it++) {
        int c = tid + it * 256;
        int p = c >> 9;
        int r = (c >> 2) & 127;
        int kc = c & 3;
        const __half* bp = (p == 0) ? Ah : (p == 1) ? Al : (p == 2) ? Bh : Bl;
        int row = ((p < 2) ? m0 : n0) + r;
        gsrc[it] = bp + (size_t)row * KD + kc * 8;
        sdst[it] = (uint32_t)(p * PLANE + r * 64 + ((kc ^ ((r >> 1) & 3)) << 4));
    }

    const int ra = lane & 15;
    const int ksel_a = lane >> 4;
    int rowA[2], swzA[2];
#pragma unroll
    for (int f = 0; f < 2; f++) {
        rowA[f] = mw * 32 + f * 16 + ra;
        swzA[f] = (rowA[f] >> 1) & 3;
    }
    const int rb = (lane & 7) + 8 * (lane >> 4);
    const int ksel_b = (lane >> 3) & 1;
    int rowB[4], swzB[4];
#pragma unroll
    for (int g = 0; g < 4; g++) {
        rowB[g] = nw * 64 + g * 16 + rb;
        swzB[g] = (rowB[g] >> 1) & 3;
    }

    float acc[2][8][4] = {};

#pragma unroll
    for (int pt = 0; pt < 2; pt++) {
        uint32_t sb = sbase + pt * STAGE_BYTES;
#pragma unroll
        for (int it = 0; it < 8; it++)
            if (ld[it]) cpa16(sb + sdst[it], gsrc[it] + pt * 32);
        cpa_commit();
    }

    for (int t = 0; t < NCH; t++) {
        cpa_wait<1>();
        __syncthreads();

        if (t + 2 < NCH) {
            uint32_t sb = sbase + ((t + 2) % NSTAGE) * STAGE_BYTES;
#pragma unroll
            for (int it = 0; it < 8; it++)
                if (ld[it]) cpa16(sb + sdst[it], gsrc[it] + (t + 2) * 32);
        }
        cpa_commit();

        const uint32_t sb = sbase + (t % NSTAGE) * STAGE_BYTES;
#pragma unroll
        for (int s16 = 0; s16 < 2; s16++) {
            uint32_t ah[2][4], al[2][4];
#pragma unroll
            for (int f = 0; f < 2; f++) {
                uint32_t off = (uint32_t)(rowA[f] * 64 +
                               (((2 * s16 + ksel_a) ^ swzA[f]) << 4));
                ldm4(ah[f], sb + off);
                if (full) ldm4(al[f], sb + PLANE + off);
            }
#pragma unroll
            for (int g = 0; g < 4; g++) {
                uint32_t offb = (uint32_t)(rowB[g] * 64 +
                                (((2 * s16 + ksel_b) ^ swzB[g]) << 4));
                uint32_t bh[4], bl[4];
                ldm4(bh, sb + 2 * PLANE + offb);
                if (full) ldm4(bl, sb + 3 * PLANE + offb);
#pragma unroll
                for (int f = 0; f < 2; f++) {
#pragma unroll
                    for (int j = 0; j < 2; j++) {
                        float* d = acc[f][g * 2 + j];
                        mma16(d, ah[f], bh[2 * j], bh[2 * j + 1]);
                        if (full) {
                            mma16(d, ah[f], bl[2 * j], bl[2 * j + 1]);
                            mma16(d, al[f], bh[2 * j], bh[2 * j + 1]);
                        }
                    }
                }
            }
        }
    }

    const int er = lane >> 2, ec = (lane & 3) * 2;
#pragma unroll
    for (int f = 0; f < 2; f++) {
        int r = m0 + mw * 32 + f * 16 + er;
#pragma unroll
        for (int j8 = 0; j8 < 8; j8++) {
            int cc = n0 + nw * 64 + j8 * 8 + ec;
            if (full) {
                uint32_t lo0, lo1;
                uint32_t hi0 = pkf(acc[f][j8][0], acc[f][j8][1], &lo0);
                uint32_t hi1 = pkf(acc[f][j8][2], acc[f][j8][3], &lo1);
                *(uint32_t*)(Ch + (size_t)r * N + cc) = hi0;
                *(uint32_t*)(Cl + (size_t)r * N + cc) = lo0;
                *(uint32_t*)(Ch + (size_t)(r + 8) * N + cc) = hi1;
                *(uint32_t*)(Cl + (size_t)(r + 8) * N + cc) = lo1;
            } else {
                *(uint32_t*)(Ch + (size_t)r * N + cc) =
                    pkh(acc[f][j8][0], acc[f][j8][1]);
                *(uint32_t*)(Ch + (size_t)(r + 8) * N + cc) =
                    pkh(acc[f][j8][2], acc[f][j8][3]);
            }
        }
    }
}

// ---------------------------------------------------------------------------
// GEMM2: lean 1-mma kernel, 5-stage pipeline (unchanged from R15).
// ---------------------------------------------------------------------------
#define G2_STAGE  16384
#define G2_NSTAGE 5
#define G2_SMEM   (G2_NSTAGE * G2_STAGE)

__global__ __launch_bounds__(256, 2)
void gemm2_kernel(const __half* __restrict__ Ah,
                  const __half* __restrict__ Bh,
                  float* __restrict__ C, int N)
{
    extern __shared__ char smem[];
    const uint32_t sbase = (uint32_t)__cvta_generic_to_shared(smem);
    const int tid = threadIdx.x, lane = tid & 31, warp = tid >> 5;
    const int m0 = blockIdx.y * 128, n0 = blockIdx.x * 128;
    const int mw = warp >> 1, nw = warp & 1;

    const __half* gsrc[4];
    uint32_t sdst[4];
#pragma unroll
    for (int it = 0; it < 4; it++) {
        int c = tid + it * 256;
        int p = c >> 9;
        int r = (c >> 2) & 127;
        int kc = c & 3;
        const __half* bp = p ? Bh : Ah;
        int row = (p ? n0 : m0) + r;
        gsrc[it] = bp + (size_t)row * KD + kc * 8;
        sdst[it] = (uint32_t)(p * PLANE + r * 64 + ((kc ^ ((r >> 1) & 3)) << 4));
    }

    const int ra = lane & 15;
    const int ksel_a = lane >> 4;
    int rowA[2], swzA[2];
#pragma unroll
    for (int f = 0; f < 2; f++) {
        rowA[f] = mw * 32 + f * 16 + ra;
        swzA[f] = (rowA[f] >> 1) & 3;
    }
    const int rb = (lane & 7) + 8 * (lane >> 4);
    const int ksel_b = (lane >> 3) & 1;
    int rowB[4], swzB[4];
#pragma unroll
    for (int g = 0; g < 4; g++) {
        rowB[g] = nw * 64 + g * 16 + rb;
        swzB[g] = (rowB[g] >> 1) & 3;
    }

    float acc[2][8][4] = {};

#pragma unroll
    for (int pt = 0; pt < 4; pt++) {
        uint32_t sb = sbase + pt * G2_STAGE;
#pragma unroll
        for (int it = 0; it < 4; it++) cpa16(sb + sdst[it], gsrc[it] + pt * 32);
        cpa_commit();
    }

    for (int t = 0; t < NCH; t++) {
        cpa_wait<3>();
        __syncthreads();

        if (t + 4 < NCH) {
            uint32_t sb = sbase + ((t + 4) % G2_NSTAGE) * G2_STAGE;
#pragma unroll
            for (int it = 0; it < 4; it++)
                cpa16(sb + sdst[it], gsrc[it] + (t + 4) * 32);
        }
        cpa_commit();

        const uint32_t sb = sbase + (t % G2_NSTAGE) * G2_STAGE;
#pragma unroll
        for (int s16 = 0; s16 < 2; s16++) {
            uint32_t ah[2][4];
#pragma unroll
            for (int f = 0; f < 2; f++) {
                uint32_t off = (uint32_t)(rowA[f] * 64 +
                               (((2 * s16 + ksel_a) ^ swzA[f]) << 4));
                ldm4(ah[f], sb + off);
            }
#pragma unroll
            for (int g = 0; g < 4; g++) {
                uint32_t offb = (uint32_t)(rowB[g] * 64 +
                                (((2 * s16 + ksel_b) ^ swzB[g]) << 4));
                uint32_t bh[4];
                ldm4(bh, sb + PLANE + offb);
#pragma unroll
                for (int f = 0; f < 2; f++) {
#pragma unroll
                    for (int j = 0; j < 2; j++)
                        mma16(acc[f][g * 2 + j], ah[f], bh[2 * j], bh[2 * j + 1]);
                }
            }
        }
    }

    const int er = lane >> 2, ec = (lane & 3) * 2;
#pragma unroll
    for (int f = 0; f < 2; f++) {
        int r = m0 + mw * 32 + f * 16 + er;
#pragma unroll
        for (int j8 = 0; j8 < 8; j8++) {
            int cc = n0 + nw * 64 + j8 * 8 + ec;
            *(float2*)(C + (size_t)r * N + cc) =
                make_float2(acc[f][j8][0], acc[f][j8][1]);
            *(float2*)(C + (size_t)(r + 8) * N + cc) =
                make_float2(acc[f][j8][2], acc[f][j8][3]);
        }
    }
}

// ---------------------------------------------------------------------------
// fp16 mma flash attention: S 2-mma, PV 1-mma.
// log2-domain softmax with packed f16x2 ex2 (halved MUFU traffic);
// l summed in fp32 from the SAME fp16 p values PV consumes.
// 3-stage KV ring (24KB/stage); smem ~90KB -> 2 CTAs/SM.
// ---------------------------------------------------------------------------
#define AQ 128
#define AKV 64
#define QS_OFF   0
#define ST_OFF   16384
#define AST      24576
#define ANST     3
#define QSC_OFF  (ST_OFF + ANST * AST)
#define ATTN2_SMEM (QSC_OFF + 256)

__global__ __launch_bounds__(256, 2)
void attn_mma2(const float* __restrict__ qm,
               const __half* __restrict__ qkvh,
               const __half* __restrict__ qkvl,
               __half* __restrict__ yh)
{
    extern __shared__ char smem[];
    const uint32_t sb = (uint32_t)__cvta_generic_to_shared(smem);
    float* qsc = (float*)(smem + QSC_OFF);
    const int tid = threadIdx.x, lane = tid & 31, warp = tid >> 5;
    const int qt = (int)gridDim.x - 1 - (int)blockIdx.x;
    const int h = blockIdx.y, b = blockIdx.z;
    const int q0 = qt * AQ;

    if (tid < 64)
        qsc[tid] = 1.44269504f * logf(2048.0f) * qm[tid] * rsqrtf(64.0f);

    const __half* kvsrc[6];
    uint32_t kvdst[6];
#pragma unroll
    for (int it = 0; it < 6; it++) {
        int c = tid + it * 256;
        int p = c >> 9, r = (c >> 3) & 63, ch = c & 7;
        const __half* bp = (p == 1) ? qkvl : qkvh;
        int col = ((p == 2) ? 2 * C_DIM : C_DIM) + h * DH + ch * 8;
        kvsrc[it] = bp + (size_t)(b * T_SEQ + r) * C3 + col;
        kvdst[it] = (uint32_t)(p * 8192 + r * 128 + ((ch ^ (r & 7)) << 4));
    }
    // prologue: stages 0 and 1 (nT >= 16 always)
#pragma unroll
    for (int pt = 0; pt < 2; pt++) {
        uint32_t stb = sb + ST_OFF + pt * AST;
        size_t delta = (size_t)pt * AKV * C3;
#pragma unroll
        for (int it = 0; it < 6; it++) cpa16(stb + kvdst[it], kvsrc[it] + delta);
        cpa_commit();
    }

    __syncthreads();  // qsc visible

    // Q load: combine hi+lo, scale (log2 domain), round once to fp16
#pragma unroll
    for (int it = 0; it < 4; it++) {
        int u = tid + it * 256;
        int r = u >> 3, ch = u & 7;
        size_t src = (size_t)(b * T_SEQ + q0 + r) * C3 + h * DH + ch * 8;
        uint4 hv = *(const uint4*)(qkvh + src);
        uint4 lv = *(const uint4*)(qkvl + src);
        const __half2* hp = (const __half2*)&hv;
        const __half2* lp = (const __half2*)&lv;
        uint32_t oh[4];
#pragma unroll
        for (int k = 0; k < 4; k++) {
            float2 hf = __half22float2(hp[k]);
            float2 lf = __half22float2(lp[k]);
            oh[k] = pkh((hf.x + lf.x) * qsc[ch * 8 + 2 * k],
                        (hf.y + lf.y) * qsc[ch * 8 + 2 * k + 1]);
        }
        uint32_t off = (uint32_t)(r * 128 + ((ch ^ (r & 7)) << 4));
        *(uint4*)(smem + QS_OFF + off) = make_uint4(oh[0], oh[1], oh[2], oh[3]);
    }

    float m0 = -1e30f, m1 = -1e30f, l0 = 0.0f, l1 = 0.0f;
    float acc[8][4] = {};

    const int maxc = (q0 + AQ > MEMLEN) ? (q0 + AQ) : MEMLEN;
    const int nT = maxc / AKV;

    for (int t = 0; t < nT; t++) {
        cpa_wait<1>();
        __syncthreads();
        if (t + 2 < nT) {
            uint32_t stb = sb + ST_OFF + ((t + 2) % ANST) * AST;
            size_t delta = (size_t)(t + 2) * AKV * C3;
#pragma unroll
            for (int it = 0; it < 6; it++) cpa16(stb + kvdst[it], kvsrc[it] + delta);
        }
        cpa_commit();
        const uint32_t st = sb + ST_OFF + (t % ANST) * AST;

        // ---- S = Q K^T (2-mma: Q single, K hi/lo) ----
        float s_[8][4] = {};
#pragma unroll
        for (int kk = 0; kk < 4; kk++) {
            uint32_t aH[4];
            {
                int row = 16 * warp + (lane & 15);
                int ch = kk * 2 + (lane >> 4);
                uint32_t off = (uint32_t)(row * 128 + ((ch ^ (row & 7)) << 4));
                ldm4(aH, sb + QS_OFF + off);
            }
#pragma unroll
            for (int jj = 0; jj < 4; jj++) {
                int row = 16 * jj + 8 * (lane >> 4) + (lane & 7);
                int ch = kk * 2 + ((lane >> 3) & 1);
                uint32_t off = (uint32_t)(row * 128 + ((ch ^ (row & 7)) << 4));
                uint32_t bH[4], bL[4];
                ldm4(bH, st + off);
                ldm4(bL, st + 8192 + off);
#pragma unroll
                for (int u = 0; u < 2; u++) {
                    float* d = s_[2 * jj + u];
                    mma16(d, aH, bH[2 * u], bH[2 * u + 1]);
                    mma16(d, aH, bL[2 * u], bL[2 * u + 1]);
                }
            }
        }

        const int kj0 = t * AKV;
        if (kj0 >= MEMLEN) {
            int r0g = q0 + 16 * warp + (lane >> 2);
            int cb = kj0 + 2 * (lane & 3);
#pragma unroll
            for (int j = 0; j < 8; j++) {
                int cg = cb + 8 * j;
                if (cg > r0g)         s_[j][0] = -1e30f;
                if (cg + 1 > r0g)     s_[j][1] = -1e30f;
                if (cg > r0g + 8)     s_[j][2] = -1e30f;
                if (cg + 1 > r0g + 8) s_[j][3] = -1e30f;
            }
        }

        // ---- online softmax (log2 domain, packed f16x2 ex2) ----
        float mx0 = -1e30f, mx1 = -1e30f;
#pragma unroll
        for (int j = 0; j < 8; j++) {
            mx0 = fmaxf(mx0, fmaxf(s_[j][0], s_[j][1]));
            mx1 = fmaxf(mx1, fmaxf(s_[j][2], s_[j][3]));
        }
        mx0 = fmaxf(mx0, __shfl_xor_sync(0xffffffffu, mx0, 1));
        mx0 = fmaxf(mx0, __shfl_xor_sync(0xffffffffu, mx0, 2));
        mx1 = fmaxf(mx1, __shfl_xor_sync(0xffffffffu, mx1, 1));
        mx1 = fmaxf(mx1, __shfl_xor_sync(0xffffffffu, mx1, 2));
        float mn0 = fmaxf(m0, mx0), mn1 = fmaxf(m1, mx1);
        float f0 = ex2f(m0 - mn0), f1 = ex2f(m1 - mn1);
        float sum0 = 0.0f, sum1 = 0.0f;
        uint32_t phA[8], phB[8];
#pragma unroll
        for (int j = 0; j < 8; j++) {
            phA[j] = ex2h2(pkh(s_[j][0] - mn0, s_[j][1] - mn0));
            phB[j] = ex2h2(pkh(s_[j][2] - mn1, s_[j][3] - mn1));
            float2 fa = h22f2(phA[j]);
            float2 fb = h22f2(phB[j]);
            sum0 += fa.x + fa.y;
            sum1 += fb.x + fb.y;
        }
        sum0 += __shfl_xor_sync(0xffffffffu, sum0, 1);
        sum0 += __shfl_xor_sync(0xffffffffu, sum0, 2);
        sum1 += __shfl_xor_sync(0xffffffffu, sum1, 1);
        sum1 += __shfl_xor_sync(0xffffffffu, sum1, 2);
        l0 = l0 * f0 + sum0; l1 = l1 * f1 + sum1;
        m0 = mn0; m1 = mn1;
#pragma unroll
        for (int j = 0; j < 8; j++) {
            acc[j][0] *= f0; acc[j][1] *= f0;
            acc[j][2] *= f1; acc[j][3] *= f1;
        }

        // ---- P @ V (1-mma) ----
#pragma unroll
        for (int jj = 0; jj < 4; jj++) {
            uint32_t pa[4] = {phA[2*jj], phB[2*jj], phA[2*jj+1], phB[2*jj+1]};
#pragma unroll
            for (int nn = 0; nn < 4; nn++) {
                int row = 16 * jj + 8 * ((lane >> 3) & 1) + (lane & 7);
                int ch = 2 * nn + (lane >> 4);
                uint32_t off = (uint32_t)(row * 128 + ((ch ^ (row & 7)) << 4));
                uint32_t vH[4];
                ldm4t(vH, st + 16384 + off);
#pragma unroll
                for (int u = 0; u < 2; u++)
                    mma16(acc[2 * nn + u], pa, vH[2 * u], vH[2 * u + 1]);
            }
        }
    }

    // ---- epilogue ----
    {
        float i0 = 1.0f / l0, i1 = 1.0f / l1;
        size_t r0 = (size_t)(b * T_SEQ + q0 + 16 * warp + (lane >> 2));
        int cb = h * DH + 2 * (lane & 3);
#pragma unroll
        for (int j = 0; j < 8; j++) {
            int cc = cb + 8 * j;
            *(uint32_t*)(yh + r0 * C_DIM + cc)       = pkh(acc[j][0] * i0, acc[j][1] * i0);
            *(uint32_t*)(yh + (r0 + 8) * C_DIM + cc) = pkh(acc[j][2] * i1, acc[j][3] * i1);
        }
    }
}

// ---------------------------------------------------------------------------
// Launch
// ---------------------------------------------------------------------------
extern "C" void kernel_launch(void* const* d_in, const int* in_sizes, int n_in,
                              void* d_out, int out_size)
{
    const float* x      = (const float*)d_in[0];
    const float* w_qkv  = (const float*)d_in[1];
    const float* w_proj = (const float*)d_in[2];
    const float* qm     = (const float*)d_in[3];
    float* out = (float*)d_out;

    static __half *p_xh = nullptr, *p_xl, *p_wqh, *p_wql, *p_wph, *p_wpl;
    static __half *p_qkvh, *p_qkvl, *p_yh;
    if (!p_xh) {
        cudaGetSymbolAddress((void**)&p_xh, g_xh);
        cudaGetSymbolAddress((void**)&p_xl, g_xl);
        cudaGetSymbolAddress((void**)&p_wqh, g_wqh);
        cudaGetSymbolAddress((void**)&p_wql, g_wql);
        cudaGetSymbolAddress((void**)&p_wph, g_wph);
        cudaGetSymbolAddress((void**)&p_wpl, g_wpl);
        cudaGetSymbolAddress((void**)&p_qkvh, g_qkvh);
        cudaGetSymbolAddress((void**)&p_qkvl, g_qkvl);
        cudaGetSymbolAddress((void**)&p_yh, g_yh);
        cudaFuncSetAttribute(gemm_fp16_kernel,
                             cudaFuncAttributeMaxDynamicSharedMemorySize, GEMM_SMEM);
        cudaFuncSetAttribute(gemm2_kernel,
                             cudaFuncAttributeMaxDynamicSharedMemorySize, G2_SMEM);
        cudaFuncSetAttribute(attn_mma2,
                             cudaFuncAttributeMaxDynamicSharedMemorySize, ATTN2_SMEM);
    }

    // Single merged split launch for x, w_qkv, w_proj
    split_all_kernel<<<(N8_ALL + 255) / 256, 256>>>(
        x, w_qkv, w_proj, p_xh, p_xl, p_wqh, p_wql, p_wph, p_wpl);

    // GEMM1: qkv = x @ w_qkv^T. Q,K cols: 3-mma hi/lo out. V cols: 1-mma, hi out.
    {
        dim3 grid(C3 / 128, M_TOT / 128);
        gemm_fp16_kernel<<<grid, 256, GEMM_SMEM>>>(p_xh, p_xl, p_wqh, p_wql,
                                                   p_qkvh, p_qkvl, C3, 2 * C_DIM);
    }

    // Fused attention -> y single fp16 plane
    {
        dim3 grid(T_SEQ / AQ, NH, B_SZ);
        attn_mma2<<<grid, 256, ATTN2_SMEM>>>(qm, p_qkvh, p_qkvl, p_yh);
    }

    // GEMM2: out = y @ w_proj^T -> fp32 (lean 1-mma, 5-stage pipeline)
    {
        dim3 grid(C_DIM / 128, M_TOT / 128);
        gemm2_kernel<<<grid, 256, G2_SMEM>>>(p_yh, p_wph, out, C_DIM);
    }
}

// round 17
// speedup vs baseline: 1.4135x; 1.0241x over previous
#include <cuda_runtime.h>
#include <cuda_fp16.h>
#include <math.h>
#include <stdint.h>

// Problem constants
#define B_SZ   2
#define T_SEQ  2048
#define C_DIM  1024
#define C3     3072
#define NH     16
#define DH     64
#define MEMLEN 1024
#define M_TOT  4096
#define KD     1024

// Scratch fp16 hi/lo planes (no cudaMalloc allowed)
__device__ __half g_xh[(size_t)M_TOT * KD];
__device__ __half g_xl[(size_t)M_TOT * KD];
__device__ __half g_wqh[(size_t)C3 * KD];
__device__ __half g_wql[(size_t)C3 * KD];
__device__ __half g_wph[(size_t)C_DIM * KD];
__device__ __half g_wpl[(size_t)C_DIM * KD];
__device__ __half g_qkvh[(size_t)M_TOT * C3];
__device__ __half g_qkvl[(size_t)M_TOT * C3];
__device__ __half g_yh[(size_t)M_TOT * KD];

// ---------------------------------------------------------------------------
// helpers
// ---------------------------------------------------------------------------
__device__ __forceinline__ uint32_t pk2(__half a, __half b) {
    __half2 t = __halves2half2(a, b);
    return *reinterpret_cast<uint32_t*>(&t);
}

__device__ __forceinline__ uint32_t pkh(float a, float b) {
    __half2 t = __floats2half2_rn(a, b);
    return *reinterpret_cast<uint32_t*>(&t);
}

__device__ __forceinline__ uint32_t pkf(float a, float b, uint32_t* lo) {
    __half ha = __float2half_rn(a), hb = __float2half_rn(b);
    __half la = __float2half_rn(a - __half2float(ha));
    __half lb = __float2half_rn(b - __half2float(hb));
    *lo = pk2(la, lb);
    return pk2(ha, hb);
}

// raw ex2.approx fp32 (for accumulator rescale factors)
__device__ __forceinline__ float ex2f(float x) {
    float r;
    asm("ex2.approx.f32 %0, %1;" : "=f"(r) : "f"(x));
    return r;
}
// packed fp16x2 ex2 (softmax probabilities)
__device__ __forceinline__ uint32_t ex2h2(uint32_t x) {
    uint32_t r;
    asm("ex2.approx.f16x2 %0, %1;" : "=r"(r) : "r"(x));
    return r;
}
__device__ __forceinline__ float2 h22f2(uint32_t x) {
    __half2 h = *reinterpret_cast<__half2*>(&x);
    return __half22float2(h);
}

__device__ __forceinline__ void ldm4(uint32_t r[4], uint32_t a) {
    asm volatile("ldmatrix.sync.aligned.m8n8.x4.shared.b16 {%0,%1,%2,%3},[%4];\n"
                 : "=r"(r[0]), "=r"(r[1]), "=r"(r[2]), "=r"(r[3]) : "r"(a));
}
__device__ __forceinline__ void ldm4t(uint32_t r[4], uint32_t a) {
    asm volatile("ldmatrix.sync.aligned.m8n8.x4.trans.shared.b16 {%0,%1,%2,%3},[%4];\n"
                 : "=r"(r[0]), "=r"(r[1]), "=r"(r[2]), "=r"(r[3]) : "r"(a));
}

__device__ __forceinline__ void mma16(float d[4], const uint32_t a[4],
                                      uint32_t b0, uint32_t b1) {
    asm volatile(
        "mma.sync.aligned.m16n8k16.row.col.f32.f16.f16.f32 "
        "{%0,%1,%2,%3},{%4,%5,%6,%7},{%8,%9},{%0,%1,%2,%3};\n"
        : "+f"(d[0]), "+f"(d[1]), "+f"(d[2]), "+f"(d[3])
        : "r"(a[0]), "r"(a[1]), "r"(a[2]), "r"(a[3]), "r"(b0), "r"(b1));
}

__device__ __forceinline__ void cpa16(uint32_t d, const void* g) {
    asm volatile("cp.async.cg.shared.global [%0], [%1], 16;" :: "r"(d), "l"(g) : "memory");
}
__device__ __forceinline__ void cpa_commit() {
    asm volatile("cp.async.commit_group;" ::: "memory");
}
template <int N>
__device__ __forceinline__ void cpa_wait() {
    asm volatile("cp.async.wait_group %0;" :: "n"(N) : "memory");
}

// ---------------------------------------------------------------------------
// Merged split: fp32 -> fp16 hi/lo for x, w_qkv, w_proj in ONE launch.
// ---------------------------------------------------------------------------
#define N8_X   (M_TOT * KD / 8)
#define N8_WQ  (C3 * KD / 8)
#define N8_WP  (C_DIM * KD / 8)
#define N8_ALL (N8_X + N8_WQ + N8_WP)

__global__ __launch_bounds__(256)
void split_all_kernel(const float* __restrict__ x,
                      const float* __restrict__ wq,
                      const float* __restrict__ wp,
                      __half* __restrict__ xh, __half* __restrict__ xl,
                      __half* __restrict__ wqh, __half* __restrict__ wql,
                      __half* __restrict__ wph, __half* __restrict__ wpl)
{
    int i = blockIdx.x * 256 + threadIdx.x;
    if (i >= N8_ALL) return;
    const float* src;
    __half *hi, *lo;
    int j = i;
    if (j < N8_X) { src = x; hi = xh; lo = xl; }
    else if ((j -= N8_X) < N8_WQ) { src = wq; hi = wqh; lo = wql; }
    else { j -= N8_WQ; src = wp; hi = wph; lo = wpl; }

    float4 v0 = ((const float4*)src)[2 * j];
    float4 v1 = ((const float4*)src)[2 * j + 1];
    float v[8] = {v0.x, v0.y, v0.z, v0.w, v1.x, v1.y, v1.z, v1.w};
    uint32_t hp[4], lp[4];
#pragma unroll
    for (int k = 0; k < 4; k++)
        hp[k] = pkf(v[2 * k], v[2 * k + 1], &lp[k]);
    ((uint4*)hi)[j] = make_uint4(hp[0], hp[1], hp[2], hp[3]);
    ((uint4*)lo)[j] = make_uint4(lp[0], lp[1], lp[2], lp[3]);
}

// ---------------------------------------------------------------------------
// GEMM1: fp16 split NT GEMM (unchanged from R16).
// Q,K blocks: 3-mma, hi+lo out. V blocks: 1-mma, hi-only out.
// ---------------------------------------------------------------------------
#define PLANE        8192
#define STAGE_BYTES  32768
#define NSTAGE       3
#define GEMM_SMEM    (NSTAGE * STAGE_BYTES)
#define NCH          32

__global__ __launch_bounds__(256, 2)
void gemm_fp16_kernel(const __half* __restrict__ Ah,
                      const __half* __restrict__ Al,
                      const __half* __restrict__ Bh,
                      const __half* __restrict__ Bl,
                      __half* __restrict__ Ch,
                      __half* __restrict__ Cl, int N, int fullN)
{
    extern __shared__ char smem[];
    const uint32_t sbase = (uint32_t)__cvta_generic_to_shared(smem);
    const int tid = threadIdx.x, lane = tid & 31, warp = tid >> 5;
    const int m0 = blockIdx.y * 128, n0 = blockIdx.x * 128;
    const bool full = (n0 < fullN);
    const int mw = warp >> 1, nw = warp & 1;

    bool ld[8];
#pragma unroll
    for (int it = 0; it < 8; it++) {
        int p = it >> 1;
        ld[it] = (p == 0) || (p == 2) || full;
    }

    const __half* gsrc[8];
    uint32_t sdst[8];
#pragma unroll
    for (int it = 0; it < 8; it++) {
        int c = tid + it * 256;
        int p = c >> 9;
        int r = (c >> 2) & 127;
        int kc = c & 3;
        const __half* bp = (p == 0) ? Ah : (p == 1) ? Al : (p == 2) ? Bh : Bl;
        int row = ((p < 2) ? m0 : n0) + r;
        gsrc[it] = bp + (size_t)row * KD + kc * 8;
        sdst[it] = (uint32_t)(p * PLANE + r * 64 + ((kc ^ ((r >> 1) & 3)) << 4));
    }

    const int ra = lane & 15;
    const int ksel_a = lane >> 4;
    int rowA[2], swzA[2];
#pragma unroll
    for (int f = 0; f < 2; f++) {
        rowA[f] = mw * 32 + f * 16 + ra;
        swzA[f] = (rowA[f] >> 1) & 3;
    }
    const int rb = (lane & 7) + 8 * (lane >> 4);
    const int ksel_b = (lane >> 3) & 1;
    int rowB[4], swzB[4];
#pragma unroll
    for (int g = 0; g < 4; g++) {
        rowB[g] = nw * 64 + g * 16 + rb;
        swzB[g] = (rowB[g] >> 1) & 3;
    }

    float acc[2][8][4] = {};

#pragma unroll
    for (int pt = 0; pt < 2; pt++) {
        uint32_t sb = sbase + pt * STAGE_BYTES;
#pragma unroll
        for (int it = 0; it < 8; it++)
            if (ld[it]) cpa16(sb + sdst[it], gsrc[it] + pt * 32);
        cpa_commit();
    }

    for (int t = 0; t < NCH; t++) {
        cpa_wait<1>();
        __syncthreads();

        if (t + 2 < NCH) {
            uint32_t sb = sbase + ((t + 2) % NSTAGE) * STAGE_BYTES;
#pragma unroll
            for (int it = 0; it < 8; it++)
                if (ld[it]) cpa16(sb + sdst[it], gsrc[it] + (t + 2) * 32);
        }
        cpa_commit();

        const uint32_t sb = sbase + (t % NSTAGE) * STAGE_BYTES;
#pragma unroll
        for (int s16 = 0; s16 < 2; s16++) {
            uint32_t ah[2][4], al[2][4];
#pragma unroll
            for (int f = 0; f < 2; f++) {
                uint32_t off = (uint32_t)(rowA[f] * 64 +
                               (((2 * s16 + ksel_a) ^ swzA[f]) << 4));
                ldm4(ah[f], sb + off);
                if (full) ldm4(al[f], sb + PLANE + off);
            }
#pragma unroll
            for (int g = 0; g < 4; g++) {
                uint32_t offb = (uint32_t)(rowB[g] * 64 +
                                (((2 * s16 + ksel_b) ^ swzB[g]) << 4));
                uint32_t bh[4], bl[4];
                ldm4(bh, sb + 2 * PLANE + offb);
                if (full) ldm4(bl, sb + 3 * PLANE + offb);
#pragma unroll
                for (int f = 0; f < 2; f++) {
#pragma unroll
                    for (int j = 0; j < 2; j++) {
                        float* d = acc[f][g * 2 + j];
                        mma16(d, ah[f], bh[2 * j], bh[2 * j + 1]);
                        if (full) {
                            mma16(d, ah[f], bl[2 * j], bl[2 * j + 1]);
                            mma16(d, al[f], bh[2 * j], bh[2 * j + 1]);
                        }
                    }
                }
            }
        }
    }

    const int er = lane >> 2, ec = (lane & 3) * 2;
#pragma unroll
    for (int f = 0; f < 2; f++) {
        int r = m0 + mw * 32 + f * 16 + er;
#pragma unroll
        for (int j8 = 0; j8 < 8; j8++) {
            int cc = n0 + nw * 64 + j8 * 8 + ec;
            if (full) {
                uint32_t lo0, lo1;
                uint32_t hi0 = pkf(acc[f][j8][0], acc[f][j8][1], &lo0);
                uint32_t hi1 = pkf(acc[f][j8][2], acc[f][j8][3], &lo1);
                *(uint32_t*)(Ch + (size_t)r * N + cc) = hi0;
                *(uint32_t*)(Cl + (size_t)r * N + cc) = lo0;
                *(uint32_t*)(Ch + (size_t)(r + 8) * N + cc) = hi1;
                *(uint32_t*)(Cl + (size_t)(r + 8) * N + cc) = lo1;
            } else {
                *(uint32_t*)(Ch + (size_t)r * N + cc) =
                    pkh(acc[f][j8][0], acc[f][j8][1]);
                *(uint32_t*)(Ch + (size_t)(r + 8) * N + cc) =
                    pkh(acc[f][j8][2], acc[f][j8][3]);
            }
        }
    }
}

// ---------------------------------------------------------------------------
// GEMM2: lean 1-mma kernel, 5-stage pipeline (unchanged from R15).
// ---------------------------------------------------------------------------
#define G2_STAGE  16384
#define G2_NSTAGE 5
#define G2_SMEM   (G2_NSTAGE * G2_STAGE)

__global__ __launch_bounds__(256, 2)
void gemm2_kernel(const __half* __restrict__ Ah,
                  const __half* __restrict__ Bh,
                  float* __restrict__ C, int N)
{
    extern __shared__ char smem[];
    const uint32_t sbase = (uint32_t)__cvta_generic_to_shared(smem);
    const int tid = threadIdx.x, lane = tid & 31, warp = tid >> 5;
    const int m0 = blockIdx.y * 128, n0 = blockIdx.x * 128;
    const int mw = warp >> 1, nw = warp & 1;

    const __half* gsrc[4];
    uint32_t sdst[4];
#pragma unroll
    for (int it = 0; it < 4; it++) {
        int c = tid + it * 256;
        int p = c >> 9;
        int r = (c >> 2) & 127;
        int kc = c & 3;
        const __half* bp = p ? Bh : Ah;
        int row = (p ? n0 : m0) + r;
        gsrc[it] = bp + (size_t)row * KD + kc * 8;
        sdst[it] = (uint32_t)(p * PLANE + r * 64 + ((kc ^ ((r >> 1) & 3)) << 4));
    }

    const int ra = lane & 15;
    const int ksel_a = lane >> 4;
    int rowA[2], swzA[2];
#pragma unroll
    for (int f = 0; f < 2; f++) {
        rowA[f] = mw * 32 + f * 16 + ra;
        swzA[f] = (rowA[f] >> 1) & 3;
    }
    const int rb = (lane & 7) + 8 * (lane >> 4);
    const int ksel_b = (lane >> 3) & 1;
    int rowB[4], swzB[4];
#pragma unroll
    for (int g = 0; g < 4; g++) {
        rowB[g] = nw * 64 + g * 16 + rb;
        swzB[g] = (rowB[g] >> 1) & 3;
    }

    float acc[2][8][4] = {};

#pragma unroll
    for (int pt = 0; pt < 4; pt++) {
        uint32_t sb = sbase + pt * G2_STAGE;
#pragma unroll
        for (int it = 0; it < 4; it++) cpa16(sb + sdst[it], gsrc[it] + pt * 32);
        cpa_commit();
    }

    for (int t = 0; t < NCH; t++) {
        cpa_wait<3>();
        __syncthreads();

        if (t + 4 < NCH) {
            uint32_t sb = sbase + ((t + 4) % G2_NSTAGE) * G2_STAGE;
#pragma unroll
            for (int it = 0; it < 4; it++)
                cpa16(sb + sdst[it], gsrc[it] + (t + 4) * 32);
        }
        cpa_commit();

        const uint32_t sb = sbase + (t % G2_NSTAGE) * G2_STAGE;
#pragma unroll
        for (int s16 = 0; s16 < 2; s16++) {
            uint32_t ah[2][4];
#pragma unroll
            for (int f = 0; f < 2; f++) {
                uint32_t off = (uint32_t)(rowA[f] * 64 +
                               (((2 * s16 + ksel_a) ^ swzA[f]) << 4));
                ldm4(ah[f], sb + off);
            }
#pragma unroll
            for (int g = 0; g < 4; g++) {
                uint32_t offb = (uint32_t)(rowB[g] * 64 +
                                (((2 * s16 + ksel_b) ^ swzB[g]) << 4));
                uint32_t bh[4];
                ldm4(bh, sb + PLANE + offb);
#pragma unroll
                for (int f = 0; f < 2; f++) {
#pragma unroll
                    for (int j = 0; j < 2; j++)
                        mma16(acc[f][g * 2 + j], ah[f], bh[2 * j], bh[2 * j + 1]);
                }
            }
        }
    }

    const int er = lane >> 2, ec = (lane & 3) * 2;
#pragma unroll
    for (int f = 0; f < 2; f++) {
        int r = m0 + mw * 32 + f * 16 + er;
#pragma unroll
        for (int j8 = 0; j8 < 8; j8++) {
            int cc = n0 + nw * 64 + j8 * 8 + ec;
            *(float2*)(C + (size_t)r * N + cc) =
                make_float2(acc[f][j8][0], acc[f][j8][1]);
            *(float2*)(C + (size_t)(r + 8) * N + cc) =
                make_float2(acc[f][j8][2], acc[f][j8][3]);
        }
    }
}

// ---------------------------------------------------------------------------
// fp16 mma flash attention v3: 128 threads, 4 warps x 32 q-rows.
// Halves K/V fragment LDSM redundancy (4 warps duplicate instead of 8).
// S 2-mma (Q single, K hi/lo), PV 1-mma, f16x2 ex2 softmax, 3-stage KV ring.
// ---------------------------------------------------------------------------
#define AQ 128
#define AKV 64
#define QS_OFF   0
#define ST_OFF   16384
#define AST      24576
#define ANST     3
#define QSC_OFF  (ST_OFF + ANST * AST)
#define ATTN3_SMEM (QSC_OFF + 256)

__global__ __launch_bounds__(128, 2)
void attn_mma3(const float* __restrict__ qm,
               const __half* __restrict__ qkvh,
               const __half* __restrict__ qkvl,
               __half* __restrict__ yh)
{
    extern __shared__ char smem[];
    const uint32_t sb = (uint32_t)__cvta_generic_to_shared(smem);
    float* qsc = (float*)(smem + QSC_OFF);
    const int tid = threadIdx.x, lane = tid & 31, warp = tid >> 5;  // warp 0..3
    const int qt = (int)gridDim.x - 1 - (int)blockIdx.x;
    const int h = blockIdx.y, b = blockIdx.z;
    const int q0 = qt * AQ;

    if (tid < 64)
        qsc[tid] = 1.44269504f * logf(2048.0f) * qm[tid] * rsqrtf(64.0f);

    // KV loader: 12 x 16B per thread per stage (3 planes x 512 chunks)
    const __half* kvsrc[12];
    uint32_t kvdst[12];
#pragma unroll
    for (int it = 0; it < 12; it++) {
        int c = tid + it * 128;
        int p = c >> 9, r = (c >> 3) & 63, ch = c & 7;
        const __half* bp = (p == 1) ? qkvl : qkvh;
        int col = ((p == 2) ? 2 * C_DIM : C_DIM) + h * DH + ch * 8;
        kvsrc[it] = bp + (size_t)(b * T_SEQ + r) * C3 + col;
        kvdst[it] = (uint32_t)(p * 8192 + r * 128 + ((ch ^ (r & 7)) << 4));
    }
    // prologue: stages 0 and 1 (nT >= 16 always)
#pragma unroll
    for (int pt = 0; pt < 2; pt++) {
        uint32_t stb = sb + ST_OFF + pt * AST;
        size_t delta = (size_t)pt * AKV * C3;
#pragma unroll
        for (int it = 0; it < 12; it++) cpa16(stb + kvdst[it], kvsrc[it] + delta);
        cpa_commit();
    }

    __syncthreads();  // qsc visible

    // Q load: 128 rows x 8 chunks, 8 per thread
#pragma unroll
    for (int it = 0; it < 8; it++) {
        int u = tid + it * 128;
        int r = u >> 3, ch = u & 7;
        size_t src = (size_t)(b * T_SEQ + q0 + r) * C3 + h * DH + ch * 8;
        uint4 hv = *(const uint4*)(qkvh + src);
        uint4 lv = *(const uint4*)(qkvl + src);
        const __half2* hp = (const __half2*)&hv;
        const __half2* lp = (const __half2*)&lv;
        uint32_t oh[4];
#pragma unroll
        for (int k = 0; k < 4; k++) {
            float2 hf = __half22float2(hp[k]);
            float2 lf = __half22float2(lp[k]);
            oh[k] = pkh((hf.x + lf.x) * qsc[ch * 8 + 2 * k],
                        (hf.y + lf.y) * qsc[ch * 8 + 2 * k + 1]);
        }
        uint32_t off = (uint32_t)(r * 128 + ((ch ^ (r & 7)) << 4));
        *(uint4*)(smem + QS_OFF + off) = make_uint4(oh[0], oh[1], oh[2], oh[3]);
    }

    float mm[2][2], ll[2][2];
#pragma unroll
    for (int f = 0; f < 2; f++) {
        mm[f][0] = -1e30f; mm[f][1] = -1e30f;
        ll[f][0] = 0.0f;   ll[f][1] = 0.0f;
    }
    float acc[2][8][4] = {};   // [f][nn*2+u][quad]

    const int maxc = (q0 + AQ > MEMLEN) ? (q0 + AQ) : MEMLEN;
    const int nT = maxc / AKV;

    for (int t = 0; t < nT; t++) {
        cpa_wait<1>();
        __syncthreads();
        if (t + 2 < nT) {
            uint32_t stb = sb + ST_OFF + ((t + 2) % ANST) * AST;
            size_t delta = (size_t)(t + 2) * AKV * C3;
#pragma unroll
            for (int it = 0; it < 12; it++) cpa16(stb + kvdst[it], kvsrc[it] + delta);
        }
        cpa_commit();
        const uint32_t st = sb + ST_OFF + (t % ANST) * AST;

        // ---- S = Q K^T : warp rows [32w, 32w+32), 2 m16 frags (f) ----
        float s_[2][8][4] = {};
#pragma unroll
        for (int kk = 0; kk < 4; kk++) {
            uint32_t aH[2][4];
#pragma unroll
            for (int f = 0; f < 2; f++) {
                int row = 32 * warp + f * 16 + (lane & 15);
                int ch = kk * 2 + (lane >> 4);
                uint32_t off = (uint32_t)(row * 128 + ((ch ^ (row & 7)) << 4));
                ldm4(aH[f], sb + QS_OFF + off);
            }
#pragma unroll
            for (int jj = 0; jj < 4; jj++) {
                int row = 16 * jj + 8 * (lane >> 4) + (lane & 7);
                int ch = kk * 2 + ((lane >> 3) & 1);
                uint32_t off = (uint32_t)(row * 128 + ((ch ^ (row & 7)) << 4));
                uint32_t bH[4], bL[4];
                ldm4(bH, st + off);
                ldm4(bL, st + 8192 + off);
#pragma unroll
                for (int f = 0; f < 2; f++)
#pragma unroll
                    for (int u = 0; u < 2; u++) {
                        float* d = s_[f][2 * jj + u];
                        mma16(d, aH[f], bH[2 * u], bH[2 * u + 1]);
                        mma16(d, aH[f], bL[2 * u], bL[2 * u + 1]);
                    }
            }
        }

        const int kj0 = t * AKV;
        if (kj0 >= MEMLEN) {
            int cb = kj0 + 2 * (lane & 3);
#pragma unroll
            for (int f = 0; f < 2; f++) {
                int r0g = q0 + 32 * warp + f * 16 + (lane >> 2);
#pragma unroll
                for (int j = 0; j < 8; j++) {
                    int cg = cb + 8 * j;
                    if (cg > r0g)         s_[f][j][0] = -1e30f;
                    if (cg + 1 > r0g)     s_[f][j][1] = -1e30f;
                    if (cg > r0g + 8)     s_[f][j][2] = -1e30f;
                    if (cg + 1 > r0g + 8) s_[f][j][3] = -1e30f;
                }
            }
        }

        // ---- online softmax per f (log2 domain, f16x2 ex2) ----
        uint32_t phA[2][8], phB[2][8];
        float fsc[2][2];
#pragma unroll
        for (int f = 0; f < 2; f++) {
            float mx0 = -1e30f, mx1 = -1e30f;
#pragma unroll
            for (int j = 0; j < 8; j++) {
                mx0 = fmaxf(mx0, fmaxf(s_[f][j][0], s_[f][j][1]));
                mx1 = fmaxf(mx1, fmaxf(s_[f][j][2], s_[f][j][3]));
            }
            mx0 = fmaxf(mx0, __shfl_xor_sync(0xffffffffu, mx0, 1));
            mx0 = fmaxf(mx0, __shfl_xor_sync(0xffffffffu, mx0, 2));
            mx1 = fmaxf(mx1, __shfl_xor_sync(0xffffffffu, mx1, 1));
            mx1 = fmaxf(mx1, __shfl_xor_sync(0xffffffffu, mx1, 2));
            float mn0 = fmaxf(mm[f][0], mx0), mn1 = fmaxf(mm[f][1], mx1);
            float f0 = ex2f(mm[f][0] - mn0), f1 = ex2f(mm[f][1] - mn1);
            float sum0 = 0.0f, sum1 = 0.0f;
#pragma unroll
            for (int j = 0; j < 8; j++) {
                phA[f][j] = ex2h2(pkh(s_[f][j][0] - mn0, s_[f][j][1] - mn0));
                phB[f][j] = ex2h2(pkh(s_[f][j][2] - mn1, s_[f][j][3] - mn1));
                float2 fa = h22f2(phA[f][j]);
                float2 fb = h22f2(phB[f][j]);
                sum0 += fa.x + fa.y;
                sum1 += fb.x + fb.y;
            }
            sum0 += __shfl_xor_sync(0xffffffffu, sum0, 1);
            sum0 += __shfl_xor_sync(0xffffffffu, sum0, 2);
            sum1 += __shfl_xor_sync(0xffffffffu, sum1, 1);
            sum1 += __shfl_xor_sync(0xffffffffu, sum1, 2);
            ll[f][0] = ll[f][0] * f0 + sum0;
            ll[f][1] = ll[f][1] * f1 + sum1;
            mm[f][0] = mn0; mm[f][1] = mn1;
            fsc[f][0] = f0; fsc[f][1] = f1;
#pragma unroll
            for (int j = 0; j < 8; j++) {
                acc[f][j][0] *= f0; acc[f][j][1] *= f0;
                acc[f][j][2] *= f1; acc[f][j][3] *= f1;
            }
        }

        // ---- P @ V (1-mma); V fragments shared across f ----
#pragma unroll
        for (int jj = 0; jj < 4; jj++) {
            uint32_t pa0[4] = {phA[0][2*jj], phB[0][2*jj], phA[0][2*jj+1], phB[0][2*jj+1]};
            uint32_t pa1[4] = {phA[1][2*jj], phB[1][2*jj], phA[1][2*jj+1], phB[1][2*jj+1]};
#pragma unroll
            for (int nn = 0; nn < 4; nn++) {
                int row = 16 * jj + 8 * ((lane >> 3) & 1) + (lane & 7);
                int ch = 2 * nn + (lane >> 4);
                uint32_t off = (uint32_t)(row * 128 + ((ch ^ (row & 7)) << 4));
                uint32_t vH[4];
                ldm4t(vH, st + 16384 + off);
#pragma unroll
                for (int u = 0; u < 2; u++) {
                    mma16(acc[0][2 * nn + u], pa0, vH[2 * u], vH[2 * u + 1]);
                    mma16(acc[1][2 * nn + u], pa1, vH[2 * u], vH[2 * u + 1]);
                }
            }
        }
    }

    // ---- epilogue ----
#pragma unroll
    for (int f = 0; f < 2; f++) {
        float i0 = 1.0f / ll[f][0], i1 = 1.0f / ll[f][1];
        size_t r0 = (size_t)(b * T_SEQ + q0 + 32 * warp + f * 16 + (lane >> 2));
        int cb = h * DH + 2 * (lane & 3);
#pragma unroll
        for (int j = 0; j < 8; j++) {
            int cc = cb + 8 * j;
            *(uint32_t*)(yh + r0 * C_DIM + cc) =
                pkh(acc[f][j][0] * i0, acc[f][j][1] * i0);
            *(uint32_t*)(yh + (r0 + 8) * C_DIM + cc) =
                pkh(acc[f][j][2] * i1, acc[f][j][3] * i1);
        }
    }
}

// ---------------------------------------------------------------------------
// Launch
// ---------------------------------------------------------------------------
extern "C" void kernel_launch(void* const* d_in, const int* in_sizes, int n_in,
                              void* d_out, int out_size)
{
    const float* x      = (const float*)d_in[0];
    const float* w_qkv  = (const float*)d_in[1];
    const float* w_proj = (const float*)d_in[2];
    const float* qm     = (const float*)d_in[3];
    float* out = (float*)d_out;

    static __half *p_xh = nullptr, *p_xl, *p_wqh, *p_wql, *p_wph, *p_wpl;
    static __half *p_qkvh, *p_qkvl, *p_yh;
    if (!p_xh) {
        cudaGetSymbolAddress((void**)&p_xh, g_xh);
        cudaGetSymbolAddress((void**)&p_xl, g_xl);
        cudaGetSymbolAddress((void**)&p_wqh, g_wqh);
        cudaGetSymbolAddress((void**)&p_wql, g_wql);
        cudaGetSymbolAddress((void**)&p_wph, g_wph);
        cudaGetSymbolAddress((void**)&p_wpl, g_wpl);
        cudaGetSymbolAddress((void**)&p_qkvh, g_qkvh);
        cudaGetSymbolAddress((void**)&p_qkvl, g_qkvl);
        cudaGetSymbolAddress((void**)&p_yh, g_yh);
        cudaFuncSetAttribute(gemm_fp16_kernel,
                             cudaFuncAttributeMaxDynamicSharedMemorySize, GEMM_SMEM);
        cudaFuncSetAttribute(gemm2_kernel,
                             cudaFuncAttributeMaxDynamicSharedMemorySize, G2_SMEM);
        cudaFuncSetAttribute(attn_mma3,
                             cudaFuncAttributeMaxDynamicSharedMemorySize, ATTN3_SMEM);
    }

    // Single merged split launch for x, w_qkv, w_proj
    split_all_kernel<<<(N8_ALL + 255) / 256, 256>>>(
        x, w_qkv, w_proj, p_xh, p_xl, p_wqh, p_wql, p_wph, p_wpl);

    // GEMM1: qkv = x @ w_qkv^T. Q,K cols: 3-mma hi/lo out. V cols: 1-mma, hi out.
    {
        dim3 grid(C3 / 128, M_TOT / 128);
        gemm_fp16_kernel<<<grid, 256, GEMM_SMEM>>>(p_xh, p_xl, p_wqh, p_wql,
                                                   p_qkvh, p_qkvl, C3, 2 * C_DIM);
    }

    // Fused attention -> y single fp16 plane (4 fat warps, 128 threads)
    {
        dim3 grid(T_SEQ / AQ, NH, B_SZ);
        attn_mma3<<<grid, 128, ATTN3_SMEM>>>(qm, p_qkvh, p_qkvl, p_yh);
    }

    // GEMM2: out = y @ w_proj^T -> fp32 (lean 1-mma, 5-stage pipeline)
    {
        dim3 grid(C_DIM / 128, M_TOT / 128);
        gemm2_kernel<<<grid, 256, G2_SMEM>>>(p_yh, p_wph, out, C_DIM);
    }
}